// round 1
// baseline (speedup 1.0000x reference)
#include <cuda_runtime.h>

#define BB  32
#define SS  512
#define DD  512
#define HH  8
#define DKK 64
#define MM  (BB*SS)   // 16384

// Scratch (device globals; no runtime allocation allowed)
__device__ float g_Q[(size_t)BB*HH*DKK*SS];   // [BH][DK][S] (pre-transposed)
__device__ float g_K[(size_t)BB*HH*DKK*SS];   // [BH][DK][S] (pre-transposed)
__device__ float g_V[(size_t)BB*HH*SS*DKK];   // [BH][S][DK]
__device__ float g_heads[(size_t)MM*DD];      // [M][H*DK] (concat layout)

__device__ __forceinline__ void fma16(float (&c)[4][4], const float4 a, const float4 b) {
    c[0][0] = fmaf(a.x, b.x, c[0][0]);
    c[0][1] = fmaf(a.x, b.y, c[0][1]);
    c[0][2] = fmaf(a.x, b.z, c[0][2]);
    c[0][3] = fmaf(a.x, b.w, c[0][3]);
    c[1][0] = fmaf(a.y, b.x, c[1][0]);
    c[1][1] = fmaf(a.y, b.y, c[1][1]);
    c[1][2] = fmaf(a.y, b.z, c[1][2]);
    c[1][3] = fmaf(a.y, b.w, c[1][3]);
    c[2][0] = fmaf(a.z, b.x, c[2][0]);
    c[2][1] = fmaf(a.z, b.y, c[2][1]);
    c[2][2] = fmaf(a.z, b.z, c[2][2]);
    c[2][3] = fmaf(a.z, b.w, c[2][3]);
    c[3][0] = fmaf(a.w, b.x, c[3][0]);
    c[3][1] = fmaf(a.w, b.y, c[3][1]);
    c[3][2] = fmaf(a.w, b.z, c[3][2]);
    c[3][3] = fmaf(a.w, b.w, c[3][3]);
}

__device__ __forceinline__ float redmax16(float v) {
    v = fmaxf(v, __shfl_xor_sync(0xffffffffu, v, 1));
    v = fmaxf(v, __shfl_xor_sync(0xffffffffu, v, 2));
    v = fmaxf(v, __shfl_xor_sync(0xffffffffu, v, 4));
    v = fmaxf(v, __shfl_xor_sync(0xffffffffu, v, 8));
    return v;
}
__device__ __forceinline__ float redsum16(float v) {
    v += __shfl_xor_sync(0xffffffffu, v, 1);
    v += __shfl_xor_sync(0xffffffffu, v, 2);
    v += __shfl_xor_sync(0xffffffffu, v, 4);
    v += __shfl_xor_sync(0xffffffffu, v, 8);
    return v;
}

// ---------------------------------------------------------------------------
// Kernel 1: QKV projections. grid (M/64, H, 3), block 256.
// Computes a 64(token) x 64(=DK, one head) tile of X @ W[h].
// which==0 -> Q (transposed store), 1 -> K (transposed), 2 -> V (natural).
// ---------------------------------------------------------------------------
__global__ void qkv_kernel(const float* __restrict__ x,
                           const float* __restrict__ Wq,
                           const float* __restrict__ Wk,
                           const float* __restrict__ Wv,
                           const float* __restrict__ bias) {
    __shared__ float Xs[16][68];   // [d][m], padded
    __shared__ float Ws[16][64];   // [d][k]

    const int m0    = blockIdx.x * 64;
    const int h     = blockIdx.y;
    const int which = blockIdx.z;
    const float* W  = (which == 0) ? Wq : (which == 1) ? Wk : Wv;
    const float* Wh = W + (size_t)h * DD * DKK;

    const int tid = threadIdx.x;
    const int tq  = tid >> 4;      // 0..15 -> 4 token rows
    const int tk  = tid & 15;      // 0..15 -> 4 k cols

    const int lm = tid >> 2;           // 0..63 token row for X load
    const int ld = (tid & 3) * 4;      // 0,4,8,12 depth offset
    const int wi = tid * 4;
    const int wd = wi >> 6;            // 0..15
    const int wn = wi & 63;

    float c[4][4] = {};

    for (int d0 = 0; d0 < DD; d0 += 16) {
        float4 xa = *(const float4*)(x + (size_t)(m0 + lm) * DD + d0 + ld);
        Xs[ld + 0][lm] = xa.x;
        Xs[ld + 1][lm] = xa.y;
        Xs[ld + 2][lm] = xa.z;
        Xs[ld + 3][lm] = xa.w;
        *(float4*)&Ws[wd][wn] = *(const float4*)(Wh + (size_t)(d0 + wd) * DKK + wn);
        __syncthreads();
#pragma unroll
        for (int dd = 0; dd < 16; dd++) {
            float4 a  = *(float4*)&Xs[dd][tq * 4];
            float4 b4 = *(float4*)&Ws[dd][tk * 4];
            fma16(c, a, b4);
        }
        __syncthreads();
    }

    const float bv = bias[0];
#pragma unroll
    for (int i = 0; i < 4; i++)
#pragma unroll
        for (int j = 0; j < 4; j++) c[i][j] += bv;

    const int b  = m0 / SS;
    const int s0 = m0 % SS;
    const int bh = b * HH + h;

    if (which == 2) {
        // V natural: [bh][s][v]
#pragma unroll
        for (int i = 0; i < 4; i++) {
            float4 v = make_float4(c[i][0], c[i][1], c[i][2], c[i][3]);
            *(float4*)(g_V + ((size_t)bh * SS + s0 + tq * 4 + i) * DKK + tk * 4) = v;
        }
    } else {
        // Q/K transposed: [bh][k][s]
        float* dst = (which == 0) ? g_Q : g_K;
#pragma unroll
        for (int j = 0; j < 4; j++) {
            float4 v = make_float4(c[0][j], c[1][j], c[2][j], c[3][j]);
            *(float4*)(dst + ((size_t)bh * DKK + tk * 4 + j) * SS + s0 + tq * 4) = v;
        }
    }
}

// ---------------------------------------------------------------------------
// Kernel 2: flash attention. grid (S/64 qtiles, B*H), block 256.
// 64-query tile, loops over 8 key tiles of 64. Online softmax.
// ---------------------------------------------------------------------------
__global__ void attn_kernel(const int* __restrict__ mask) {
    extern __shared__ float sm[];
    float* Qt = sm;            // [64 d][64 q]   stride 64
    float* Kt = sm + 4096;     // [64 d][64 kcol] stride 64
    float* Vs = sm + 8192;     // [64 k][64 v]   stride 64
    float* Pt = sm + 12288;    // [64 k][64 q]   stride 68 (padded)

    const int q0 = blockIdx.x * 64;
    const int bh = blockIdx.y;
    const int b  = bh / HH;
    const int h  = bh % HH;

    const int tid = threadIdx.x;
    const int tq  = tid >> 4;   // row group (4 query rows)
    const int tk  = tid & 15;   // col group (4 key cols / 4 v cols)

    // Load Q tile (already [d][s] in gmem -> direct coalesced copy)
#pragma unroll
    for (int t = 0; t < 4; t++) {
        int lin = tid + t * 256;          // float4 index
        int r = lin >> 4;
        int cc = (lin & 15) * 4;
        *(float4*)&Qt[r * 64 + cc] =
            *(const float4*)(g_Q + ((size_t)bh * DKK + r) * SS + q0 + cc);
    }

    float mi[4], li[4], o[4][4] = {};
#pragma unroll
    for (int i = 0; i < 4; i++) { mi[i] = -1e30f; li[i] = 0.0f; }

    const float scale = 0.125f;  // 1/sqrt(64)

    for (int kt = 0; kt < 8; kt++) {
        __syncthreads();  // previous iteration's readers done with Kt/Vs/Pt
#pragma unroll
        for (int t = 0; t < 4; t++) {
            int lin = tid + t * 256;
            int r = lin >> 4;
            int cc = (lin & 15) * 4;
            *(float4*)&Kt[r * 64 + cc] =
                *(const float4*)(g_K + ((size_t)bh * DKK + r) * SS + kt * 64 + cc);
            *(float4*)&Vs[r * 64 + cc] =
                *(const float4*)(g_V + ((size_t)bh * SS + kt * 64 + r) * DKK + cc);
        }
        int4 mk = *(const int4*)(mask + b * SS + kt * 64 + tk * 4);
        __syncthreads();

        // scores: s[i][j] = sum_d Q[q_i][d] * K[k_j][d]
        float s4[4][4] = {};
#pragma unroll 16
        for (int dd = 0; dd < 64; dd++) {
            float4 a  = *(float4*)&Qt[dd * 64 + tq * 4];
            float4 b4 = *(float4*)&Kt[dd * 64 + tk * 4];
            fma16(s4, a, b4);
        }

        // mask + scale (reference: m*scores + (1-m)*(-1e30), scores pre-scaled)
        float p[4][4];
#pragma unroll
        for (int i = 0; i < 4; i++) {
            p[i][0] = mk.x ? s4[i][0] * scale : -1e30f;
            p[i][1] = mk.y ? s4[i][1] * scale : -1e30f;
            p[i][2] = mk.z ? s4[i][2] * scale : -1e30f;
            p[i][3] = mk.w ? s4[i][3] * scale : -1e30f;
        }

        // online softmax update per query row (replicated across 16 lanes)
        float al[4];
#pragma unroll
        for (int i = 0; i < 4; i++) {
            float rmax = fmaxf(fmaxf(p[i][0], p[i][1]), fmaxf(p[i][2], p[i][3]));
            rmax = redmax16(rmax);
            float mn = fmaxf(mi[i], rmax);
            al[i] = __expf(mi[i] - mn);
            p[i][0] = __expf(p[i][0] - mn);
            p[i][1] = __expf(p[i][1] - mn);
            p[i][2] = __expf(p[i][2] - mn);
            p[i][3] = __expf(p[i][3] - mn);
            float rs = p[i][0] + p[i][1] + p[i][2] + p[i][3];
            rs = redsum16(rs);
            li[i] = li[i] * al[i] + rs;
            mi[i] = mn;
#pragma unroll
            for (int j = 0; j < 4; j++) o[i][j] *= al[i];
        }

        // stage P transposed [k][q] (float4 over q)
#pragma unroll
        for (int j = 0; j < 4; j++) {
            *(float4*)&Pt[(tk * 4 + j) * 68 + tq * 4] =
                make_float4(p[0][j], p[1][j], p[2][j], p[3][j]);
        }
        __syncthreads();

        // O += P @ V
#pragma unroll 16
        for (int kk = 0; kk < 64; kk++) {
            float4 pp = *(float4*)&Pt[kk * 68 + tq * 4];
            float4 vv = *(float4*)&Vs[kk * 64 + tk * 4];
            fma16(o, pp, vv);
        }
    }

    // finalize: divide by l, write heads in concat layout [M][h*64+v]
#pragma unroll
    for (int i = 0; i < 4; i++) {
        float inv = 1.0f / li[i];
        size_t row = (size_t)b * SS + q0 + tq * 4 + i;
        *(float4*)(g_heads + row * DD + h * DKK + tk * 4) =
            make_float4(o[i][0] * inv, o[i][1] * inv, o[i][2] * inv, o[i][3] * inv);
    }
}

// ---------------------------------------------------------------------------
// Kernel 3: output projection. grid (M/64, D/64), block 256.
// out = heads @ Wo + bias
// ---------------------------------------------------------------------------
__global__ void oproj_kernel(const float* __restrict__ Wo,
                             const float* __restrict__ bias,
                             float* __restrict__ out) {
    __shared__ float Xs[16][68];
    __shared__ float Ws[16][64];

    const int m0 = blockIdx.x * 64;
    const int n0 = blockIdx.y * 64;

    const int tid = threadIdx.x;
    const int tq  = tid >> 4;
    const int tk  = tid & 15;

    const int lm = tid >> 2;
    const int ld = (tid & 3) * 4;
    const int wi = tid * 4;
    const int wd = wi >> 6;
    const int wn = wi & 63;

    float c[4][4] = {};

    for (int d0 = 0; d0 < DD; d0 += 16) {
        float4 xa = *(const float4*)(g_heads + (size_t)(m0 + lm) * DD + d0 + ld);
        Xs[ld + 0][lm] = xa.x;
        Xs[ld + 1][lm] = xa.y;
        Xs[ld + 2][lm] = xa.z;
        Xs[ld + 3][lm] = xa.w;
        *(float4*)&Ws[wd][wn] = *(const float4*)(Wo + (size_t)(d0 + wd) * DD + n0 + wn);
        __syncthreads();
#pragma unroll
        for (int dd = 0; dd < 16; dd++) {
            float4 a  = *(float4*)&Xs[dd][tq * 4];
            float4 b4 = *(float4*)&Ws[dd][tk * 4];
            fma16(c, a, b4);
        }
        __syncthreads();
    }

    const float bv = bias[0];
#pragma unroll
    for (int i = 0; i < 4; i++) {
        float4 v = make_float4(c[i][0] + bv, c[i][1] + bv, c[i][2] + bv, c[i][3] + bv);
        *(float4*)(out + (size_t)(m0 + tq * 4 + i) * DD + n0 + tk * 4) = v;
    }
}

// ---------------------------------------------------------------------------
extern "C" void kernel_launch(void* const* d_in, const int* in_sizes, int n_in,
                              void* d_out, int out_size) {
    const float* x    = (const float*)d_in[0];
    const int*   mask = (const int*)  d_in[1];
    const float* Wq   = (const float*)d_in[2];
    const float* Wk   = (const float*)d_in[3];
    const float* Wv   = (const float*)d_in[4];
    const float* Wo   = (const float*)d_in[5];
    const float* bias = (const float*)d_in[6];
    float* out = (float*)d_out;

    // 1) QKV projections
    qkv_kernel<<<dim3(MM / 64, HH, 3), 256>>>(x, Wq, Wk, Wv, bias);

    // 2) fused masked-softmax attention (flash style)
    const int smem_bytes = (3 * 64 * 64 + 64 * 68) * (int)sizeof(float);  // 66560
    cudaFuncSetAttribute(attn_kernel, cudaFuncAttributeMaxDynamicSharedMemorySize,
                         smem_bytes);
    attn_kernel<<<dim3(SS / 64, BB * HH), 256, smem_bytes>>>(mask);

    // 3) output projection
    oproj_kernel<<<dim3(MM / 64, DD / 64), 256>>>(Wo, bias, out);
}

// round 2
// speedup vs baseline: 1.2179x; 1.2179x over previous
#include <cuda_runtime.h>

#define BB  32
#define SS  512
#define DD  512
#define HH  8
#define DKK 64
#define MM  (BB*SS)   // 16384

// Scratch (device globals; no runtime allocation allowed)
__device__ float g_Q[(size_t)BB*HH*DKK*SS];   // [BH][DK][S] (pre-transposed)
__device__ float g_K[(size_t)BB*HH*DKK*SS];   // [BH][DK][S] (pre-transposed)
__device__ float g_V[(size_t)BB*HH*SS*DKK];   // [BH][S][DK]
__device__ float g_heads[(size_t)MM*DD];      // [M][H*DK] (concat layout)

typedef unsigned long long u64;

__device__ __forceinline__ u64 dup2(float v) {
    u64 r; asm("mov.b64 %0, {%1, %1};" : "=l"(r) : "f"(v)); return r;
}
__device__ __forceinline__ void ffma2(u64 &c, u64 a, u64 b) {
    asm("fma.rn.f32x2 %0, %1, %2, %0;" : "+l"(c) : "l"(a), "l"(b));
}
__device__ __forceinline__ void mul2(u64 &c, u64 a) {
    asm("mul.rn.f32x2 %0, %0, %1;" : "+l"(c) : "l"(a));
}
__device__ __forceinline__ float2 unpk(u64 v) {
    float2 r; asm("mov.b64 {%0, %1}, %2;" : "=f"(r.x), "=f"(r.y) : "l"(v)); return r;
}

__device__ __forceinline__ float redmax16(float v) {
    v = fmaxf(v, __shfl_xor_sync(0xffffffffu, v, 1));
    v = fmaxf(v, __shfl_xor_sync(0xffffffffu, v, 2));
    v = fmaxf(v, __shfl_xor_sync(0xffffffffu, v, 4));
    v = fmaxf(v, __shfl_xor_sync(0xffffffffu, v, 8));
    return v;
}
__device__ __forceinline__ float redsum16(float v) {
    v += __shfl_xor_sync(0xffffffffu, v, 1);
    v += __shfl_xor_sync(0xffffffffu, v, 2);
    v += __shfl_xor_sync(0xffffffffu, v, 4);
    v += __shfl_xor_sync(0xffffffffu, v, 8);
    return v;
}

// 8x8 microtile inner product step: a0/a1 = 8 row values, b0/b1 = 8 col values
// (as 4 packed pairs). c2[8][4] packed along columns.
#define MICRO_STEP(c2, a0, a1, bp0, bp1, bp2, bp3)                          \
    {                                                                        \
        u64 ad0 = dup2(a0.x), ad1 = dup2(a0.y), ad2 = dup2(a0.z),            \
            ad3 = dup2(a0.w);                                                \
        u64 ad4 = dup2(a1.x), ad5 = dup2(a1.y), ad6 = dup2(a1.z),            \
            ad7 = dup2(a1.w);                                                \
        ffma2(c2[0][0], ad0, bp0); ffma2(c2[0][1], ad0, bp1);                \
        ffma2(c2[0][2], ad0, bp2); ffma2(c2[0][3], ad0, bp3);                \
        ffma2(c2[1][0], ad1, bp0); ffma2(c2[1][1], ad1, bp1);                \
        ffma2(c2[1][2], ad1, bp2); ffma2(c2[1][3], ad1, bp3);                \
        ffma2(c2[2][0], ad2, bp0); ffma2(c2[2][1], ad2, bp1);                \
        ffma2(c2[2][2], ad2, bp2); ffma2(c2[2][3], ad2, bp3);                \
        ffma2(c2[3][0], ad3, bp0); ffma2(c2[3][1], ad3, bp1);                \
        ffma2(c2[3][2], ad3, bp2); ffma2(c2[3][3], ad3, bp3);                \
        ffma2(c2[4][0], ad4, bp0); ffma2(c2[4][1], ad4, bp1);                \
        ffma2(c2[4][2], ad4, bp2); ffma2(c2[4][3], ad4, bp3);                \
        ffma2(c2[5][0], ad5, bp0); ffma2(c2[5][1], ad5, bp1);                \
        ffma2(c2[5][2], ad5, bp2); ffma2(c2[5][3], ad5, bp3);                \
        ffma2(c2[6][0], ad6, bp0); ffma2(c2[6][1], ad6, bp1);                \
        ffma2(c2[6][2], ad6, bp2); ffma2(c2[6][3], ad6, bp3);                \
        ffma2(c2[7][0], ad7, bp0); ffma2(c2[7][1], ad7, bp1);                \
        ffma2(c2[7][2], ad7, bp2); ffma2(c2[7][3], ad7, bp3);                \
    }

// ---------------------------------------------------------------------------
// Kernel 1: QKV projections. grid (M/128, H/2, 3), block 256.
// 128(token) x 128(= 2 heads x DK) tile. 8x8 microtile, packed f32x2 FMA.
// which==0 -> Q (transposed store), 1 -> K (transposed), 2 -> V (natural).
// ---------------------------------------------------------------------------
__global__ __launch_bounds__(256, 2)
void qkv_kernel(const float* __restrict__ x,
                const float* __restrict__ Wq,
                const float* __restrict__ Wk,
                const float* __restrict__ Wv,
                const float* __restrict__ bias) {
    __shared__ float As[16 * 132];   // A^T: [d][m], pad to 132
    __shared__ float Bs[16 * 128];   // [d][n]

    const int m0    = blockIdx.x * 128;
    const int h0    = blockIdx.y * 2;
    const int which = blockIdx.z;
    const float* W  = (which == 0) ? Wq : (which == 1) ? Wk : Wv;
    const float* slab0 = W + (size_t)h0 * DD * DKK;

    const int tid = threadIdx.x;
    const int tq  = tid >> 4;       // 0..15
    const int tk  = tid & 15;       // 0..15

    const int aRow = tid >> 1;          // 0..127
    const int aD   = (tid & 1) * 8;     // 0 or 8
    const int bRow = tid >> 5;          // 0..7
    const int bCol = (tid & 31) * 4;    // 0..124

    const float* asrc = x + (size_t)(m0 + aRow) * DD + aD;
    const float* bsrc = (bCol < 64) ? (slab0 + bCol)
                                    : (slab0 + DD * DKK + (bCol - 64));

    u64 c2[8][4] = {};

    // prefetch first tile
    float4 xa = *(const float4*)(asrc);
    float4 xb = *(const float4*)(asrc + 4);
    float4 wa = *(const float4*)(bsrc + (size_t)bRow * DKK);
    float4 wb = *(const float4*)(bsrc + (size_t)(bRow + 8) * DKK);

    for (int d0 = 0; d0 < DD; d0 += 16) {
        __syncthreads();
        As[(aD + 0) * 132 + aRow] = xa.x;
        As[(aD + 1) * 132 + aRow] = xa.y;
        As[(aD + 2) * 132 + aRow] = xa.z;
        As[(aD + 3) * 132 + aRow] = xa.w;
        As[(aD + 4) * 132 + aRow] = xb.x;
        As[(aD + 5) * 132 + aRow] = xb.y;
        As[(aD + 6) * 132 + aRow] = xb.z;
        As[(aD + 7) * 132 + aRow] = xb.w;
        *(float4*)&Bs[bRow * 128 + bCol]       = wa;
        *(float4*)&Bs[(bRow + 8) * 128 + bCol] = wb;
        __syncthreads();

        const int d1 = (d0 + 16 < DD) ? d0 + 16 : d0;  // clamped prefetch
        xa = *(const float4*)(asrc + d1);
        xb = *(const float4*)(asrc + d1 + 4);
        wa = *(const float4*)(bsrc + (size_t)(d1 + bRow) * DKK);
        wb = *(const float4*)(bsrc + (size_t)(d1 + bRow + 8) * DKK);

#pragma unroll
        for (int dd = 0; dd < 16; dd++) {
            float4 a0 = *(const float4*)&As[dd * 132 + tq * 4];
            float4 a1 = *(const float4*)&As[dd * 132 + 64 + tq * 4];
            ulonglong2 b0 = *(const ulonglong2*)&Bs[dd * 128 + tk * 4];
            ulonglong2 b1 = *(const ulonglong2*)&Bs[dd * 128 + 64 + tk * 4];
            MICRO_STEP(c2, a0, a1, b0.x, b0.y, b1.x, b1.y);
        }
    }

    // unpack + bias
    const float bv = bias[0];
    float c[8][8];
#pragma unroll
    for (int i = 0; i < 8; i++)
#pragma unroll
        for (int j = 0; j < 4; j++) {
            float2 t = unpk(c2[i][j]);
            c[i][2 * j]     = t.x + bv;
            c[i][2 * j + 1] = t.y + bv;
        }

    const int b  = m0 / SS;
    const int sb = m0 % SS;

    if (which == 2) {
        // V natural: [bh][s][v]; cols 0-3 -> head h0, 4-7 -> head h0+1
#pragma unroll
        for (int i = 0; i < 8; i++) {
            int s = sb + ((i < 4) ? (tq * 4 + i) : (64 + tq * 4 + (i - 4)));
            *(float4*)(g_V + ((size_t)(b * HH + h0) * SS + s) * DKK + tk * 4) =
                make_float4(c[i][0], c[i][1], c[i][2], c[i][3]);
            *(float4*)(g_V + ((size_t)(b * HH + h0 + 1) * SS + s) * DKK + tk * 4) =
                make_float4(c[i][4], c[i][5], c[i][6], c[i][7]);
        }
    } else {
        float* dst = (which == 0) ? g_Q : g_K;
#pragma unroll
        for (int j = 0; j < 8; j++) {
            int head = (j < 4) ? h0 : h0 + 1;
            int k    = tk * 4 + (j & 3);
            float* p = dst + ((size_t)(b * HH + head) * DKK + k) * SS + sb + tq * 4;
            *(float4*)p        = make_float4(c[0][j], c[1][j], c[2][j], c[3][j]);
            *(float4*)(p + 64) = make_float4(c[4][j], c[5][j], c[6][j], c[7][j]);
        }
    }
}

// ---------------------------------------------------------------------------
// Kernel 2: flash attention. grid (S/64, B*H), block 256. Packed f32x2.
// ---------------------------------------------------------------------------
__global__ __launch_bounds__(256, 2)
void attn_kernel(const int* __restrict__ mask) {
    extern __shared__ float sm[];
    float* Qt = sm;            // [64 d][64 q]   stride 64
    float* Kt = sm + 4096;     // [64 d][64 k]   stride 64
    float* Vs = sm + 8192;     // [64 k][64 v]   stride 64
    float* Pt = sm + 12288;    // [64 k][64 q]   stride 68 (padded)

    const int q0 = blockIdx.x * 64;
    const int bh = blockIdx.y;
    const int b  = bh / HH;
    const int h  = bh % HH;

    const int tid = threadIdx.x;
    const int tq  = tid >> 4;
    const int tk  = tid & 15;

    // Load Q tile ([d][s] in gmem -> direct coalesced copy)
#pragma unroll
    for (int t = 0; t < 4; t++) {
        int lin = tid + t * 256;
        int r   = lin >> 4;
        int cc  = (lin & 15) * 4;
        *(float4*)&Qt[r * 64 + cc] =
            *(const float4*)(g_Q + ((size_t)bh * DKK + r) * SS + q0 + cc);
    }

    // prefetch first K/V tile into registers
    float4 kreg[4], vreg[4];
#pragma unroll
    for (int t = 0; t < 4; t++) {
        int lin = tid + t * 256;
        int r   = lin >> 4;
        int cc  = (lin & 15) * 4;
        kreg[t] = *(const float4*)(g_K + ((size_t)bh * DKK + r) * SS + cc);
        vreg[t] = *(const float4*)(g_V + ((size_t)bh * SS + r) * DKK + cc);
    }

    float mi[4], li[4];
    u64 o2[4][2] = {};   // packed O accumulators (cols = v dims)
#pragma unroll
    for (int i = 0; i < 4; i++) { mi[i] = -1e30f; li[i] = 0.0f; }

    const float scale = 0.125f;  // 1/sqrt(64)

    for (int kt = 0; kt < 8; kt++) {
        __syncthreads();  // prev iteration readers done with Kt/Vs/Pt
#pragma unroll
        for (int t = 0; t < 4; t++) {
            int lin = tid + t * 256;
            int r   = lin >> 4;
            int cc  = (lin & 15) * 4;
            *(float4*)&Kt[r * 64 + cc] = kreg[t];
            *(float4*)&Vs[r * 64 + cc] = vreg[t];
        }
        int4 mk = *(const int4*)(mask + b * SS + kt * 64 + tk * 4);
        __syncthreads();

        // prefetch next tile (clamped; overlaps with scores compute)
        const int kn = (kt < 7) ? kt + 1 : kt;
#pragma unroll
        for (int t = 0; t < 4; t++) {
            int lin = tid + t * 256;
            int r   = lin >> 4;
            int cc  = (lin & 15) * 4;
            kreg[t] = *(const float4*)(g_K + ((size_t)bh * DKK + r) * SS + kn * 64 + cc);
            vreg[t] = *(const float4*)(g_V + ((size_t)bh * SS + kn * 64 + r) * DKK + cc);
        }

        // scores: s[i][j] = sum_d Q[d][q_i] * K[d][k_j]  (packed over k pairs)
        u64 s2[4][2] = {};
#pragma unroll
        for (int dd = 0; dd < 64; dd++) {
            float4 a = *(const float4*)&Qt[dd * 64 + tq * 4];
            ulonglong2 bb = *(const ulonglong2*)&Kt[dd * 64 + tk * 4];
            u64 d0_ = dup2(a.x), d1_ = dup2(a.y), d2_ = dup2(a.z), d3_ = dup2(a.w);
            ffma2(s2[0][0], d0_, bb.x); ffma2(s2[0][1], d0_, bb.y);
            ffma2(s2[1][0], d1_, bb.x); ffma2(s2[1][1], d1_, bb.y);
            ffma2(s2[2][0], d2_, bb.x); ffma2(s2[2][1], d2_, bb.y);
            ffma2(s2[3][0], d3_, bb.x); ffma2(s2[3][1], d3_, bb.y);
        }

        // unpack + mask + scale
        float p[4][4];
#pragma unroll
        for (int i = 0; i < 4; i++) {
            float2 t0 = unpk(s2[i][0]);
            float2 t1 = unpk(s2[i][1]);
            p[i][0] = mk.x ? t0.x * scale : -1e30f;
            p[i][1] = mk.y ? t0.y * scale : -1e30f;
            p[i][2] = mk.z ? t1.x * scale : -1e30f;
            p[i][3] = mk.w ? t1.y * scale : -1e30f;
        }

        // online softmax update (row stats replicated across the 16 tk lanes)
#pragma unroll
        for (int i = 0; i < 4; i++) {
            float rmax = fmaxf(fmaxf(p[i][0], p[i][1]), fmaxf(p[i][2], p[i][3]));
            rmax = redmax16(rmax);
            float mn = fmaxf(mi[i], rmax);
            float al = __expf(mi[i] - mn);
            p[i][0] = __expf(p[i][0] - mn);
            p[i][1] = __expf(p[i][1] - mn);
            p[i][2] = __expf(p[i][2] - mn);
            p[i][3] = __expf(p[i][3] - mn);
            float rs = p[i][0] + p[i][1] + p[i][2] + p[i][3];
            rs = redsum16(rs);
            li[i] = li[i] * al + rs;
            mi[i] = mn;
            u64 ad = dup2(al);
            mul2(o2[i][0], ad);
            mul2(o2[i][1], ad);
        }

        // stage P transposed [k][q]
#pragma unroll
        for (int j = 0; j < 4; j++) {
            *(float4*)&Pt[(tk * 4 + j) * 68 + tq * 4] =
                make_float4(p[0][j], p[1][j], p[2][j], p[3][j]);
        }
        __syncthreads();

        // O += P @ V (packed over v pairs)
#pragma unroll
        for (int kk = 0; kk < 64; kk++) {
            float4 pp = *(const float4*)&Pt[kk * 68 + tq * 4];
            ulonglong2 vv = *(const ulonglong2*)&Vs[kk * 64 + tk * 4];
            u64 d0_ = dup2(pp.x), d1_ = dup2(pp.y), d2_ = dup2(pp.z), d3_ = dup2(pp.w);
            ffma2(o2[0][0], d0_, vv.x); ffma2(o2[0][1], d0_, vv.y);
            ffma2(o2[1][0], d1_, vv.x); ffma2(o2[1][1], d1_, vv.y);
            ffma2(o2[2][0], d2_, vv.x); ffma2(o2[2][1], d2_, vv.y);
            ffma2(o2[3][0], d3_, vv.x); ffma2(o2[3][1], d3_, vv.y);
        }
    }

    // finalize
#pragma unroll
    for (int i = 0; i < 4; i++) {
        float inv = 1.0f / li[i];
        float2 t0 = unpk(o2[i][0]);
        float2 t1 = unpk(o2[i][1]);
        size_t row = (size_t)b * SS + q0 + tq * 4 + i;
        *(float4*)(g_heads + row * DD + h * DKK + tk * 4) =
            make_float4(t0.x * inv, t0.y * inv, t1.x * inv, t1.y * inv);
    }
}

// ---------------------------------------------------------------------------
// Kernel 3: output projection. grid (M/128, D/128), block 256. 8x8 microtile.
// ---------------------------------------------------------------------------
__global__ __launch_bounds__(256, 2)
void oproj_kernel(const float* __restrict__ Wo,
                  const float* __restrict__ bias,
                  float* __restrict__ out) {
    __shared__ float As[16 * 132];
    __shared__ float Bs[16 * 128];

    const int m0 = blockIdx.x * 128;
    const int n0 = blockIdx.y * 128;

    const int tid = threadIdx.x;
    const int tq  = tid >> 4;
    const int tk  = tid & 15;

    const int aRow = tid >> 1;
    const int aD   = (tid & 1) * 8;
    const int bRow = tid >> 5;
    const int bCol = (tid & 31) * 4;

    const float* asrc = g_heads + (size_t)(m0 + aRow) * DD + aD;
    const float* bsrc = Wo + n0 + bCol;

    u64 c2[8][4] = {};

    float4 xa = *(const float4*)(asrc);
    float4 xb = *(const float4*)(asrc + 4);
    float4 wa = *(const float4*)(bsrc + (size_t)bRow * DD);
    float4 wb = *(const float4*)(bsrc + (size_t)(bRow + 8) * DD);

    for (int d0 = 0; d0 < DD; d0 += 16) {
        __syncthreads();
        As[(aD + 0) * 132 + aRow] = xa.x;
        As[(aD + 1) * 132 + aRow] = xa.y;
        As[(aD + 2) * 132 + aRow] = xa.z;
        As[(aD + 3) * 132 + aRow] = xa.w;
        As[(aD + 4) * 132 + aRow] = xb.x;
        As[(aD + 5) * 132 + aRow] = xb.y;
        As[(aD + 6) * 132 + aRow] = xb.z;
        As[(aD + 7) * 132 + aRow] = xb.w;
        *(float4*)&Bs[bRow * 128 + bCol]       = wa;
        *(float4*)&Bs[(bRow + 8) * 128 + bCol] = wb;
        __syncthreads();

        const int d1 = (d0 + 16 < DD) ? d0 + 16 : d0;
        xa = *(const float4*)(asrc + d1);
        xb = *(const float4*)(asrc + d1 + 4);
        wa = *(const float4*)(bsrc + (size_t)(d1 + bRow) * DD);
        wb = *(const float4*)(bsrc + (size_t)(d1 + bRow + 8) * DD);

#pragma unroll
        for (int dd = 0; dd < 16; dd++) {
            float4 a0 = *(const float4*)&As[dd * 132 + tq * 4];
            float4 a1 = *(const float4*)&As[dd * 132 + 64 + tq * 4];
            ulonglong2 b0 = *(const ulonglong2*)&Bs[dd * 128 + tk * 4];
            ulonglong2 b1 = *(const ulonglong2*)&Bs[dd * 128 + 64 + tk * 4];
            MICRO_STEP(c2, a0, a1, b0.x, b0.y, b1.x, b1.y);
        }
    }

    const float bv = bias[0];
#pragma unroll
    for (int i = 0; i < 8; i++) {
        int m = m0 + ((i < 4) ? (tq * 4 + i) : (64 + tq * 4 + (i - 4)));
        float2 t0 = unpk(c2[i][0]);
        float2 t1 = unpk(c2[i][1]);
        float2 t2 = unpk(c2[i][2]);
        float2 t3 = unpk(c2[i][3]);
        *(float4*)(out + (size_t)m * DD + n0 + tk * 4) =
            make_float4(t0.x + bv, t0.y + bv, t1.x + bv, t1.y + bv);
        *(float4*)(out + (size_t)m * DD + n0 + 64 + tk * 4) =
            make_float4(t2.x + bv, t2.y + bv, t3.x + bv, t3.y + bv);
    }
}

// ---------------------------------------------------------------------------
extern "C" void kernel_launch(void* const* d_in, const int* in_sizes, int n_in,
                              void* d_out, int out_size) {
    const float* x    = (const float*)d_in[0];
    const int*   mask = (const int*)  d_in[1];
    const float* Wq   = (const float*)d_in[2];
    const float* Wk   = (const float*)d_in[3];
    const float* Wv   = (const float*)d_in[4];
    const float* Wo   = (const float*)d_in[5];
    const float* bias = (const float*)d_in[6];
    float* out = (float*)d_out;

    // 1) QKV projections (128x128 tiles, 2 heads per block)
    qkv_kernel<<<dim3(MM / 128, HH / 2, 3), 256>>>(x, Wq, Wk, Wv, bias);

    // 2) fused masked-softmax attention (flash style)
    const int smem_bytes = (3 * 64 * 64 + 64 * 68) * (int)sizeof(float);  // 66560
    cudaFuncSetAttribute(attn_kernel, cudaFuncAttributeMaxDynamicSharedMemorySize,
                         smem_bytes);
    attn_kernel<<<dim3(SS / 64, BB * HH), 256, smem_bytes>>>(mask);

    // 3) output projection
    oproj_kernel<<<dim3(MM / 128, DD / 128), 256>>>(Wo, bias, out);
}

// round 4
// speedup vs baseline: 1.3007x; 1.0680x over previous
#include <cuda_runtime.h>
#include <cstdint>

#define BB  32
#define SS  512
#define DD  512
#define HH  8
#define DKK 64
#define MM  (BB*SS)   // 16384

// Scratch (device globals; no runtime allocation allowed)
__device__ float g_Q[(size_t)BB*HH*DKK*SS];   // [BH][DK][S] (pre-transposed)
__device__ float g_K[(size_t)BB*HH*DKK*SS];   // [BH][DK][S] (pre-transposed)
__device__ float g_V[(size_t)BB*HH*SS*DKK];   // [BH][S][DK]
__device__ float g_heads[(size_t)MM*DD];      // [M][H*DK] (concat layout)
__device__ float g_Bhi[(size_t)4*DD*DD];      // [mat][n][k] tf32-hi weights
__device__ float g_Blo[(size_t)4*DD*DD];      // [mat][n][k] residual weights

typedef unsigned long long u64;

__device__ __forceinline__ float tf32_hi(float x) {
    float r; asm("cvt.rna.tf32.f32 %0, %1;" : "=f"(r) : "f"(x)); return r;
}

// mma.sync m16n8k8 tf32 (portable PTX; runs on Blackwell tensor fallback)
__device__ __forceinline__ void mma8(float* d, const float* a, const float* b) {
    asm volatile(
        "mma.sync.aligned.m16n8k8.row.col.f32.tf32.tf32.f32 "
        "{%0,%1,%2,%3}, {%4,%5,%6,%7}, {%8,%9}, {%0,%1,%2,%3};"
        : "+f"(d[0]), "+f"(d[1]), "+f"(d[2]), "+f"(d[3])
        : "r"(__float_as_uint(a[0])), "r"(__float_as_uint(a[1])),
          "r"(__float_as_uint(a[2])), "r"(__float_as_uint(a[3])),
          "r"(__float_as_uint(b[0])), "r"(__float_as_uint(b[1])));
}

// ===================== SIMT helpers for attention =====================
__device__ __forceinline__ u64 dup2(float v) {
    u64 r; asm("mov.b64 %0, {%1, %1};" : "=l"(r) : "f"(v)); return r;
}
__device__ __forceinline__ void ffma2(u64 &c, u64 a, u64 b) {
    asm("fma.rn.f32x2 %0, %1, %2, %0;" : "+l"(c) : "l"(a), "l"(b));
}
__device__ __forceinline__ void mul2(u64 &c, u64 a) {
    asm("mul.rn.f32x2 %0, %0, %1;" : "+l"(c) : "l"(a));
}
__device__ __forceinline__ float2 unpk(u64 v) {
    float2 r; asm("mov.b64 {%0, %1}, %2;" : "=f"(r.x), "=f"(r.y) : "l"(v)); return r;
}
__device__ __forceinline__ float redmax16(float v) {
    v = fmaxf(v, __shfl_xor_sync(0xffffffffu, v, 1));
    v = fmaxf(v, __shfl_xor_sync(0xffffffffu, v, 2));
    v = fmaxf(v, __shfl_xor_sync(0xffffffffu, v, 4));
    v = fmaxf(v, __shfl_xor_sync(0xffffffffu, v, 8));
    return v;
}
__device__ __forceinline__ float redsum16(float v) {
    v += __shfl_xor_sync(0xffffffffu, v, 1);
    v += __shfl_xor_sync(0xffffffffu, v, 2);
    v += __shfl_xor_sync(0xffffffffu, v, 4);
    v += __shfl_xor_sync(0xffffffffu, v, 8);
    return v;
}

// ---------------------------------------------------------------------------
// Prep: transpose weights into [mat][n][k] with hi/lo tf32 split.
// grid (8, 8, 4), block 256.  z<3: x=d-tile, y=head.  z=3: x=k-tile, y=n-tile.
// ---------------------------------------------------------------------------
__global__ void prep_kernel(const float* __restrict__ Wq,
                            const float* __restrict__ Wk,
                            const float* __restrict__ Wv,
                            const float* __restrict__ Wo) {
    __shared__ float t[64][65];
    const int z  = blockIdx.z;
    const int y  = blockIdx.y;
    const int xt = blockIdx.x;
    const float* W = (z == 0) ? Wq : (z == 1) ? Wk : (z == 2) ? Wv : Wo;
    const int tid = threadIdx.x;

#pragma unroll
    for (int i = 0; i < 4; i++) {
        int idx = tid + i * 256;
        int r   = idx >> 4;
        int c4  = (idx & 15) * 4;
        const float* p = (z < 3)
            ? W + (size_t)y * DD * DKK + (size_t)(xt * 64 + r) * DKK + c4
            : W + (size_t)(xt * 64 + r) * DD + y * 64 + c4;
        float4 v = *(const float4*)p;
        t[c4 + 0][r] = v.x; t[c4 + 1][r] = v.y;
        t[c4 + 2][r] = v.z; t[c4 + 3][r] = v.w;
    }
    __syncthreads();

    float* oh = g_Bhi + (size_t)z * DD * DD;
    float* ol = g_Blo + (size_t)z * DD * DD;
#pragma unroll
    for (int i = 0; i < 4; i++) {
        int idx = tid + i * 256;
        int c   = idx >> 4;
        int r4  = (idx & 15) * 4;
        float4 v = make_float4(t[c][r4], t[c][r4 + 1], t[c][r4 + 2], t[c][r4 + 3]);
        float4 hi = make_float4(tf32_hi(v.x), tf32_hi(v.y), tf32_hi(v.z), tf32_hi(v.w));
        float4 lo = make_float4(v.x - hi.x, v.y - hi.y, v.z - hi.z, v.w - hi.w);
        size_t o = (size_t)(y * 64 + c) * DD + xt * 64 + r4;
        *(float4*)(oh + o) = hi;
        *(float4*)(ol + o) = lo;
    }
}

// ---------------------------------------------------------------------------
// mma.sync tf32 3x-split GEMM. Block tile 128x128, K=512 in chunks of 32.
// 8 warps: warp tile 64(m) x 32(n). grid (M/128, N/128, nmat).
// mat 0/1 -> Q/K transposed store, 2 -> V natural, 3 -> out row-major.
// ---------------------------------------------------------------------------
#define PADK 36                    // 32 + 4 pad: conflict-free LDS
#define RA_H 0
#define RA_L (128 * PADK)
#define RB_H (2 * 128 * PADK)
#define RB_L (3 * 128 * PADK)
#define SMEM_GEMM (4 * 128 * PADK * 4)   // 73728 bytes

__global__ __launch_bounds__(256, 1)
void mma_gemm_kernel(const float* __restrict__ Aparam, int matBase,
                     const float* __restrict__ bias, float* __restrict__ outp) {
    extern __shared__ float sm[];

    const int mat = matBase + blockIdx.z;
    const int m0  = blockIdx.x * 128;
    const int n0  = blockIdx.y * 128;
    const float* A   = (mat >= 3) ? g_heads : Aparam;
    const float* Bhi = g_Bhi + (size_t)mat * DD * DD;
    const float* Blo = g_Blo + (size_t)mat * DD * DD;

    const int tid  = threadIdx.x;
    const int wid  = tid >> 5;
    const int lane = tid & 31;
    const int wm   = (wid >> 2) * 64;   // 0 or 64
    const int wn   = (wid & 3) * 32;    // 0..96
    const int g    = lane >> 2;         // 0..7
    const int t4   = lane & 3;          // 0..3

    const int srow = tid >> 3;          // 0..31
    const int scol = (tid & 7) * 4;     // 0..28

    float acc[4][4][4] = {};            // [mi][ni][c]

    float4 pa[4], pbh[4], pbl[4];
#pragma unroll
    for (int q = 0; q < 4; q++) {
        const int r = srow + q * 32;
        pa[q]  = *(const float4*)(A   + (size_t)(m0 + r) * DD + scol);
        pbh[q] = *(const float4*)(Bhi + (size_t)(n0 + r) * DD + scol);
        pbl[q] = *(const float4*)(Blo + (size_t)(n0 + r) * DD + scol);
    }

    for (int ch = 0; ch < 16; ch++) {
#pragma unroll
        for (int q = 0; q < 4; q++) {
            const int r = srow + q * 32;
            float4 v  = pa[q];
            float4 hi = make_float4(tf32_hi(v.x), tf32_hi(v.y),
                                    tf32_hi(v.z), tf32_hi(v.w));
            float4 lo = make_float4(v.x - hi.x, v.y - hi.y,
                                    v.z - hi.z, v.w - hi.w);
            *(float4*)&sm[RA_H + r * PADK + scol] = hi;
            *(float4*)&sm[RA_L + r * PADK + scol] = lo;
            *(float4*)&sm[RB_H + r * PADK + scol] = pbh[q];
            *(float4*)&sm[RB_L + r * PADK + scol] = pbl[q];
        }
        __syncthreads();

        if (ch < 15) {
            const int d1 = (ch + 1) * 32;
#pragma unroll
            for (int q = 0; q < 4; q++) {
                const int r = srow + q * 32;
                pa[q]  = *(const float4*)(A   + (size_t)(m0 + r) * DD + d1 + scol);
                pbh[q] = *(const float4*)(Bhi + (size_t)(n0 + r) * DD + d1 + scol);
                pbl[q] = *(const float4*)(Blo + (size_t)(n0 + r) * DD + d1 + scol);
            }
        }

#pragma unroll
        for (int k8 = 0; k8 < 4; k8++) {
            float aH[4][4], aL[4][4];
#pragma unroll
            for (int mi = 0; mi < 4; mi++) {
                const int rb = (wm + mi * 16 + g) * PADK + k8 * 8 + t4;
                aH[mi][0] = sm[RA_H + rb];
                aH[mi][1] = sm[RA_H + rb + 8 * PADK];
                aH[mi][2] = sm[RA_H + rb + 4];
                aH[mi][3] = sm[RA_H + rb + 8 * PADK + 4];
                aL[mi][0] = sm[RA_L + rb];
                aL[mi][1] = sm[RA_L + rb + 8 * PADK];
                aL[mi][2] = sm[RA_L + rb + 4];
                aL[mi][3] = sm[RA_L + rb + 8 * PADK + 4];
            }
#pragma unroll
            for (int ni = 0; ni < 4; ni++) {
                const int nb = (wn + ni * 8 + g) * PADK + k8 * 8 + t4;
                float bH[2] = { sm[RB_H + nb], sm[RB_H + nb + 4] };
                float bL[2] = { sm[RB_L + nb], sm[RB_L + nb + 4] };
#pragma unroll
                for (int mi = 0; mi < 4; mi++) {
                    mma8(acc[mi][ni], aH[mi], bH);
                    mma8(acc[mi][ni], aL[mi], bH);
                    mma8(acc[mi][ni], aH[mi], bL);
                }
            }
        }
        __syncthreads();
    }

    // epilogue
    const float bv = bias[0];
#pragma unroll
    for (int mi = 0; mi < 4; mi++) {
#pragma unroll
        for (int h2 = 0; h2 < 2; h2++) {
            const int row  = m0 + wm + mi * 16 + g + 8 * h2;
            const int b    = row >> 9;
            const int s    = row & 511;
#pragma unroll
            for (int ni = 0; ni < 4; ni++) {
                const int col0 = n0 + wn + ni * 8 + 2 * t4;
                const float v0 = acc[mi][ni][2 * h2]     + bv;
                const float v1 = acc[mi][ni][2 * h2 + 1] + bv;
                if (mat < 2) {
                    float* dst = (mat == 0) ? g_Q : g_K;
                    float* base = dst + ((size_t)(b * HH + (col0 >> 6)) * DKK) * SS;
                    base[(size_t)(col0 & 63) * SS + s]       = v0;
                    base[(size_t)((col0 & 63) + 1) * SS + s] = v1;
                } else if (mat == 2) {
                    *(float2*)(g_V + ((size_t)(b * HH + (col0 >> 6)) * SS + s) * DKK
                               + (col0 & 63)) = make_float2(v0, v1);
                } else {
                    *(float2*)(outp + (size_t)row * DD + col0) = make_float2(v0, v1);
                }
            }
        }
    }
}

// ---------------------------------------------------------------------------
// Flash attention (SIMT, packed f32x2). grid (S/64, B*H), block 256.
// ---------------------------------------------------------------------------
__global__ __launch_bounds__(256, 2)
void attn_kernel(const int* __restrict__ mask) {
    extern __shared__ float smf[];
    float* Qt = smf;            // [64 d][64 q]
    float* Kt = smf + 4096;     // [64 d][64 k]
    float* Vs = smf + 8192;     // [64 k][64 v]
    float* Pt = smf + 12288;    // [64 k][64 q] stride 68

    const int q0 = blockIdx.x * 64;
    const int bh = blockIdx.y;
    const int b  = bh / HH;
    const int h  = bh % HH;

    const int tid = threadIdx.x;
    const int tq  = tid >> 4;
    const int tk  = tid & 15;

#pragma unroll
    for (int t = 0; t < 4; t++) {
        int lin = tid + t * 256;
        int r   = lin >> 4;
        int cc  = (lin & 15) * 4;
        *(float4*)&Qt[r * 64 + cc] =
            *(const float4*)(g_Q + ((size_t)bh * DKK + r) * SS + q0 + cc);
    }

    float4 kreg[4], vreg[4];
#pragma unroll
    for (int t = 0; t < 4; t++) {
        int lin = tid + t * 256;
        int r   = lin >> 4;
        int cc  = (lin & 15) * 4;
        kreg[t] = *(const float4*)(g_K + ((size_t)bh * DKK + r) * SS + cc);
        vreg[t] = *(const float4*)(g_V + ((size_t)bh * SS + r) * DKK + cc);
    }

    float mi[4], li[4];
    u64 o2[4][2] = {};
#pragma unroll
    for (int i = 0; i < 4; i++) { mi[i] = -1e30f; li[i] = 0.0f; }

    const float scale = 0.125f;

    for (int kt = 0; kt < 8; kt++) {
        __syncthreads();
#pragma unroll
        for (int t = 0; t < 4; t++) {
            int lin = tid + t * 256;
            int r   = lin >> 4;
            int cc  = (lin & 15) * 4;
            *(float4*)&Kt[r * 64 + cc] = kreg[t];
            *(float4*)&Vs[r * 64 + cc] = vreg[t];
        }
        int4 mk = *(const int4*)(mask + b * SS + kt * 64 + tk * 4);
        __syncthreads();

        const int kn = (kt < 7) ? kt + 1 : kt;
#pragma unroll
        for (int t = 0; t < 4; t++) {
            int lin = tid + t * 256;
            int r   = lin >> 4;
            int cc  = (lin & 15) * 4;
            kreg[t] = *(const float4*)(g_K + ((size_t)bh * DKK + r) * SS + kn * 64 + cc);
            vreg[t] = *(const float4*)(g_V + ((size_t)bh * SS + kn * 64 + r) * DKK + cc);
        }

        u64 s2[4][2] = {};
#pragma unroll
        for (int dd = 0; dd < 64; dd++) {
            float4 a = *(const float4*)&Qt[dd * 64 + tq * 4];
            ulonglong2 bb = *(const ulonglong2*)&Kt[dd * 64 + tk * 4];
            u64 d0_ = dup2(a.x), d1_ = dup2(a.y), d2_ = dup2(a.z), d3_ = dup2(a.w);
            ffma2(s2[0][0], d0_, bb.x); ffma2(s2[0][1], d0_, bb.y);
            ffma2(s2[1][0], d1_, bb.x); ffma2(s2[1][1], d1_, bb.y);
            ffma2(s2[2][0], d2_, bb.x); ffma2(s2[2][1], d2_, bb.y);
            ffma2(s2[3][0], d3_, bb.x); ffma2(s2[3][1], d3_, bb.y);
        }

        float p[4][4];
#pragma unroll
        for (int i = 0; i < 4; i++) {
            float2 t0 = unpk(s2[i][0]);
            float2 t1 = unpk(s2[i][1]);
            p[i][0] = mk.x ? t0.x * scale : -1e30f;
            p[i][1] = mk.y ? t0.y * scale : -1e30f;
            p[i][2] = mk.z ? t1.x * scale : -1e30f;
            p[i][3] = mk.w ? t1.y * scale : -1e30f;
        }

#pragma unroll
        for (int i = 0; i < 4; i++) {
            float rmax = fmaxf(fmaxf(p[i][0], p[i][1]), fmaxf(p[i][2], p[i][3]));
            rmax = redmax16(rmax);
            float mn = fmaxf(mi[i], rmax);
            float al = __expf(mi[i] - mn);
            p[i][0] = __expf(p[i][0] - mn);
            p[i][1] = __expf(p[i][1] - mn);
            p[i][2] = __expf(p[i][2] - mn);
            p[i][3] = __expf(p[i][3] - mn);
            float rs = p[i][0] + p[i][1] + p[i][2] + p[i][3];
            rs = redsum16(rs);
            li[i] = li[i] * al + rs;
            mi[i] = mn;
            u64 ad = dup2(al);
            mul2(o2[i][0], ad);
            mul2(o2[i][1], ad);
        }

#pragma unroll
        for (int j = 0; j < 4; j++) {
            *(float4*)&Pt[(tk * 4 + j) * 68 + tq * 4] =
                make_float4(p[0][j], p[1][j], p[2][j], p[3][j]);
        }
        __syncthreads();

#pragma unroll
        for (int kk = 0; kk < 64; kk++) {
            float4 pp = *(const float4*)&Pt[kk * 68 + tq * 4];
            ulonglong2 vv = *(const ulonglong2*)&Vs[kk * 64 + tk * 4];
            u64 d0_ = dup2(pp.x), d1_ = dup2(pp.y), d2_ = dup2(pp.z), d3_ = dup2(pp.w);
            ffma2(o2[0][0], d0_, vv.x); ffma2(o2[0][1], d0_, vv.y);
            ffma2(o2[1][0], d1_, vv.x); ffma2(o2[1][1], d1_, vv.y);
            ffma2(o2[2][0], d2_, vv.x); ffma2(o2[2][1], d2_, vv.y);
            ffma2(o2[3][0], d3_, vv.x); ffma2(o2[3][1], d3_, vv.y);
        }
    }

#pragma unroll
    for (int i = 0; i < 4; i++) {
        float inv = 1.0f / li[i];
        float2 t0 = unpk(o2[i][0]);
        float2 t1 = unpk(o2[i][1]);
        size_t row = (size_t)b * SS + q0 + tq * 4 + i;
        *(float4*)(g_heads + row * DD + h * DKK + tk * 4) =
            make_float4(t0.x * inv, t0.y * inv, t1.x * inv, t1.y * inv);
    }
}

// ---------------------------------------------------------------------------
extern "C" void kernel_launch(void* const* d_in, const int* in_sizes, int n_in,
                              void* d_out, int out_size) {
    const float* x    = (const float*)d_in[0];
    const int*   mask = (const int*)  d_in[1];
    const float* Wq   = (const float*)d_in[2];
    const float* Wk   = (const float*)d_in[3];
    const float* Wv   = (const float*)d_in[4];
    const float* Wo   = (const float*)d_in[5];
    const float* bias = (const float*)d_in[6];
    float* out = (float*)d_out;

    // 0) transpose + hi/lo split all weight matrices
    prep_kernel<<<dim3(8, 8, 4), 256>>>(Wq, Wk, Wv, Wo);

    // 1) QKV projections on tensor cores (3xTF32 mma.sync)
    cudaFuncSetAttribute(mma_gemm_kernel,
                         cudaFuncAttributeMaxDynamicSharedMemorySize, SMEM_GEMM);
    mma_gemm_kernel<<<dim3(MM / 128, 4, 3), 256, SMEM_GEMM>>>(x, 0, bias, out);

    // 2) fused masked-softmax attention (flash style, SIMT)
    const int smem_attn = (3 * 64 * 64 + 64 * 68) * (int)sizeof(float);
    cudaFuncSetAttribute(attn_kernel, cudaFuncAttributeMaxDynamicSharedMemorySize,
                         smem_attn);
    attn_kernel<<<dim3(SS / 64, BB * HH), 256, smem_attn>>>(mask);

    // 3) output projection on tensor cores (3xTF32 mma.sync)
    mma_gemm_kernel<<<dim3(MM / 128, 4, 1), 256, SMEM_GEMM>>>(x, 3, bias, out);
}

// round 6
// speedup vs baseline: 1.5547x; 1.1952x over previous
#include <cuda_runtime.h>
#include <cuda_bf16.h>
#include <cstdint>

#define BB  32
#define SS  512
#define DD  512
#define HH  8
#define DKK 64
#define MM  (BB*SS)   // 16384

typedef unsigned long long u64;
typedef __nv_bfloat16 bf16;

// Scratch (device globals; no runtime allocation allowed)
__device__ float g_Q[(size_t)BB*HH*DKK*SS];   // [BH][DK][S] (pre-transposed)
__device__ float g_K[(size_t)BB*HH*DKK*SS];   // [BH][DK][S] (pre-transposed)
__device__ float g_V[(size_t)BB*HH*SS*DKK];   // [BH][S][DK]
__device__ bf16  g_xhi[(size_t)MM*DD];        // x split hi (bf16)
__device__ bf16  g_xlo[(size_t)MM*DD];        // x split lo
__device__ bf16  g_hhi[(size_t)MM*DD];        // heads split hi
__device__ bf16  g_hlo[(size_t)MM*DD];        // heads split lo
__device__ bf16  g_Whi[(size_t)4*DD*DD];      // [mat][n][k] bf16-hi weights
__device__ bf16  g_Wlo[(size_t)4*DD*DD];      // [mat][n][k] bf16-lo weights

// ===================== PTX helpers =====================
__device__ __forceinline__ void cpasync16(uint32_t s, const void* g) {
    asm volatile("cp.async.cg.shared.global [%0], [%1], 16;" :: "r"(s), "l"(g));
}
__device__ __forceinline__ void cpcommit() {
    asm volatile("cp.async.commit_group;" ::: "memory");
}
template <int N> __device__ __forceinline__ void cpwait() {
    asm volatile("cp.async.wait_group %0;" :: "n"(N) : "memory");
}
#define LDMX4(r, a)                                                            \
    asm volatile("ldmatrix.sync.aligned.m8n8.x4.shared.b16 {%0,%1,%2,%3}, [%4];" \
        : "=r"((r)[0]), "=r"((r)[1]), "=r"((r)[2]), "=r"((r)[3]) : "r"(a))

__device__ __forceinline__ void mma16(float* c, const uint32_t* a,
                                      uint32_t b0, uint32_t b1) {
    asm volatile(
        "mma.sync.aligned.m16n8k16.row.col.f32.bf16.bf16.f32 "
        "{%0,%1,%2,%3},{%4,%5,%6,%7},{%8,%9},{%0,%1,%2,%3};"
        : "+f"(c[0]), "+f"(c[1]), "+f"(c[2]), "+f"(c[3])
        : "r"(a[0]), "r"(a[1]), "r"(a[2]), "r"(a[3]), "r"(b0), "r"(b1));
}

__device__ __forceinline__ uint32_t pack2(bf16 a, bf16 b) {
    return (uint32_t)__bfloat16_as_ushort(a) |
           ((uint32_t)__bfloat16_as_ushort(b) << 16);
}

// ===================== SIMT helpers for attention =====================
__device__ __forceinline__ u64 dup2(float v) {
    u64 r; asm("mov.b64 %0, {%1, %1};" : "=l"(r) : "f"(v)); return r;
}
__device__ __forceinline__ void ffma2(u64 &c, u64 a, u64 b) {
    asm("fma.rn.f32x2 %0, %1, %2, %0;" : "+l"(c) : "l"(a), "l"(b));
}
__device__ __forceinline__ void mul2(u64 &c, u64 a) {
    asm("mul.rn.f32x2 %0, %0, %1;" : "+l"(c) : "l"(a));
}
__device__ __forceinline__ float2 unpk(u64 v) {
    float2 r; asm("mov.b64 {%0, %1}, %2;" : "=f"(r.x), "=f"(r.y) : "l"(v)); return r;
}
__device__ __forceinline__ float redmax16(float v) {
    v = fmaxf(v, __shfl_xor_sync(0xffffffffu, v, 1));
    v = fmaxf(v, __shfl_xor_sync(0xffffffffu, v, 2));
    v = fmaxf(v, __shfl_xor_sync(0xffffffffu, v, 4));
    v = fmaxf(v, __shfl_xor_sync(0xffffffffu, v, 8));
    return v;
}
__device__ __forceinline__ float redsum16(float v) {
    v += __shfl_xor_sync(0xffffffffu, v, 1);
    v += __shfl_xor_sync(0xffffffffu, v, 2);
    v += __shfl_xor_sync(0xffffffffu, v, 4);
    v += __shfl_xor_sync(0xffffffffu, v, 8);
    return v;
}

// ---------------------------------------------------------------------------
// Prep W: transpose weights into [mat][n][k], split to bf16 hi/lo.
// grid (8, 8, 4), block 256.
// ---------------------------------------------------------------------------
__global__ void prepw_kernel(const float* __restrict__ Wq,
                             const float* __restrict__ Wk,
                             const float* __restrict__ Wv,
                             const float* __restrict__ Wo) {
    __shared__ float t[64][65];
    const int z  = blockIdx.z;
    const int y  = blockIdx.y;
    const int xt = blockIdx.x;
    const float* W = (z == 0) ? Wq : (z == 1) ? Wk : (z == 2) ? Wv : Wo;
    const int tid = threadIdx.x;

#pragma unroll
    for (int i = 0; i < 4; i++) {
        int idx = tid + i * 256;
        int r   = idx >> 4;
        int c4  = (idx & 15) * 4;
        const float* p = (z < 3)
            ? W + (size_t)y * DD * DKK + (size_t)(xt * 64 + r) * DKK + c4
            : W + (size_t)(xt * 64 + r) * DD + y * 64 + c4;
        float4 v = *(const float4*)p;
        t[c4 + 0][r] = v.x; t[c4 + 1][r] = v.y;
        t[c4 + 2][r] = v.z; t[c4 + 3][r] = v.w;
    }
    __syncthreads();

    bf16* oh = g_Whi + (size_t)z * DD * DD;
    bf16* ol = g_Wlo + (size_t)z * DD * DD;
#pragma unroll
    for (int i = 0; i < 4; i++) {
        int idx = tid + i * 256;
        int c   = idx >> 4;
        int r4  = (idx & 15) * 4;
        size_t o = (size_t)(y * 64 + c) * DD + xt * 64 + r4;
        uint2 uh, ul;
        float v0 = t[c][r4],     v1 = t[c][r4 + 1];
        float v2 = t[c][r4 + 2], v3 = t[c][r4 + 3];
        bf16 h0 = __float2bfloat16(v0), h1 = __float2bfloat16(v1);
        bf16 h2 = __float2bfloat16(v2), h3 = __float2bfloat16(v3);
        uh.x = pack2(h0, h1); uh.y = pack2(h2, h3);
        ul.x = pack2(__float2bfloat16(v0 - __bfloat162float(h0)),
                     __float2bfloat16(v1 - __bfloat162float(h1)));
        ul.y = pack2(__float2bfloat16(v2 - __bfloat162float(h2)),
                     __float2bfloat16(v3 - __bfloat162float(h3)));
        *(uint2*)(oh + o) = uh;
        *(uint2*)(ol + o) = ul;
    }
}

// ---------------------------------------------------------------------------
// Prep X: split x into bf16 hi/lo, row-major. grid 8192, block 256 (4 el/thr).
// ---------------------------------------------------------------------------
__global__ void prepx_kernel(const float* __restrict__ x) {
    const size_t i4 = (size_t)blockIdx.x * 256 + threadIdx.x;   // float4 index
    float4 v = ((const float4*)x)[i4];
    bf16 h0 = __float2bfloat16(v.x), h1 = __float2bfloat16(v.y);
    bf16 h2 = __float2bfloat16(v.z), h3 = __float2bfloat16(v.w);
    uint2 uh, ul;
    uh.x = pack2(h0, h1); uh.y = pack2(h2, h3);
    ul.x = pack2(__float2bfloat16(v.x - __bfloat162float(h0)),
                 __float2bfloat16(v.y - __bfloat162float(h1)));
    ul.y = pack2(__float2bfloat16(v.z - __bfloat162float(h2)),
                 __float2bfloat16(v.w - __bfloat162float(h3)));
    *(uint2*)(g_xhi + i4 * 4) = uh;
    *(uint2*)(g_xlo + i4 * 4) = ul;
}

// ---------------------------------------------------------------------------
// bf16 3x-split GEMM on mma.sync m16n8k16 + ldmatrix + cp.async pipeline.
// Block tile 128x128, K=512 in chunks of 32, 3-stage pipeline.
// 8 warps: warp tile 64(m) x 32(n). grid (M/128, N/128, nmat).
// mat 0/1 -> Q/K transposed store, 2 -> V natural, 3 -> out row-major.
// ---------------------------------------------------------------------------
#define CHK  32                 // K elems per chunk
#define ROWB 80                 // 64 data bytes + 16 pad (conflict-free ldmatrix)
#define BUFB (128 * ROWB)       // 10240 per buffer
#define STGB (4 * BUFB)         // Ah, Al, Bh, Bl
#define NSTG 3
#define SMEM_GEMM (NSTG * STGB) // 122880

__global__ __launch_bounds__(256, 1)
void mma_gemm_kernel(int matBase, const float* __restrict__ bias,
                     float* __restrict__ outp) {
    extern __shared__ char smc[];
    const uint32_t sb0 = (uint32_t)__cvta_generic_to_shared(smc);

    const int mat = matBase + blockIdx.z;
    const int m0  = blockIdx.x * 128;
    const int n0  = blockIdx.y * 128;
    const bf16* Ahi = (mat >= 3) ? g_hhi : g_xhi;
    const bf16* Alo = (mat >= 3) ? g_hlo : g_xlo;
    const bf16* Bhi = g_Whi + (size_t)mat * DD * DD;
    const bf16* Blo = g_Wlo + (size_t)mat * DD * DD;

    const int tid  = threadIdx.x;
    const int wid  = tid >> 5;
    const int lane = tid & 31;
    const int wm   = (wid >> 2) * 64;   // 0 or 64
    const int wn   = (wid & 3) * 32;    // 0..96
    const int g    = lane >> 2;         // 0..7
    const int t4   = lane & 3;          // 0..3

    // ldmatrix per-lane offset: q = lane>>3 selects submatrix, r = lane&7 row
    const uint32_t lq   = lane >> 3;
    const uint32_t lr   = lane & 7;
    const uint32_t lmo  = (lr + (lq & 1) * 8) * ROWB + (lq >> 1) * 16;

    float acc[4][4][4] = {};            // [mi][ni][c]

    // cp.async issue helper (inlined twice via lambda-like macro)
    const int irow = tid >> 1;                 // not used; mapping below
#define ISSUE(ch) do {                                                         \
        const int d0 = (ch) * CHK;                                             \
        const uint32_t st = sb0 + ((ch) % NSTG) * STGB;                        \
        _Pragma("unroll")                                                      \
        for (int t = 0; t < 2; t++) {                                          \
            int idx = tid + 256 * t;                                           \
            int row = idx >> 2;                                                \
            int seg = idx & 3;                                                 \
            uint32_t so = (uint32_t)(row * ROWB + seg * 16);                   \
            size_t  ga  = (size_t)(m0 + row) * DD + d0 + seg * 8;              \
            size_t  gb  = (size_t)(n0 + row) * DD + d0 + seg * 8;              \
            cpasync16(st + so,            Ahi + ga);                           \
            cpasync16(st + BUFB + so,     Alo + ga);                           \
            cpasync16(st + 2 * BUFB + so, Bhi + gb);                           \
            cpasync16(st + 3 * BUFB + so, Blo + gb);                           \
        }                                                                      \
        cpcommit();                                                            \
    } while (0)

    ISSUE(0);
    ISSUE(1);

    for (int ch = 0; ch < 16; ch++) {
        if (ch >= 14) cpwait<0>(); else cpwait<1>();
        __syncthreads();
        if (ch + 2 < 16) ISSUE(ch + 2);

        const uint32_t st = sb0 + (ch % NSTG) * STGB;
#pragma unroll
        for (int kk = 0; kk < 2; kk++) {
            const uint32_t ko = kk * 32;
            uint32_t aH[4][4], aL[4][4], bH[2][4], bL[2][4];
#pragma unroll
            for (int mi = 0; mi < 4; mi++) {
                uint32_t ad = st + (uint32_t)((wm + mi * 16) * ROWB) + ko + lmo;
                LDMX4(aH[mi], ad);
                LDMX4(aL[mi], ad + BUFB);
            }
#pragma unroll
            for (int nn = 0; nn < 2; nn++) {
                uint32_t bd = st + 2 * BUFB + (uint32_t)((wn + nn * 16) * ROWB) + ko + lmo;
                LDMX4(bH[nn], bd);
                LDMX4(bL[nn], bd + BUFB);
            }
#pragma unroll
            for (int mi = 0; mi < 4; mi++)
#pragma unroll
                for (int ni = 0; ni < 4; ni++) {
                    const int nn = ni >> 1, sel = ni & 1;
                    mma16(acc[mi][ni], aH[mi], bH[nn][sel], bH[nn][sel + 2]);
                    mma16(acc[mi][ni], aL[mi], bH[nn][sel], bH[nn][sel + 2]);
                    mma16(acc[mi][ni], aH[mi], bL[nn][sel], bL[nn][sel + 2]);
                }
        }
        __syncthreads();
    }

    // epilogue
    const float bv = bias[0];
#pragma unroll
    for (int mi = 0; mi < 4; mi++) {
#pragma unroll
        for (int h2 = 0; h2 < 2; h2++) {
            const int row = m0 + wm + mi * 16 + g + 8 * h2;
            const int b   = row >> 9;
            const int s   = row & 511;
#pragma unroll
            for (int ni = 0; ni < 4; ni++) {
                const int col0 = n0 + wn + ni * 8 + 2 * t4;
                const float v0 = acc[mi][ni][2 * h2]     + bv;
                const float v1 = acc[mi][ni][2 * h2 + 1] + bv;
                if (mat < 2) {
                    float* dst = (mat == 0) ? g_Q : g_K;
                    float* base = dst + ((size_t)(b * HH + (col0 >> 6)) * DKK) * SS;
                    base[(size_t)(col0 & 63) * SS + s]       = v0;
                    base[(size_t)((col0 & 63) + 1) * SS + s] = v1;
                } else if (mat == 2) {
                    *(float2*)(g_V + ((size_t)(b * HH + (col0 >> 6)) * SS + s) * DKK
                               + (col0 & 63)) = make_float2(v0, v1);
                } else {
                    *(float2*)(outp + (size_t)row * DD + col0) = make_float2(v0, v1);
                }
            }
        }
    }
#undef ISSUE
}

// ---------------------------------------------------------------------------
// Flash attention (SIMT, packed f32x2). grid (S/64, B*H), block 256.
// Epilogue writes heads as bf16 hi/lo for the oproj GEMM.
// ---------------------------------------------------------------------------
__global__ __launch_bounds__(256, 2)
void attn_kernel(const int* __restrict__ mask) {
    extern __shared__ float smf[];
    float* Qt = smf;            // [64 d][64 q]
    float* Kt = smf + 4096;     // [64 d][64 k]
    float* Vs = smf + 8192;     // [64 k][64 v]
    float* Pt = smf + 12288;    // [64 k][64 q] stride 68

    const int q0 = blockIdx.x * 64;
    const int bh = blockIdx.y;
    const int b  = bh / HH;
    const int h  = bh % HH;

    const int tid = threadIdx.x;
    const int tq  = tid >> 4;
    const int tk  = tid & 15;

#pragma unroll
    for (int t = 0; t < 4; t++) {
        int lin = tid + t * 256;
        int r   = lin >> 4;
        int cc  = (lin & 15) * 4;
        *(float4*)&Qt[r * 64 + cc] =
            *(const float4*)(g_Q + ((size_t)bh * DKK + r) * SS + q0 + cc);
    }

    float4 kreg[4], vreg[4];
#pragma unroll
    for (int t = 0; t < 4; t++) {
        int lin = tid + t * 256;
        int r   = lin >> 4;
        int cc  = (lin & 15) * 4;
        kreg[t] = *(const float4*)(g_K + ((size_t)bh * DKK + r) * SS + cc);
        vreg[t] = *(const float4*)(g_V + ((size_t)bh * SS + r) * DKK + cc);
    }

    float mi[4], li[4];
    u64 o2[4][2] = {};
#pragma unroll
    for (int i = 0; i < 4; i++) { mi[i] = -1e30f; li[i] = 0.0f; }

    const float scale = 0.125f;

    for (int kt = 0; kt < 8; kt++) {
        __syncthreads();
#pragma unroll
        for (int t = 0; t < 4; t++) {
            int lin = tid + t * 256;
            int r   = lin >> 4;
            int cc  = (lin & 15) * 4;
            *(float4*)&Kt[r * 64 + cc] = kreg[t];
            *(float4*)&Vs[r * 64 + cc] = vreg[t];
        }
        int4 mk = *(const int4*)(mask + b * SS + kt * 64 + tk * 4);
        __syncthreads();

        const int kn = (kt < 7) ? kt + 1 : kt;
#pragma unroll
        for (int t = 0; t < 4; t++) {
            int lin = tid + t * 256;
            int r   = lin >> 4;
            int cc  = (lin & 15) * 4;
            kreg[t] = *(const float4*)(g_K + ((size_t)bh * DKK + r) * SS + kn * 64 + cc);
            vreg[t] = *(const float4*)(g_V + ((size_t)bh * SS + kn * 64 + r) * DKK + cc);
        }

        u64 s2[4][2] = {};
#pragma unroll
        for (int dd = 0; dd < 64; dd++) {
            float4 a = *(const float4*)&Qt[dd * 64 + tq * 4];
            ulonglong2 bb = *(const ulonglong2*)&Kt[dd * 64 + tk * 4];
            u64 d0_ = dup2(a.x), d1_ = dup2(a.y), d2_ = dup2(a.z), d3_ = dup2(a.w);
            ffma2(s2[0][0], d0_, bb.x); ffma2(s2[0][1], d0_, bb.y);
            ffma2(s2[1][0], d1_, bb.x); ffma2(s2[1][1], d1_, bb.y);
            ffma2(s2[2][0], d2_, bb.x); ffma2(s2[2][1], d2_, bb.y);
            ffma2(s2[3][0], d3_, bb.x); ffma2(s2[3][1], d3_, bb.y);
        }

        float p[4][4];
#pragma unroll
        for (int i = 0; i < 4; i++) {
            float2 t0 = unpk(s2[i][0]);
            float2 t1 = unpk(s2[i][1]);
            p[i][0] = mk.x ? t0.x * scale : -1e30f;
            p[i][1] = mk.y ? t0.y * scale : -1e30f;
            p[i][2] = mk.z ? t1.x * scale : -1e30f;
            p[i][3] = mk.w ? t1.y * scale : -1e30f;
        }

#pragma unroll
        for (int i = 0; i < 4; i++) {
            float rmax = fmaxf(fmaxf(p[i][0], p[i][1]), fmaxf(p[i][2], p[i][3]));
            rmax = redmax16(rmax);
            float mn = fmaxf(mi[i], rmax);
            float al = __expf(mi[i] - mn);
            p[i][0] = __expf(p[i][0] - mn);
            p[i][1] = __expf(p[i][1] - mn);
            p[i][2] = __expf(p[i][2] - mn);
            p[i][3] = __expf(p[i][3] - mn);
            float rs = p[i][0] + p[i][1] + p[i][2] + p[i][3];
            rs = redsum16(rs);
            li[i] = li[i] * al + rs;
            mi[i] = mn;
            u64 ad = dup2(al);
            mul2(o2[i][0], ad);
            mul2(o2[i][1], ad);
        }

#pragma unroll
        for (int j = 0; j < 4; j++) {
            *(float4*)&Pt[(tk * 4 + j) * 68 + tq * 4] =
                make_float4(p[0][j], p[1][j], p[2][j], p[3][j]);
        }
        __syncthreads();

#pragma unroll
        for (int kk = 0; kk < 64; kk++) {
            float4 pp = *(const float4*)&Pt[kk * 68 + tq * 4];
            ulonglong2 vv = *(const ulonglong2*)&Vs[kk * 64 + tk * 4];
            u64 d0_ = dup2(pp.x), d1_ = dup2(pp.y), d2_ = dup2(pp.z), d3_ = dup2(pp.w);
            ffma2(o2[0][0], d0_, vv.x); ffma2(o2[0][1], d0_, vv.y);
            ffma2(o2[1][0], d1_, vv.x); ffma2(o2[1][1], d1_, vv.y);
            ffma2(o2[2][0], d2_, vv.x); ffma2(o2[2][1], d2_, vv.y);
            ffma2(o2[3][0], d3_, vv.x); ffma2(o2[3][1], d3_, vv.y);
        }
    }

    // finalize: split heads to bf16 hi/lo
#pragma unroll
    for (int i = 0; i < 4; i++) {
        float inv = 1.0f / li[i];
        float2 t0 = unpk(o2[i][0]);
        float2 t1 = unpk(o2[i][1]);
        float v0 = t0.x * inv, v1 = t0.y * inv, v2 = t1.x * inv, v3 = t1.y * inv;
        bf16 h0 = __float2bfloat16(v0), h1 = __float2bfloat16(v1);
        bf16 h2 = __float2bfloat16(v2), h3 = __float2bfloat16(v3);
        uint2 uh, ul;
        uh.x = pack2(h0, h1); uh.y = pack2(h2, h3);
        ul.x = pack2(__float2bfloat16(v0 - __bfloat162float(h0)),
                     __float2bfloat16(v1 - __bfloat162float(h1)));
        ul.y = pack2(__float2bfloat16(v2 - __bfloat162float(h2)),
                     __float2bfloat16(v3 - __bfloat162float(h3)));
        size_t off = ((size_t)b * SS + q0 + tq * 4 + i) * DD + h * DKK + tk * 4;
        *(uint2*)(g_hhi + off) = uh;
        *(uint2*)(g_hlo + off) = ul;
    }
}

// ---------------------------------------------------------------------------
extern "C" void kernel_launch(void* const* d_in, const int* in_sizes, int n_in,
                              void* d_out, int out_size) {
    const float* x    = (const float*)d_in[0];
    const int*   mask = (const int*)  d_in[1];
    const float* Wq   = (const float*)d_in[2];
    const float* Wk   = (const float*)d_in[3];
    const float* Wv   = (const float*)d_in[4];
    const float* Wo   = (const float*)d_in[5];
    const float* bias = (const float*)d_in[6];
    float* out = (float*)d_out;

    // 0) weight transpose + bf16 hi/lo split; x bf16 hi/lo split
    prepw_kernel<<<dim3(8, 8, 4), 256>>>(Wq, Wk, Wv, Wo);
    prepx_kernel<<<MM * DD / 4 / 256, 256>>>(x);

    // 1) QKV projections (3xBF16 mma.sync + ldmatrix + cp.async)
    cudaFuncSetAttribute(mma_gemm_kernel,
                         cudaFuncAttributeMaxDynamicSharedMemorySize, SMEM_GEMM);
    mma_gemm_kernel<<<dim3(MM / 128, 4, 3), 256, SMEM_GEMM>>>(0, bias, out);

    // 2) fused masked-softmax attention (flash style, SIMT)
    const int smem_attn = (3 * 64 * 64 + 64 * 68) * (int)sizeof(float);
    cudaFuncSetAttribute(attn_kernel, cudaFuncAttributeMaxDynamicSharedMemorySize,
                         smem_attn);
    attn_kernel<<<dim3(SS / 64, BB * HH), 256, smem_attn>>>(mask);

    // 3) output projection (3xBF16 mma.sync)
    mma_gemm_kernel<<<dim3(MM / 128, 4, 1), 256, SMEM_GEMM>>>(3, bias, out);
}

// round 7
// speedup vs baseline: 1.9391x; 1.2473x over previous
#include <cuda_runtime.h>
#include <cuda_bf16.h>
#include <cstdint>

#define BB  32
#define SS  512
#define DD  512
#define HH  8
#define DKK 64
#define MM  (BB*SS)   // 16384

typedef __nv_bfloat16 bf16;

// Scratch (device globals; no runtime allocation allowed)
__device__ bf16 g_Qhi[(size_t)BB*HH*SS*DKK];  // [bh][s][dk]
__device__ bf16 g_Qlo[(size_t)BB*HH*SS*DKK];
__device__ bf16 g_Khi[(size_t)BB*HH*SS*DKK];  // [bh][s][dk]
__device__ bf16 g_Klo[(size_t)BB*HH*SS*DKK];
__device__ bf16 g_Vthi[(size_t)BB*HH*DKK*SS]; // [bh][dk][s] (transposed)
__device__ bf16 g_Vtlo[(size_t)BB*HH*DKK*SS];
__device__ bf16 g_xhi[(size_t)MM*DD];         // x split hi
__device__ bf16 g_xlo[(size_t)MM*DD];
__device__ bf16 g_hhi[(size_t)MM*DD];         // heads split hi (concat layout)
__device__ bf16 g_hlo[(size_t)MM*DD];
__device__ bf16 g_Whi[(size_t)4*DD*DD];       // [mat][n][k]
__device__ bf16 g_Wlo[(size_t)4*DD*DD];

// ===================== PTX helpers =====================
__device__ __forceinline__ void cpasync16(uint32_t s, const void* g) {
    asm volatile("cp.async.cg.shared.global [%0], [%1], 16;" :: "r"(s), "l"(g));
}
__device__ __forceinline__ void cpcommit() {
    asm volatile("cp.async.commit_group;" ::: "memory");
}
template <int N> __device__ __forceinline__ void cpwait() {
    asm volatile("cp.async.wait_group %0;" :: "n"(N) : "memory");
}
#define LDMX4(r, a)                                                            \
    asm volatile("ldmatrix.sync.aligned.m8n8.x4.shared.b16 {%0,%1,%2,%3}, [%4];" \
        : "=r"((r)[0]), "=r"((r)[1]), "=r"((r)[2]), "=r"((r)[3]) : "r"(a))

__device__ __forceinline__ void mma16(float* c, const uint32_t* a,
                                      uint32_t b0, uint32_t b1) {
    asm volatile(
        "mma.sync.aligned.m16n8k16.row.col.f32.bf16.bf16.f32 "
        "{%0,%1,%2,%3},{%4,%5,%6,%7},{%8,%9},{%0,%1,%2,%3};"
        : "+f"(c[0]), "+f"(c[1]), "+f"(c[2]), "+f"(c[3])
        : "r"(a[0]), "r"(a[1]), "r"(a[2]), "r"(a[3]), "r"(b0), "r"(b1));
}

__device__ __forceinline__ uint32_t pack2(bf16 a, bf16 b) {
    return (uint32_t)__bfloat16_as_ushort(a) |
           ((uint32_t)__bfloat16_as_ushort(b) << 16);
}
__device__ __forceinline__ uint32_t split_hi(float v0, float v1, uint32_t& lo) {
    bf16 h0 = __float2bfloat16(v0), h1 = __float2bfloat16(v1);
    lo = pack2(__float2bfloat16(v0 - __bfloat162float(h0)),
               __float2bfloat16(v1 - __bfloat162float(h1)));
    return pack2(h0, h1);
}

// ---------------------------------------------------------------------------
// Prep W: transpose weights into [mat][n][k], split to bf16 hi/lo.
// ---------------------------------------------------------------------------
__global__ void prepw_kernel(const float* __restrict__ Wq,
                             const float* __restrict__ Wk,
                             const float* __restrict__ Wv,
                             const float* __restrict__ Wo) {
    __shared__ float t[64][65];
    const int z  = blockIdx.z;
    const int y  = blockIdx.y;
    const int xt = blockIdx.x;
    const float* W = (z == 0) ? Wq : (z == 1) ? Wk : (z == 2) ? Wv : Wo;
    const int tid = threadIdx.x;

#pragma unroll
    for (int i = 0; i < 4; i++) {
        int idx = tid + i * 256;
        int r   = idx >> 4;
        int c4  = (idx & 15) * 4;
        const float* p = (z < 3)
            ? W + (size_t)y * DD * DKK + (size_t)(xt * 64 + r) * DKK + c4
            : W + (size_t)(xt * 64 + r) * DD + y * 64 + c4;
        float4 v = *(const float4*)p;
        t[c4 + 0][r] = v.x; t[c4 + 1][r] = v.y;
        t[c4 + 2][r] = v.z; t[c4 + 3][r] = v.w;
    }
    __syncthreads();

    bf16* oh = g_Whi + (size_t)z * DD * DD;
    bf16* ol = g_Wlo + (size_t)z * DD * DD;
#pragma unroll
    for (int i = 0; i < 4; i++) {
        int idx = tid + i * 256;
        int c   = idx >> 4;
        int r4  = (idx & 15) * 4;
        size_t o = (size_t)(y * 64 + c) * DD + xt * 64 + r4;
        uint2 uh, ul;
        uh.x = split_hi(t[c][r4],     t[c][r4 + 1], ul.x);
        uh.y = split_hi(t[c][r4 + 2], t[c][r4 + 3], ul.y);
        *(uint2*)(oh + o) = uh;
        *(uint2*)(ol + o) = ul;
    }
}

// ---------------------------------------------------------------------------
// Prep X: split x into bf16 hi/lo, row-major.
// ---------------------------------------------------------------------------
__global__ void prepx_kernel(const float* __restrict__ x) {
    const size_t i4 = (size_t)blockIdx.x * 256 + threadIdx.x;
    float4 v = ((const float4*)x)[i4];
    uint2 uh, ul;
    uh.x = split_hi(v.x, v.y, ul.x);
    uh.y = split_hi(v.z, v.w, ul.y);
    *(uint2*)(g_xhi + i4 * 4) = uh;
    *(uint2*)(g_xlo + i4 * 4) = ul;
}

// ---------------------------------------------------------------------------
// bf16 3x-split GEMM (mma.sync + ldmatrix + cp.async). 128x128 tiles.
// mat 0 -> Qhi/lo natural, 1 -> Khi/lo natural, 2 -> Vt transposed,
// 3 -> out fp32 row-major.
// ---------------------------------------------------------------------------
#define ROWB 80
#define BUFB (128 * ROWB)
#define STGB (4 * BUFB)
#define NSTG 3
#define SMEM_GEMM (NSTG * STGB)

__global__ __launch_bounds__(256, 1)
void mma_gemm_kernel(int matBase, const float* __restrict__ bias,
                     float* __restrict__ outp) {
    extern __shared__ char smc[];
    const uint32_t sb0 = (uint32_t)__cvta_generic_to_shared(smc);

    const int mat = matBase + blockIdx.z;
    const int m0  = blockIdx.x * 128;
    const int n0  = blockIdx.y * 128;
    const bf16* Ahi = (mat >= 3) ? g_hhi : g_xhi;
    const bf16* Alo = (mat >= 3) ? g_hlo : g_xlo;
    const bf16* Bhi = g_Whi + (size_t)mat * DD * DD;
    const bf16* Blo = g_Wlo + (size_t)mat * DD * DD;

    const int tid  = threadIdx.x;
    const int wid  = tid >> 5;
    const int lane = tid & 31;
    const int wm   = (wid >> 2) * 64;
    const int wn   = (wid & 3) * 32;
    const int g    = lane >> 2;
    const int t4   = lane & 3;

    const uint32_t lq  = lane >> 3;
    const uint32_t lr  = lane & 7;
    const uint32_t lmo = (lr + (lq & 1) * 8) * ROWB + (lq >> 1) * 16;

    float acc[4][4][4] = {};

#define ISSUE(ch) do {                                                         \
        const int d0 = (ch) * 32;                                              \
        const uint32_t st = sb0 + ((ch) % NSTG) * STGB;                        \
        _Pragma("unroll")                                                      \
        for (int t = 0; t < 2; t++) {                                          \
            int idx = tid + 256 * t;                                           \
            int row = idx >> 2;                                                \
            int seg = idx & 3;                                                 \
            uint32_t so = (uint32_t)(row * ROWB + seg * 16);                   \
            size_t  ga  = (size_t)(m0 + row) * DD + d0 + seg * 8;              \
            size_t  gb  = (size_t)(n0 + row) * DD + d0 + seg * 8;              \
            cpasync16(st + so,            Ahi + ga);                           \
            cpasync16(st + BUFB + so,     Alo + ga);                           \
            cpasync16(st + 2 * BUFB + so, Bhi + gb);                           \
            cpasync16(st + 3 * BUFB + so, Blo + gb);                           \
        }                                                                      \
        cpcommit();                                                            \
    } while (0)

    ISSUE(0);
    ISSUE(1);

    for (int ch = 0; ch < 16; ch++) {
        if (ch >= 14) cpwait<0>(); else cpwait<1>();
        __syncthreads();
        if (ch + 2 < 16) ISSUE(ch + 2);

        const uint32_t st = sb0 + (ch % NSTG) * STGB;
#pragma unroll
        for (int kk = 0; kk < 2; kk++) {
            const uint32_t ko = kk * 32;
            uint32_t aH[4][4], aL[4][4], bH[2][4], bL[2][4];
#pragma unroll
            for (int mi = 0; mi < 4; mi++) {
                uint32_t ad = st + (uint32_t)((wm + mi * 16) * ROWB) + ko + lmo;
                LDMX4(aH[mi], ad);
                LDMX4(aL[mi], ad + BUFB);
            }
#pragma unroll
            for (int nn = 0; nn < 2; nn++) {
                uint32_t bd = st + 2 * BUFB + (uint32_t)((wn + nn * 16) * ROWB) + ko + lmo;
                LDMX4(bH[nn], bd);
                LDMX4(bL[nn], bd + BUFB);
            }
#pragma unroll
            for (int mi = 0; mi < 4; mi++)
#pragma unroll
                for (int ni = 0; ni < 4; ni++) {
                    const int nn = ni >> 1, sel = ni & 1;
                    mma16(acc[mi][ni], aH[mi], bH[nn][sel], bH[nn][sel + 2]);
                    mma16(acc[mi][ni], aL[mi], bH[nn][sel], bH[nn][sel + 2]);
                    mma16(acc[mi][ni], aH[mi], bL[nn][sel], bL[nn][sel + 2]);
                }
        }
        __syncthreads();
    }

    // epilogue
    const float bv = bias[0];
#pragma unroll
    for (int mi = 0; mi < 4; mi++) {
#pragma unroll
        for (int h2 = 0; h2 < 2; h2++) {
            const int row = m0 + wm + mi * 16 + g + 8 * h2;
            const int b   = row >> 9;
            const int s   = row & 511;
#pragma unroll
            for (int ni = 0; ni < 4; ni++) {
                const int col0 = n0 + wn + ni * 8 + 2 * t4;
                const float v0 = acc[mi][ni][2 * h2]     + bv;
                const float v1 = acc[mi][ni][2 * h2 + 1] + bv;
                if (mat < 2) {
                    bf16* dhi = (mat == 0) ? g_Qhi : g_Khi;
                    bf16* dlo = (mat == 0) ? g_Qlo : g_Klo;
                    size_t a = ((size_t)(b * HH + (col0 >> 6)) * SS + s) * DKK
                               + (col0 & 63);
                    uint32_t lo;
                    uint32_t hi = split_hi(v0, v1, lo);
                    *(uint32_t*)(dhi + a) = hi;
                    *(uint32_t*)(dlo + a) = lo;
                } else if (mat == 2) {
                    size_t a = ((size_t)(b * HH + (col0 >> 6)) * DKK + (col0 & 63)) * SS + s;
                    bf16 h0 = __float2bfloat16(v0), h1 = __float2bfloat16(v1);
                    g_Vthi[a]      = h0;
                    g_Vthi[a + SS] = h1;
                    g_Vtlo[a]      = __float2bfloat16(v0 - __bfloat162float(h0));
                    g_Vtlo[a + SS] = __float2bfloat16(v1 - __bfloat162float(h1));
                } else {
                    *(float2*)(outp + (size_t)row * DD + col0) = make_float2(v0, v1);
                }
            }
        }
    }
#undef ISSUE
}

// ---------------------------------------------------------------------------
// Flash attention on mma.sync bf16 (3x-split both matmuls).
// grid (S/64, B*H), block 256 (8 warps: 2m x 4n).
// ---------------------------------------------------------------------------
#define QROWB 144                 // 128B row + 16 pad (conflict-free ldmatrix)
#define PROWB 272                 // 256B row + 16 pad
#define SQ_HI 0
#define SQ_LO 9216
#define SK_HI 18432
#define SK_LO 36864
#define SP_HI 18432               // P overlays K region (dead during PV)
#define SP_LO 35840
#define SV_HI 55296
#define SV_LO 72704
#define SRED  90112
#define SRED2 91136
#define SMEM_ATTN 92160

__global__ __launch_bounds__(256, 2)
void attn_kernel(const int* __restrict__ mask) {
    extern __shared__ char smc[];
    const uint32_t sb = (uint32_t)__cvta_generic_to_shared(smc);
    float* redf  = (float*)(smc + SRED);
    float* redf2 = (float*)(smc + SRED2);

    const int q0 = blockIdx.x * 64;
    const int bh = blockIdx.y;
    const int b  = bh / HH;
    const int h  = bh % HH;

    const int tid  = threadIdx.x;
    const int wid  = tid >> 5;
    const int lane = tid & 31;
    const int wm2  = wid >> 2;          // 0/1: q 32-group
    const int wn2  = wid & 3;           // 0..3
    const int g    = lane >> 2;
    const int t4   = lane & 3;
    const int QR   = wm2 * 32;
    const int KNB  = wn2 * 32;          // key base within ktile (scores)

    const uint32_t lq = lane >> 3, lr = lane & 7;
    const uint32_t lmoQ = (lr + (lq & 1) * 8) * QROWB + (lq >> 1) * 16;
    const uint32_t lmoP = (lr + (lq & 1) * 8) * PROWB + (lq >> 1) * 16;

    // Q tile load (group)
    {
        int row = tid >> 2;
        int s0  = (tid & 3) * 2;
        size_t   ga = ((size_t)bh * SS + q0 + row) * DKK;
        uint32_t so = sb + (uint32_t)(row * QROWB);
#pragma unroll
        for (int j = 0; j < 2; j++) {
            cpasync16(so + SQ_HI + (s0 + j) * 16, g_Qhi + ga + (s0 + j) * 8);
            cpasync16(so + SQ_LO + (s0 + j) * 16, g_Qlo + ga + (s0 + j) * 8);
        }
        cpcommit();
    }

    float acc_o[2][2][4] = {};          // [mi][ni2][c]
    float li[2][2] = {};
    float mx[2][2] = {{-1e30f, -1e30f}, {-1e30f, -1e30f}};

    for (int kt = 0; kt < 4; kt++) {
        __syncthreads();                // K/P and V regions free

        // K tile cp.async (128 keys x 64 d)
        {
            int row = tid >> 1;
            int sN  = (tid & 1) * 4;
            size_t   ga = ((size_t)bh * SS + kt * 128 + row) * DKK;
            uint32_t so = sb + (uint32_t)(row * QROWB);
#pragma unroll
            for (int j = 0; j < 4; j++) {
                cpasync16(so + SK_HI + (sN + j) * 16, g_Khi + ga + (sN + j) * 8);
                cpasync16(so + SK_LO + (sN + j) * 16, g_Klo + ga + (sN + j) * 8);
            }
            cpcommit();
        }
        // V^T tile cp.async (64 d x 128 keys)
        {
            int row = tid >> 2;
            int sN  = (tid & 3) * 4;
            size_t   ga = ((size_t)bh * DKK + row) * SS + kt * 128;
            uint32_t so = sb + (uint32_t)(row * PROWB);
#pragma unroll
            for (int j = 0; j < 4; j++) {
                cpasync16(so + SV_HI + (sN + j) * 16, g_Vthi + ga + (sN + j) * 8);
                cpasync16(so + SV_LO + (sN + j) * 16, g_Vtlo + ga + (sN + j) * 8);
            }
            cpcommit();
        }
        cpwait<1>();                    // Q + K complete (V may be in flight)
        __syncthreads();

        // ---- scores: 32q x 32k per warp ----
        float s4[2][4][4] = {};
#pragma unroll
        for (int ks = 0; ks < 4; ks++) {
            uint32_t aH[2][4], aL[2][4], bH[2][4], bL[2][4];
#pragma unroll
            for (int mi = 0; mi < 2; mi++) {
                uint32_t ad = sb + (uint32_t)((QR + mi * 16) * QROWB) + ks * 32 + lmoQ;
                LDMX4(aH[mi], ad + SQ_HI);
                LDMX4(aL[mi], ad + SQ_LO);
            }
#pragma unroll
            for (int nn = 0; nn < 2; nn++) {
                uint32_t bd = sb + (uint32_t)((KNB + nn * 16) * QROWB) + ks * 32 + lmoQ;
                LDMX4(bH[nn], bd + SK_HI);
                LDMX4(bL[nn], bd + SK_LO);
            }
#pragma unroll
            for (int mi = 0; mi < 2; mi++)
#pragma unroll
                for (int ni = 0; ni < 4; ni++) {
                    const int nn = ni >> 1, sel = ni & 1;
                    mma16(s4[mi][ni], aH[mi], bH[nn][sel], bH[nn][sel + 2]);
                    mma16(s4[mi][ni], aL[mi], bH[nn][sel], bH[nn][sel + 2]);
                    mma16(s4[mi][ni], aH[mi], bL[nn][sel], bL[nn][sel + 2]);
                }
        }

        // ---- mask + scale ----
        int2 mk[4];
#pragma unroll
        for (int ni = 0; ni < 4; ni++)
            mk[ni] = *(const int2*)(mask + b * SS + kt * 128 + KNB + ni * 8 + 2 * t4);
#pragma unroll
        for (int mi = 0; mi < 2; mi++)
#pragma unroll
            for (int ni = 0; ni < 4; ni++) {
                s4[mi][ni][0] = mk[ni].x ? s4[mi][ni][0] * 0.125f : -1e30f;
                s4[mi][ni][1] = mk[ni].y ? s4[mi][ni][1] * 0.125f : -1e30f;
                s4[mi][ni][2] = mk[ni].x ? s4[mi][ni][2] * 0.125f : -1e30f;
                s4[mi][ni][3] = mk[ni].y ? s4[mi][ni][3] * 0.125f : -1e30f;
            }

        // ---- local row max -> smem ----
#pragma unroll
        for (int mi = 0; mi < 2; mi++)
#pragma unroll
            for (int half = 0; half < 2; half++) {
                float m = -1e30f;
#pragma unroll
                for (int ni = 0; ni < 4; ni++)
                    m = fmaxf(m, fmaxf(s4[mi][ni][half * 2], s4[mi][ni][half * 2 + 1]));
                m = fmaxf(m, __shfl_xor_sync(0xffffffffu, m, 1));
                m = fmaxf(m, __shfl_xor_sync(0xffffffffu, m, 2));
                if (t4 == 0)
                    redf[(wm2 * 4 + wn2) * 32 + mi * 16 + g + 8 * half] = m;
            }
        __syncthreads();

        // ---- global max, rescale O, p=exp, write P, local sums ----
        float mnew[2][2], lsum[2][2] = {};
#pragma unroll
        for (int mi = 0; mi < 2; mi++)
#pragma unroll
            for (int half = 0; half < 2; half++) {
                const int rl = mi * 16 + g + 8 * half;
                float gm = fmaxf(fmaxf(redf[(wm2 * 4 + 0) * 32 + rl],
                                       redf[(wm2 * 4 + 1) * 32 + rl]),
                                 fmaxf(redf[(wm2 * 4 + 2) * 32 + rl],
                                       redf[(wm2 * 4 + 3) * 32 + rl]));
                float mn = fmaxf(mx[mi][half], gm);
                float al = __expf(mx[mi][half] - mn);
                mx[mi][half] = mn;
                mnew[mi][half] = mn;
                li[mi][half] *= al;
#pragma unroll
                for (int ni2 = 0; ni2 < 2; ni2++) {
                    acc_o[mi][ni2][half * 2]     *= al;
                    acc_o[mi][ni2][half * 2 + 1] *= al;
                }
            }
#pragma unroll
        for (int mi = 0; mi < 2; mi++)
#pragma unroll
            for (int ni = 0; ni < 4; ni++) {
                float p0 = __expf(s4[mi][ni][0] - mnew[mi][0]);
                float p1 = __expf(s4[mi][ni][1] - mnew[mi][0]);
                float p2 = __expf(s4[mi][ni][2] - mnew[mi][1]);
                float p3 = __expf(s4[mi][ni][3] - mnew[mi][1]);
                lsum[mi][0] += p0 + p1;
                lsum[mi][1] += p2 + p3;
                uint32_t lo0, lo1;
                uint32_t hi0 = split_hi(p0, p1, lo0);
                uint32_t hi1 = split_hi(p2, p3, lo1);
                const uint32_t cb = (uint32_t)((KNB + ni * 8 + 2 * t4) * 2);
                const uint32_t r0 = (uint32_t)((QR + mi * 16 + g) * PROWB) + cb;
                *(uint32_t*)(smc + SP_HI + r0)               = hi0;
                *(uint32_t*)(smc + SP_LO + r0)               = lo0;
                *(uint32_t*)(smc + SP_HI + r0 + 8 * PROWB)   = hi1;
                *(uint32_t*)(smc + SP_LO + r0 + 8 * PROWB)   = lo1;
            }
#pragma unroll
        for (int mi = 0; mi < 2; mi++)
#pragma unroll
            for (int half = 0; half < 2; half++) {
                float sgl = lsum[mi][half];
                sgl += __shfl_xor_sync(0xffffffffu, sgl, 1);
                sgl += __shfl_xor_sync(0xffffffffu, sgl, 2);
                if (t4 == 0)
                    redf2[(wm2 * 4 + wn2) * 32 + mi * 16 + g + 8 * half] = sgl;
            }
        cpwait<0>();                    // V complete (visibility via next barrier)
        __syncthreads();
#pragma unroll
        for (int mi = 0; mi < 2; mi++)
#pragma unroll
            for (int half = 0; half < 2; half++) {
                const int rl = mi * 16 + g + 8 * half;
                li[mi][half] += redf2[(wm2 * 4 + 0) * 32 + rl]
                              + redf2[(wm2 * 4 + 1) * 32 + rl]
                              + redf2[(wm2 * 4 + 2) * 32 + rl]
                              + redf2[(wm2 * 4 + 3) * 32 + rl];
            }

        // ---- PV: 32q x 16v per warp, k = 128 keys ----
#pragma unroll
        for (int ks = 0; ks < 8; ks++) {
            uint32_t pH[2][4], pL[2][4], vH[4], vL[4];
#pragma unroll
            for (int mi = 0; mi < 2; mi++) {
                uint32_t pd = sb + (uint32_t)((QR + mi * 16) * PROWB) + ks * 32 + lmoP;
                LDMX4(pH[mi], pd + SP_HI);
                LDMX4(pL[mi], pd + SP_LO);
            }
            uint32_t vd = sb + (uint32_t)((wn2 * 16) * PROWB) + ks * 32 + lmoP;
            LDMX4(vH, vd + SV_HI);
            LDMX4(vL, vd + SV_LO);
#pragma unroll
            for (int mi = 0; mi < 2; mi++)
#pragma unroll
                for (int ni2 = 0; ni2 < 2; ni2++) {
                    mma16(acc_o[mi][ni2], pH[mi], vH[ni2], vH[ni2 + 2]);
                    mma16(acc_o[mi][ni2], pL[mi], vH[ni2], vH[ni2 + 2]);
                    mma16(acc_o[mi][ni2], pH[mi], vL[ni2], vL[ni2 + 2]);
                }
        }
    }

    // ---- finalize: heads (concat layout) as bf16 hi/lo ----
#pragma unroll
    for (int mi = 0; mi < 2; mi++)
#pragma unroll
        for (int half = 0; half < 2; half++) {
            const float inv = 1.0f / li[mi][half];
            const int tok = q0 + QR + mi * 16 + g + 8 * half;
#pragma unroll
            for (int ni2 = 0; ni2 < 2; ni2++) {
                const int col = wn2 * 16 + ni2 * 8 + 2 * t4;
                float v0 = acc_o[mi][ni2][half * 2]     * inv;
                float v1 = acc_o[mi][ni2][half * 2 + 1] * inv;
                uint32_t lo;
                uint32_t hi = split_hi(v0, v1, lo);
                size_t a = ((size_t)b * SS + tok) * DD + h * DKK + col;
                *(uint32_t*)(g_hhi + a) = hi;
                *(uint32_t*)(g_hlo + a) = lo;
            }
        }
}

// ---------------------------------------------------------------------------
extern "C" void kernel_launch(void* const* d_in, const int* in_sizes, int n_in,
                              void* d_out, int out_size) {
    const float* x    = (const float*)d_in[0];
    const int*   mask = (const int*)  d_in[1];
    const float* Wq   = (const float*)d_in[2];
    const float* Wk   = (const float*)d_in[3];
    const float* Wv   = (const float*)d_in[4];
    const float* Wo   = (const float*)d_in[5];
    const float* bias = (const float*)d_in[6];
    float* out = (float*)d_out;

    // 0) weight transpose + bf16 hi/lo split; x bf16 hi/lo split
    prepw_kernel<<<dim3(8, 8, 4), 256>>>(Wq, Wk, Wv, Wo);
    prepx_kernel<<<MM * DD / 4 / 256, 256>>>(x);

    // 1) QKV projections (3xBF16 mma.sync)
    cudaFuncSetAttribute(mma_gemm_kernel,
                         cudaFuncAttributeMaxDynamicSharedMemorySize, SMEM_GEMM);
    mma_gemm_kernel<<<dim3(MM / 128, 4, 3), 256, SMEM_GEMM>>>(0, bias, out);

    // 2) fused masked-softmax attention (flash, bf16 mma.sync)
    cudaFuncSetAttribute(attn_kernel,
                         cudaFuncAttributeMaxDynamicSharedMemorySize, SMEM_ATTN);
    attn_kernel<<<dim3(SS / 64, BB * HH), 256, SMEM_ATTN>>>(mask);

    // 3) output projection (3xBF16 mma.sync)
    mma_gemm_kernel<<<dim3(MM / 128, 4, 1), 256, SMEM_GEMM>>>(3, bias, out);
}

// round 8
// speedup vs baseline: 1.9456x; 1.0033x over previous
#include <cuda_runtime.h>
#include <cuda_bf16.h>
#include <cstdint>

#define BB  32
#define SS  512
#define DD  512
#define HH  8
#define DKK 64
#define MM  (BB*SS)   // 16384

typedef __nv_bfloat16 bf16;

// Scratch (device globals; no runtime allocation allowed)
__device__ bf16 g_Qhi[(size_t)BB*HH*SS*DKK];  // [bh][s][dk]
__device__ bf16 g_Qlo[(size_t)BB*HH*SS*DKK];
__device__ bf16 g_Khi[(size_t)BB*HH*SS*DKK];  // [bh][s][dk]
__device__ bf16 g_Klo[(size_t)BB*HH*SS*DKK];
__device__ bf16 g_Vthi[(size_t)BB*HH*DKK*SS]; // [bh][dk][s] (transposed)
__device__ bf16 g_Vtlo[(size_t)BB*HH*DKK*SS];
__device__ bf16 g_xhi[(size_t)MM*DD];         // x split hi
__device__ bf16 g_xlo[(size_t)MM*DD];
__device__ bf16 g_hhi[(size_t)MM*DD];         // heads split hi (concat layout)
__device__ bf16 g_hlo[(size_t)MM*DD];
__device__ bf16 g_Whi[(size_t)4*DD*DD];       // [mat][n][k]
__device__ bf16 g_Wlo[(size_t)4*DD*DD];

// ===================== PTX helpers =====================
__device__ __forceinline__ void cpasync16(uint32_t s, const void* g) {
    asm volatile("cp.async.cg.shared.global [%0], [%1], 16;" :: "r"(s), "l"(g));
}
__device__ __forceinline__ void cpcommit() {
    asm volatile("cp.async.commit_group;" ::: "memory");
}
template <int N> __device__ __forceinline__ void cpwait() {
    asm volatile("cp.async.wait_group %0;" :: "n"(N) : "memory");
}
#define LDMX4(r, a)                                                            \
    asm volatile("ldmatrix.sync.aligned.m8n8.x4.shared.b16 {%0,%1,%2,%3}, [%4];" \
        : "=r"((r)[0]), "=r"((r)[1]), "=r"((r)[2]), "=r"((r)[3]) : "r"(a))

__device__ __forceinline__ void mma16(float* c, const uint32_t* a,
                                      uint32_t b0, uint32_t b1) {
    asm volatile(
        "mma.sync.aligned.m16n8k16.row.col.f32.bf16.bf16.f32 "
        "{%0,%1,%2,%3},{%4,%5,%6,%7},{%8,%9},{%0,%1,%2,%3};"
        : "+f"(c[0]), "+f"(c[1]), "+f"(c[2]), "+f"(c[3])
        : "r"(a[0]), "r"(a[1]), "r"(a[2]), "r"(a[3]), "r"(b0), "r"(b1));
}

__device__ __forceinline__ uint32_t pack2(bf16 a, bf16 b) {
    return (uint32_t)__bfloat16_as_ushort(a) |
           ((uint32_t)__bfloat16_as_ushort(b) << 16);
}
__device__ __forceinline__ uint32_t split_hi(float v0, float v1, uint32_t& lo) {
    bf16 h0 = __float2bfloat16(v0), h1 = __float2bfloat16(v1);
    lo = pack2(__float2bfloat16(v0 - __bfloat162float(h0)),
               __float2bfloat16(v1 - __bfloat162float(h1)));
    return pack2(h0, h1);
}

// ---------------------------------------------------------------------------
// Prep W: transpose weights into [mat][n][k], split to bf16 hi/lo.
// ---------------------------------------------------------------------------
__global__ void prepw_kernel(const float* __restrict__ Wq,
                             const float* __restrict__ Wk,
                             const float* __restrict__ Wv,
                             const float* __restrict__ Wo) {
    __shared__ float t[64][65];
    const int z  = blockIdx.z;
    const int y  = blockIdx.y;
    const int xt = blockIdx.x;
    const float* W = (z == 0) ? Wq : (z == 1) ? Wk : (z == 2) ? Wv : Wo;
    const int tid = threadIdx.x;

#pragma unroll
    for (int i = 0; i < 4; i++) {
        int idx = tid + i * 256;
        int r   = idx >> 4;
        int c4  = (idx & 15) * 4;
        const float* p = (z < 3)
            ? W + (size_t)y * DD * DKK + (size_t)(xt * 64 + r) * DKK + c4
            : W + (size_t)(xt * 64 + r) * DD + y * 64 + c4;
        float4 v = *(const float4*)p;
        t[c4 + 0][r] = v.x; t[c4 + 1][r] = v.y;
        t[c4 + 2][r] = v.z; t[c4 + 3][r] = v.w;
    }
    __syncthreads();

    bf16* oh = g_Whi + (size_t)z * DD * DD;
    bf16* ol = g_Wlo + (size_t)z * DD * DD;
#pragma unroll
    for (int i = 0; i < 4; i++) {
        int idx = tid + i * 256;
        int c   = idx >> 4;
        int r4  = (idx & 15) * 4;
        size_t o = (size_t)(y * 64 + c) * DD + xt * 64 + r4;
        uint2 uh, ul;
        uh.x = split_hi(t[c][r4],     t[c][r4 + 1], ul.x);
        uh.y = split_hi(t[c][r4 + 2], t[c][r4 + 3], ul.y);
        *(uint2*)(oh + o) = uh;
        *(uint2*)(ol + o) = ul;
    }
}

// ---------------------------------------------------------------------------
// Prep X: split x into bf16 hi/lo, row-major.
// ---------------------------------------------------------------------------
__global__ void prepx_kernel(const float* __restrict__ x) {
    const size_t i4 = (size_t)blockIdx.x * 256 + threadIdx.x;
    float4 v = ((const float4*)x)[i4];
    uint2 uh, ul;
    uh.x = split_hi(v.x, v.y, ul.x);
    uh.y = split_hi(v.z, v.w, ul.y);
    *(uint2*)(g_xhi + i4 * 4) = uh;
    *(uint2*)(g_xlo + i4 * 4) = ul;
}

// ---------------------------------------------------------------------------
// bf16 3x-split GEMM (mma.sync + ldmatrix + cp.async). 128x128 tiles.
// 3-term products issued as 3 SEPARATED passes (breaks acc RAW chains).
// mat 0 -> Qhi/lo natural, 1 -> Khi/lo natural, 2 -> Vt transposed,
// 3 -> out fp32 row-major.
// ---------------------------------------------------------------------------
#define ROWB 80
#define BUFB (128 * ROWB)
#define STGB (4 * BUFB)
#define NSTG 3
#define SMEM_GEMM (NSTG * STGB)

__global__ __launch_bounds__(256, 1)
void mma_gemm_kernel(int matBase, const float* __restrict__ bias,
                     float* __restrict__ outp) {
    extern __shared__ char smc[];
    const uint32_t sb0 = (uint32_t)__cvta_generic_to_shared(smc);

    const int mat = matBase + blockIdx.z;
    const int m0  = blockIdx.x * 128;
    const int n0  = blockIdx.y * 128;
    const bf16* Ahi = (mat >= 3) ? g_hhi : g_xhi;
    const bf16* Alo = (mat >= 3) ? g_hlo : g_xlo;
    const bf16* Bhi = g_Whi + (size_t)mat * DD * DD;
    const bf16* Blo = g_Wlo + (size_t)mat * DD * DD;

    const int tid  = threadIdx.x;
    const int wid  = tid >> 5;
    const int lane = tid & 31;
    const int wm   = (wid >> 2) * 64;
    const int wn   = (wid & 3) * 32;
    const int g    = lane >> 2;
    const int t4   = lane & 3;

    const uint32_t lq  = lane >> 3;
    const uint32_t lr  = lane & 7;
    const uint32_t lmo = (lr + (lq & 1) * 8) * ROWB + (lq >> 1) * 16;

    float acc[4][4][4] = {};

#define ISSUE(ch) do {                                                         \
        const int d0 = (ch) * 32;                                              \
        const uint32_t st = sb0 + ((ch) % NSTG) * STGB;                        \
        _Pragma("unroll")                                                      \
        for (int t = 0; t < 2; t++) {                                          \
            int idx = tid + 256 * t;                                           \
            int row = idx >> 2;                                                \
            int seg = idx & 3;                                                 \
            uint32_t so = (uint32_t)(row * ROWB + seg * 16);                   \
            size_t  ga  = (size_t)(m0 + row) * DD + d0 + seg * 8;              \
            size_t  gb  = (size_t)(n0 + row) * DD + d0 + seg * 8;              \
            cpasync16(st + so,            Ahi + ga);                           \
            cpasync16(st + BUFB + so,     Alo + ga);                           \
            cpasync16(st + 2 * BUFB + so, Bhi + gb);                           \
            cpasync16(st + 3 * BUFB + so, Blo + gb);                           \
        }                                                                      \
        cpcommit();                                                            \
    } while (0)

    ISSUE(0);
    ISSUE(1);

    for (int ch = 0; ch < 16; ch++) {
        if (ch >= 14) cpwait<0>(); else cpwait<1>();
        __syncthreads();
        if (ch + 2 < 16) ISSUE(ch + 2);

        const uint32_t st = sb0 + (ch % NSTG) * STGB;
#pragma unroll
        for (int kk = 0; kk < 2; kk++) {
            const uint32_t ko = kk * 32;
            uint32_t aH[4][4], aL[4][4], bH[2][4], bL[2][4];
#pragma unroll
            for (int mi = 0; mi < 4; mi++) {
                uint32_t ad = st + (uint32_t)((wm + mi * 16) * ROWB) + ko + lmo;
                LDMX4(aH[mi], ad);
                LDMX4(aL[mi], ad + BUFB);
            }
#pragma unroll
            for (int nn = 0; nn < 2; nn++) {
                uint32_t bd = st + 2 * BUFB + (uint32_t)((wn + nn * 16) * ROWB) + ko + lmo;
                LDMX4(bH[nn], bd);
                LDMX4(bL[nn], bd + BUFB);
            }
            // pass 1: hi*hi (16 independent accs)
#pragma unroll
            for (int mi = 0; mi < 4; mi++)
#pragma unroll
                for (int ni = 0; ni < 4; ni++) {
                    const int nn = ni >> 1, sel = ni & 1;
                    mma16(acc[mi][ni], aH[mi], bH[nn][sel], bH[nn][sel + 2]);
                }
            // pass 2: lo*hi
#pragma unroll
            for (int mi = 0; mi < 4; mi++)
#pragma unroll
                for (int ni = 0; ni < 4; ni++) {
                    const int nn = ni >> 1, sel = ni & 1;
                    mma16(acc[mi][ni], aL[mi], bH[nn][sel], bH[nn][sel + 2]);
                }
            // pass 3: hi*lo
#pragma unroll
            for (int mi = 0; mi < 4; mi++)
#pragma unroll
                for (int ni = 0; ni < 4; ni++) {
                    const int nn = ni >> 1, sel = ni & 1;
                    mma16(acc[mi][ni], aH[mi], bL[nn][sel], bL[nn][sel + 2]);
                }
        }
        __syncthreads();
    }

    // epilogue
    const float bv = bias[0];
#pragma unroll
    for (int mi = 0; mi < 4; mi++) {
#pragma unroll
        for (int h2 = 0; h2 < 2; h2++) {
            const int row = m0 + wm + mi * 16 + g + 8 * h2;
            const int b   = row >> 9;
            const int s   = row & 511;
#pragma unroll
            for (int ni = 0; ni < 4; ni++) {
                const int col0 = n0 + wn + ni * 8 + 2 * t4;
                const float v0 = acc[mi][ni][2 * h2]     + bv;
                const float v1 = acc[mi][ni][2 * h2 + 1] + bv;
                if (mat < 2) {
                    bf16* dhi = (mat == 0) ? g_Qhi : g_Khi;
                    bf16* dlo = (mat == 0) ? g_Qlo : g_Klo;
                    size_t a = ((size_t)(b * HH + (col0 >> 6)) * SS + s) * DKK
                               + (col0 & 63);
                    uint32_t lo;
                    uint32_t hi = split_hi(v0, v1, lo);
                    *(uint32_t*)(dhi + a) = hi;
                    *(uint32_t*)(dlo + a) = lo;
                } else if (mat == 2) {
                    size_t a = ((size_t)(b * HH + (col0 >> 6)) * DKK + (col0 & 63)) * SS + s;
                    bf16 h0 = __float2bfloat16(v0), h1 = __float2bfloat16(v1);
                    g_Vthi[a]      = h0;
                    g_Vthi[a + SS] = h1;
                    g_Vtlo[a]      = __float2bfloat16(v0 - __bfloat162float(h0));
                    g_Vtlo[a + SS] = __float2bfloat16(v1 - __bfloat162float(h1));
                } else {
                    *(float2*)(outp + (size_t)row * DD + col0) = make_float2(v0, v1);
                }
            }
        }
    }
#undef ISSUE
}

// ---------------------------------------------------------------------------
// Flash attention on mma.sync bf16 (3x-split both matmuls, pass-separated).
// grid (S/64, B*H), block 256 (8 warps: 2m x 4n).
// ---------------------------------------------------------------------------
#define QROWB 144                 // 128B row + 16 pad (conflict-free ldmatrix)
#define PROWB 272                 // 256B row + 16 pad
#define SQ_HI 0
#define SQ_LO 9216
#define SK_HI 18432
#define SK_LO 36864
#define SP_HI 18432               // P overlays K region (dead during PV)
#define SP_LO 35840
#define SV_HI 55296
#define SV_LO 72704
#define SRED  90112
#define SRED2 91136
#define SMEM_ATTN 92160

__global__ __launch_bounds__(256, 2)
void attn_kernel(const int* __restrict__ mask) {
    extern __shared__ char smc[];
    const uint32_t sb = (uint32_t)__cvta_generic_to_shared(smc);
    float* redf  = (float*)(smc + SRED);
    float* redf2 = (float*)(smc + SRED2);

    const int q0 = blockIdx.x * 64;
    const int bh = blockIdx.y;
    const int b  = bh / HH;
    const int h  = bh % HH;

    const int tid  = threadIdx.x;
    const int wid  = tid >> 5;
    const int lane = tid & 31;
    const int wm2  = wid >> 2;          // 0/1: q 32-group
    const int wn2  = wid & 3;           // 0..3
    const int g    = lane >> 2;
    const int t4   = lane & 3;
    const int QR   = wm2 * 32;
    const int KNB  = wn2 * 32;          // key base within ktile (scores)

    const uint32_t lq = lane >> 3, lr = lane & 7;
    const uint32_t lmoQ = (lr + (lq & 1) * 8) * QROWB + (lq >> 1) * 16;
    const uint32_t lmoP = (lr + (lq & 1) * 8) * PROWB + (lq >> 1) * 16;

    // Q tile load (group)
    {
        int row = tid >> 2;
        int s0  = (tid & 3) * 2;
        size_t   ga = ((size_t)bh * SS + q0 + row) * DKK;
        uint32_t so = sb + (uint32_t)(row * QROWB);
#pragma unroll
        for (int j = 0; j < 2; j++) {
            cpasync16(so + SQ_HI + (s0 + j) * 16, g_Qhi + ga + (s0 + j) * 8);
            cpasync16(so + SQ_LO + (s0 + j) * 16, g_Qlo + ga + (s0 + j) * 8);
        }
        cpcommit();
    }

    float acc_o[2][2][4] = {};          // [mi][ni2][c]
    float li[2][2] = {};
    float mx[2][2] = {{-1e30f, -1e30f}, {-1e30f, -1e30f}};

    for (int kt = 0; kt < 4; kt++) {
        __syncthreads();                // K/P and V regions free

        // K tile cp.async (128 keys x 64 d)
        {
            int row = tid >> 1;
            int sN  = (tid & 1) * 4;
            size_t   ga = ((size_t)bh * SS + kt * 128 + row) * DKK;
            uint32_t so = sb + (uint32_t)(row * QROWB);
#pragma unroll
            for (int j = 0; j < 4; j++) {
                cpasync16(so + SK_HI + (sN + j) * 16, g_Khi + ga + (sN + j) * 8);
                cpasync16(so + SK_LO + (sN + j) * 16, g_Klo + ga + (sN + j) * 8);
            }
            cpcommit();
        }
        // V^T tile cp.async (64 d x 128 keys)
        {
            int row = tid >> 2;
            int sN  = (tid & 3) * 4;
            size_t   ga = ((size_t)bh * DKK + row) * SS + kt * 128;
            uint32_t so = sb + (uint32_t)(row * PROWB);
#pragma unroll
            for (int j = 0; j < 4; j++) {
                cpasync16(so + SV_HI + (sN + j) * 16, g_Vthi + ga + (sN + j) * 8);
                cpasync16(so + SV_LO + (sN + j) * 16, g_Vtlo + ga + (sN + j) * 8);
            }
            cpcommit();
        }
        cpwait<1>();                    // Q + K complete (V may be in flight)
        __syncthreads();

        // ---- scores: 32q x 32k per warp (3 separated passes) ----
        float s4[2][4][4] = {};
#pragma unroll
        for (int ks = 0; ks < 4; ks++) {
            uint32_t aH[2][4], aL[2][4], bH[2][4], bL[2][4];
#pragma unroll
            for (int mi = 0; mi < 2; mi++) {
                uint32_t ad = sb + (uint32_t)((QR + mi * 16) * QROWB) + ks * 32 + lmoQ;
                LDMX4(aH[mi], ad + SQ_HI);
                LDMX4(aL[mi], ad + SQ_LO);
            }
#pragma unroll
            for (int nn = 0; nn < 2; nn++) {
                uint32_t bd = sb + (uint32_t)((KNB + nn * 16) * QROWB) + ks * 32 + lmoQ;
                LDMX4(bH[nn], bd + SK_HI);
                LDMX4(bL[nn], bd + SK_LO);
            }
#pragma unroll
            for (int mi = 0; mi < 2; mi++)
#pragma unroll
                for (int ni = 0; ni < 4; ni++) {
                    const int nn = ni >> 1, sel = ni & 1;
                    mma16(s4[mi][ni], aH[mi], bH[nn][sel], bH[nn][sel + 2]);
                }
#pragma unroll
            for (int mi = 0; mi < 2; mi++)
#pragma unroll
                for (int ni = 0; ni < 4; ni++) {
                    const int nn = ni >> 1, sel = ni & 1;
                    mma16(s4[mi][ni], aL[mi], bH[nn][sel], bH[nn][sel + 2]);
                }
#pragma unroll
            for (int mi = 0; mi < 2; mi++)
#pragma unroll
                for (int ni = 0; ni < 4; ni++) {
                    const int nn = ni >> 1, sel = ni & 1;
                    mma16(s4[mi][ni], aH[mi], bL[nn][sel], bL[nn][sel + 2]);
                }
        }

        // ---- mask + scale ----
        int2 mk[4];
#pragma unroll
        for (int ni = 0; ni < 4; ni++)
            mk[ni] = *(const int2*)(mask + b * SS + kt * 128 + KNB + ni * 8 + 2 * t4);
#pragma unroll
        for (int mi = 0; mi < 2; mi++)
#pragma unroll
            for (int ni = 0; ni < 4; ni++) {
                s4[mi][ni][0] = mk[ni].x ? s4[mi][ni][0] * 0.125f : -1e30f;
                s4[mi][ni][1] = mk[ni].y ? s4[mi][ni][1] * 0.125f : -1e30f;
                s4[mi][ni][2] = mk[ni].x ? s4[mi][ni][2] * 0.125f : -1e30f;
                s4[mi][ni][3] = mk[ni].y ? s4[mi][ni][3] * 0.125f : -1e30f;
            }

        // ---- local row max -> smem ----
#pragma unroll
        for (int mi = 0; mi < 2; mi++)
#pragma unroll
            for (int half = 0; half < 2; half++) {
                float m = -1e30f;
#pragma unroll
                for (int ni = 0; ni < 4; ni++)
                    m = fmaxf(m, fmaxf(s4[mi][ni][half * 2], s4[mi][ni][half * 2 + 1]));
                m = fmaxf(m, __shfl_xor_sync(0xffffffffu, m, 1));
                m = fmaxf(m, __shfl_xor_sync(0xffffffffu, m, 2));
                if (t4 == 0)
                    redf[(wm2 * 4 + wn2) * 32 + mi * 16 + g + 8 * half] = m;
            }
        __syncthreads();

        // ---- global max, rescale O, p=exp, write P, local sums ----
        float mnew[2][2], lsum[2][2] = {};
#pragma unroll
        for (int mi = 0; mi < 2; mi++)
#pragma unroll
            for (int half = 0; half < 2; half++) {
                const int rl = mi * 16 + g + 8 * half;
                float gm = fmaxf(fmaxf(redf[(wm2 * 4 + 0) * 32 + rl],
                                       redf[(wm2 * 4 + 1) * 32 + rl]),
                                 fmaxf(redf[(wm2 * 4 + 2) * 32 + rl],
                                       redf[(wm2 * 4 + 3) * 32 + rl]));
                float mn = fmaxf(mx[mi][half], gm);
                float al = __expf(mx[mi][half] - mn);
                mx[mi][half] = mn;
                mnew[mi][half] = mn;
                li[mi][half] *= al;
#pragma unroll
                for (int ni2 = 0; ni2 < 2; ni2++) {
                    acc_o[mi][ni2][half * 2]     *= al;
                    acc_o[mi][ni2][half * 2 + 1] *= al;
                }
            }
#pragma unroll
        for (int mi = 0; mi < 2; mi++)
#pragma unroll
            for (int ni = 0; ni < 4; ni++) {
                float p0 = __expf(s4[mi][ni][0] - mnew[mi][0]);
                float p1 = __expf(s4[mi][ni][1] - mnew[mi][0]);
                float p2 = __expf(s4[mi][ni][2] - mnew[mi][1]);
                float p3 = __expf(s4[mi][ni][3] - mnew[mi][1]);
                lsum[mi][0] += p0 + p1;
                lsum[mi][1] += p2 + p3;
                uint32_t lo0, lo1;
                uint32_t hi0 = split_hi(p0, p1, lo0);
                uint32_t hi1 = split_hi(p2, p3, lo1);
                const uint32_t cb = (uint32_t)((KNB + ni * 8 + 2 * t4) * 2);
                const uint32_t r0 = (uint32_t)((QR + mi * 16 + g) * PROWB) + cb;
                *(uint32_t*)(smc + SP_HI + r0)               = hi0;
                *(uint32_t*)(smc + SP_LO + r0)               = lo0;
                *(uint32_t*)(smc + SP_HI + r0 + 8 * PROWB)   = hi1;
                *(uint32_t*)(smc + SP_LO + r0 + 8 * PROWB)   = lo1;
            }
#pragma unroll
        for (int mi = 0; mi < 2; mi++)
#pragma unroll
            for (int half = 0; half < 2; half++) {
                float sgl = lsum[mi][half];
                sgl += __shfl_xor_sync(0xffffffffu, sgl, 1);
                sgl += __shfl_xor_sync(0xffffffffu, sgl, 2);
                if (t4 == 0)
                    redf2[(wm2 * 4 + wn2) * 32 + mi * 16 + g + 8 * half] = sgl;
            }
        cpwait<0>();                    // V complete (visibility via next barrier)
        __syncthreads();
#pragma unroll
        for (int mi = 0; mi < 2; mi++)
#pragma unroll
            for (int half = 0; half < 2; half++) {
                const int rl = mi * 16 + g + 8 * half;
                li[mi][half] += redf2[(wm2 * 4 + 0) * 32 + rl]
                              + redf2[(wm2 * 4 + 1) * 32 + rl]
                              + redf2[(wm2 * 4 + 2) * 32 + rl]
                              + redf2[(wm2 * 4 + 3) * 32 + rl];
            }

        // ---- PV: 32q x 16v per warp, k = 128 keys (3 separated passes) ----
#pragma unroll
        for (int ks = 0; ks < 8; ks++) {
            uint32_t pH[2][4], pL[2][4], vH[4], vL[4];
#pragma unroll
            for (int mi = 0; mi < 2; mi++) {
                uint32_t pd = sb + (uint32_t)((QR + mi * 16) * PROWB) + ks * 32 + lmoP;
                LDMX4(pH[mi], pd + SP_HI);
                LDMX4(pL[mi], pd + SP_LO);
            }
            uint32_t vd = sb + (uint32_t)((wn2 * 16) * PROWB) + ks * 32 + lmoP;
            LDMX4(vH, vd + SV_HI);
            LDMX4(vL, vd + SV_LO);
#pragma unroll
            for (int mi = 0; mi < 2; mi++)
#pragma unroll
                for (int ni2 = 0; ni2 < 2; ni2++)
                    mma16(acc_o[mi][ni2], pH[mi], vH[ni2], vH[ni2 + 2]);
#pragma unroll
            for (int mi = 0; mi < 2; mi++)
#pragma unroll
                for (int ni2 = 0; ni2 < 2; ni2++)
                    mma16(acc_o[mi][ni2], pL[mi], vH[ni2], vH[ni2 + 2]);
#pragma unroll
            for (int mi = 0; mi < 2; mi++)
#pragma unroll
                for (int ni2 = 0; ni2 < 2; ni2++)
                    mma16(acc_o[mi][ni2], pH[mi], vL[ni2], vL[ni2 + 2]);
        }
    }

    // ---- finalize: heads (concat layout) as bf16 hi/lo ----
#pragma unroll
    for (int mi = 0; mi < 2; mi++)
#pragma unroll
        for (int half = 0; half < 2; half++) {
            const float inv = 1.0f / li[mi][half];
            const int tok = q0 + QR + mi * 16 + g + 8 * half;
#pragma unroll
            for (int ni2 = 0; ni2 < 2; ni2++) {
                const int col = wn2 * 16 + ni2 * 8 + 2 * t4;
                float v0 = acc_o[mi][ni2][half * 2]     * inv;
                float v1 = acc_o[mi][ni2][half * 2 + 1] * inv;
                uint32_t lo;
                uint32_t hi = split_hi(v0, v1, lo);
                size_t a = ((size_t)b * SS + tok) * DD + h * DKK + col;
                *(uint32_t*)(g_hhi + a) = hi;
                *(uint32_t*)(g_hlo + a) = lo;
            }
        }
}

// ---------------------------------------------------------------------------
extern "C" void kernel_launch(void* const* d_in, const int* in_sizes, int n_in,
                              void* d_out, int out_size) {
    const float* x    = (const float*)d_in[0];
    const int*   mask = (const int*)  d_in[1];
    const float* Wq   = (const float*)d_in[2];
    const float* Wk   = (const float*)d_in[3];
    const float* Wv   = (const float*)d_in[4];
    const float* Wo   = (const float*)d_in[5];
    const float* bias = (const float*)d_in[6];
    float* out = (float*)d_out;

    // 0) weight transpose + bf16 hi/lo split; x bf16 hi/lo split
    prepw_kernel<<<dim3(8, 8, 4), 256>>>(Wq, Wk, Wv, Wo);
    prepx_kernel<<<MM * DD / 4 / 256, 256>>>(x);

    // 1) QKV projections (3xBF16 mma.sync)
    cudaFuncSetAttribute(mma_gemm_kernel,
                         cudaFuncAttributeMaxDynamicSharedMemorySize, SMEM_GEMM);
    mma_gemm_kernel<<<dim3(MM / 128, 4, 3), 256, SMEM_GEMM>>>(0, bias, out);

    // 2) fused masked-softmax attention (flash, bf16 mma.sync)
    cudaFuncSetAttribute(attn_kernel,
                         cudaFuncAttributeMaxDynamicSharedMemorySize, SMEM_ATTN);
    attn_kernel<<<dim3(SS / 64, BB * HH), 256, SMEM_ATTN>>>(mask);

    // 3) output projection (3xBF16 mma.sync)
    mma_gemm_kernel<<<dim3(MM / 128, 4, 1), 256, SMEM_GEMM>>>(3, bias, out);
}

// round 9
// speedup vs baseline: 2.1805x; 1.1207x over previous
#include <cuda_runtime.h>
#include <cuda_bf16.h>
#include <cstdint>

#define BB  32
#define SS  512
#define DD  512
#define HH  8
#define DKK 64
#define MM  (BB*SS)   // 16384

typedef __nv_bfloat16 bf16;

// Q pre-scale: 1/sqrt(64) * log2(e)  (scores land in log2 domain)
#define QSCL (0.125f * 1.4426950408889634f)

// Scratch (device globals; no runtime allocation allowed)
__device__ bf16 g_Qhi[(size_t)BB*HH*SS*DKK];  // [bh][s][dk] (pre-scaled)
__device__ bf16 g_Qlo[(size_t)BB*HH*SS*DKK];
__device__ bf16 g_Khi[(size_t)BB*HH*SS*DKK];  // [bh][s][dk]
__device__ bf16 g_Klo[(size_t)BB*HH*SS*DKK];
__device__ bf16 g_Vthi[(size_t)BB*HH*DKK*SS]; // [bh][dk][s] (transposed)
__device__ bf16 g_Vtlo[(size_t)BB*HH*DKK*SS];
__device__ bf16 g_xhi[(size_t)MM*DD];         // x split hi
__device__ bf16 g_xlo[(size_t)MM*DD];
__device__ bf16 g_hhi[(size_t)MM*DD];         // heads split hi (concat layout)
__device__ bf16 g_hlo[(size_t)MM*DD];
__device__ bf16 g_Whi[(size_t)4*DD*DD];       // [mat][n][k]
__device__ bf16 g_Wlo[(size_t)4*DD*DD];

// ===================== PTX helpers =====================
__device__ __forceinline__ void cpasync16(uint32_t s, const void* g) {
    asm volatile("cp.async.cg.shared.global [%0], [%1], 16;" :: "r"(s), "l"(g));
}
__device__ __forceinline__ void cpcommit() {
    asm volatile("cp.async.commit_group;" ::: "memory");
}
template <int N> __device__ __forceinline__ void cpwait() {
    asm volatile("cp.async.wait_group %0;" :: "n"(N) : "memory");
}
#define LDMX4(r, a)                                                            \
    asm volatile("ldmatrix.sync.aligned.m8n8.x4.shared.b16 {%0,%1,%2,%3}, [%4];" \
        : "=r"((r)[0]), "=r"((r)[1]), "=r"((r)[2]), "=r"((r)[3]) : "r"(a))

__device__ __forceinline__ void mma16(float* c, const uint32_t* a,
                                      uint32_t b0, uint32_t b1) {
    asm volatile(
        "mma.sync.aligned.m16n8k16.row.col.f32.bf16.bf16.f32 "
        "{%0,%1,%2,%3},{%4,%5,%6,%7},{%8,%9},{%0,%1,%2,%3};"
        : "+f"(c[0]), "+f"(c[1]), "+f"(c[2]), "+f"(c[3])
        : "r"(a[0]), "r"(a[1]), "r"(a[2]), "r"(a[3]), "r"(b0), "r"(b1));
}

__device__ __forceinline__ uint32_t pack2(bf16 a, bf16 b) {
    return (uint32_t)__bfloat16_as_ushort(a) |
           ((uint32_t)__bfloat16_as_ushort(b) << 16);
}
__device__ __forceinline__ uint32_t split_hi(float v0, float v1, uint32_t& lo) {
    bf16 h0 = __float2bfloat16(v0), h1 = __float2bfloat16(v1);
    lo = pack2(__float2bfloat16(v0 - __bfloat162float(h0)),
               __float2bfloat16(v1 - __bfloat162float(h1)));
    return pack2(h0, h1);
}

// ---------------------------------------------------------------------------
// Prep W: transpose weights into [mat][n][k], split to bf16 hi/lo.
// ---------------------------------------------------------------------------
__global__ void prepw_kernel(const float* __restrict__ Wq,
                             const float* __restrict__ Wk,
                             const float* __restrict__ Wv,
                             const float* __restrict__ Wo) {
    __shared__ float t[64][65];
    const int z  = blockIdx.z;
    const int y  = blockIdx.y;
    const int xt = blockIdx.x;
    const float* W = (z == 0) ? Wq : (z == 1) ? Wk : (z == 2) ? Wv : Wo;
    const int tid = threadIdx.x;

#pragma unroll
    for (int i = 0; i < 4; i++) {
        int idx = tid + i * 256;
        int r   = idx >> 4;
        int c4  = (idx & 15) * 4;
        const float* p = (z < 3)
            ? W + (size_t)y * DD * DKK + (size_t)(xt * 64 + r) * DKK + c4
            : W + (size_t)(xt * 64 + r) * DD + y * 64 + c4;
        float4 v = *(const float4*)p;
        t[c4 + 0][r] = v.x; t[c4 + 1][r] = v.y;
        t[c4 + 2][r] = v.z; t[c4 + 3][r] = v.w;
    }
    __syncthreads();

    bf16* oh = g_Whi + (size_t)z * DD * DD;
    bf16* ol = g_Wlo + (size_t)z * DD * DD;
#pragma unroll
    for (int i = 0; i < 4; i++) {
        int idx = tid + i * 256;
        int c   = idx >> 4;
        int r4  = (idx & 15) * 4;
        size_t o = (size_t)(y * 64 + c) * DD + xt * 64 + r4;
        uint2 uh, ul;
        uh.x = split_hi(t[c][r4],     t[c][r4 + 1], ul.x);
        uh.y = split_hi(t[c][r4 + 2], t[c][r4 + 3], ul.y);
        *(uint2*)(oh + o) = uh;
        *(uint2*)(ol + o) = ul;
    }
}

// ---------------------------------------------------------------------------
// Prep X: split x into bf16 hi/lo, row-major.
// ---------------------------------------------------------------------------
__global__ void prepx_kernel(const float* __restrict__ x) {
    const size_t i4 = (size_t)blockIdx.x * 256 + threadIdx.x;
    float4 v = ((const float4*)x)[i4];
    uint2 uh, ul;
    uh.x = split_hi(v.x, v.y, ul.x);
    uh.y = split_hi(v.z, v.w, ul.y);
    *(uint2*)(g_xhi + i4 * 4) = uh;
    *(uint2*)(g_xlo + i4 * 4) = ul;
}

// ---------------------------------------------------------------------------
// bf16 3x-split GEMM, 2-stage cp.async double buffer, 2 blocks/SM.
// Block tile 128x128, K=512 in chunks of 32. 8 warps: 64(m) x 32(n) each.
// mat 0 -> Q (scaled by QSCL), 1 -> K natural, 2 -> Vt transposed,
// 3 -> out fp32 row-major.
// ---------------------------------------------------------------------------
#define ROWB 80
#define BUFB (128 * ROWB)
#define STGB (4 * BUFB)
#define NSTG 2
#define SMEM_GEMM (NSTG * STGB)     // 81920

__global__ __launch_bounds__(256, 2)
void mma_gemm_kernel(int matBase, const float* __restrict__ bias,
                     float* __restrict__ outp) {
    extern __shared__ char smc[];
    const uint32_t sb0 = (uint32_t)__cvta_generic_to_shared(smc);

    const int mat = matBase + blockIdx.z;
    const int m0  = blockIdx.x * 128;
    const int n0  = blockIdx.y * 128;
    const bf16* Ahi = (mat >= 3) ? g_hhi : g_xhi;
    const bf16* Alo = (mat >= 3) ? g_hlo : g_xlo;
    const bf16* Bhi = g_Whi + (size_t)mat * DD * DD;
    const bf16* Blo = g_Wlo + (size_t)mat * DD * DD;

    const int tid  = threadIdx.x;
    const int wid  = tid >> 5;
    const int lane = tid & 31;
    const int wm   = (wid >> 2) * 64;
    const int wn   = (wid & 3) * 32;
    const int g    = lane >> 2;
    const int t4   = lane & 3;

    const uint32_t lq  = lane >> 3;
    const uint32_t lr  = lane & 7;
    const uint32_t lmo = (lr + (lq & 1) * 8) * ROWB + (lq >> 1) * 16;

    float acc[4][4][4] = {};

#define ISSUE(ch) do {                                                         \
        const int d0 = (ch) * 32;                                              \
        const uint32_t st = sb0 + ((ch) & 1) * STGB;                           \
        _Pragma("unroll")                                                      \
        for (int t = 0; t < 2; t++) {                                          \
            int idx = tid + 256 * t;                                           \
            int row = idx >> 2;                                                \
            int seg = idx & 3;                                                 \
            uint32_t so = (uint32_t)(row * ROWB + seg * 16);                   \
            size_t  ga  = (size_t)(m0 + row) * DD + d0 + seg * 8;              \
            size_t  gb  = (size_t)(n0 + row) * DD + d0 + seg * 8;              \
            cpasync16(st + so,            Ahi + ga);                           \
            cpasync16(st + BUFB + so,     Alo + ga);                           \
            cpasync16(st + 2 * BUFB + so, Bhi + gb);                           \
            cpasync16(st + 3 * BUFB + so, Blo + gb);                           \
        }                                                                      \
        cpcommit();                                                            \
    } while (0)

    ISSUE(0);

    for (int ch = 0; ch < 16; ch++) {
        if (ch + 1 < 16) { ISSUE(ch + 1); cpwait<1>(); }
        else             { cpwait<0>(); }
        __syncthreads();

        const uint32_t st = sb0 + (ch & 1) * STGB;
#pragma unroll
        for (int kk = 0; kk < 2; kk++) {
            const uint32_t ko = kk * 32;
            uint32_t bH[2][4], bL[2][4];
#pragma unroll
            for (int nn = 0; nn < 2; nn++) {
                uint32_t bd = st + 2 * BUFB + (uint32_t)((wn + nn * 16) * ROWB) + ko + lmo;
                LDMX4(bH[nn], bd);
                LDMX4(bL[nn], bd + BUFB);
            }
#pragma unroll
            for (int mi = 0; mi < 4; mi++) {
                uint32_t aH[4], aL[4];
                uint32_t ad = st + (uint32_t)((wm + mi * 16) * ROWB) + ko + lmo;
                LDMX4(aH, ad);
                LDMX4(aL, ad + BUFB);
#pragma unroll
                for (int ni = 0; ni < 4; ni++) {
                    const int nn = ni >> 1, sel = ni & 1;
                    mma16(acc[mi][ni], aH, bH[nn][sel], bH[nn][sel + 2]);
                    mma16(acc[mi][ni], aL, bH[nn][sel], bH[nn][sel + 2]);
                    mma16(acc[mi][ni], aH, bL[nn][sel], bL[nn][sel + 2]);
                }
            }
        }
        __syncthreads();
    }

    // epilogue
    const float bv = bias[0];
#pragma unroll
    for (int mi = 0; mi < 4; mi++) {
#pragma unroll
        for (int h2 = 0; h2 < 2; h2++) {
            const int row = m0 + wm + mi * 16 + g + 8 * h2;
            const int b   = row >> 9;
            const int s   = row & 511;
#pragma unroll
            for (int ni = 0; ni < 4; ni++) {
                const int col0 = n0 + wn + ni * 8 + 2 * t4;
                float v0 = acc[mi][ni][2 * h2]     + bv;
                float v1 = acc[mi][ni][2 * h2 + 1] + bv;
                if (mat < 2) {
                    if (mat == 0) { v0 *= QSCL; v1 *= QSCL; }
                    bf16* dhi = (mat == 0) ? g_Qhi : g_Khi;
                    bf16* dlo = (mat == 0) ? g_Qlo : g_Klo;
                    size_t a = ((size_t)(b * HH + (col0 >> 6)) * SS + s) * DKK
                               + (col0 & 63);
                    uint32_t lo;
                    uint32_t hi = split_hi(v0, v1, lo);
                    *(uint32_t*)(dhi + a) = hi;
                    *(uint32_t*)(dlo + a) = lo;
                } else if (mat == 2) {
                    size_t a = ((size_t)(b * HH + (col0 >> 6)) * DKK + (col0 & 63)) * SS + s;
                    bf16 h0 = __float2bfloat16(v0), h1 = __float2bfloat16(v1);
                    g_Vthi[a]      = h0;
                    g_Vthi[a + SS] = h1;
                    g_Vtlo[a]      = __float2bfloat16(v0 - __bfloat162float(h0));
                    g_Vtlo[a + SS] = __float2bfloat16(v1 - __bfloat162float(h1));
                } else {
                    *(float2*)(outp + (size_t)row * DD + col0) = make_float2(v0, v1);
                }
            }
        }
    }
#undef ISSUE
}

// ---------------------------------------------------------------------------
// Flash attention on mma.sync bf16 (3x-split both matmuls).
// Q pre-scaled by 0.125*log2e -> softmax via exp2f, mask is a pure select.
// Per-warp partial li over its key slice; one cross-warp li reduce at end.
// grid (S/64, B*H), block 256 (8 warps: 2m x 4n).
// ---------------------------------------------------------------------------
#define QROWB 144                 // 128B row + 16 pad (conflict-free ldmatrix)
#define PROWB 272                 // 256B row + 16 pad
#define SQ_HI 0
#define SQ_LO 9216
#define SK_HI 18432
#define SK_LO 36864
#define SP_HI 18432               // P overlays K region (dead during PV)
#define SP_LO 35840
#define SV_HI 55296
#define SV_LO 72704
#define SRED  90112
#define SRED2 91136
#define SMEM_ATTN 92160

__global__ __launch_bounds__(256, 2)
void attn_kernel(const int* __restrict__ mask) {
    extern __shared__ char smc[];
    const uint32_t sb = (uint32_t)__cvta_generic_to_shared(smc);
    float* redf  = (float*)(smc + SRED);
    float* redf2 = (float*)(smc + SRED2);

    const int q0 = blockIdx.x * 64;
    const int bh = blockIdx.y;
    const int b  = bh / HH;
    const int h  = bh % HH;

    const int tid  = threadIdx.x;
    const int wid  = tid >> 5;
    const int lane = tid & 31;
    const int wm2  = wid >> 2;          // 0/1: q 32-group
    const int wn2  = wid & 3;           // 0..3
    const int g    = lane >> 2;
    const int t4   = lane & 3;
    const int QR   = wm2 * 32;
    const int KNB  = wn2 * 32;          // key base within ktile (scores)

    const uint32_t lq = lane >> 3, lr = lane & 7;
    const uint32_t lmoQ = (lr + (lq & 1) * 8) * QROWB + (lq >> 1) * 16;
    const uint32_t lmoP = (lr + (lq & 1) * 8) * PROWB + (lq >> 1) * 16;

    // Q tile load (group)
    {
        int row = tid >> 2;
        int s0  = (tid & 3) * 2;
        size_t   ga = ((size_t)bh * SS + q0 + row) * DKK;
        uint32_t so = sb + (uint32_t)(row * QROWB);
#pragma unroll
        for (int j = 0; j < 2; j++) {
            cpasync16(so + SQ_HI + (s0 + j) * 16, g_Qhi + ga + (s0 + j) * 8);
            cpasync16(so + SQ_LO + (s0 + j) * 16, g_Qlo + ga + (s0 + j) * 8);
        }
        cpcommit();
    }

    float acc_o[2][2][4] = {};          // [mi][ni2][c]
    float li[2][2] = {};                // per-warp PARTIAL (own key slice)
    float mx[2][2] = {{-1e30f, -1e30f}, {-1e30f, -1e30f}};

    for (int kt = 0; kt < 4; kt++) {
        __syncthreads();                // K/P and V regions free

        // K tile cp.async (128 keys x 64 d)
        {
            int row = tid >> 1;
            int sN  = (tid & 1) * 4;
            size_t   ga = ((size_t)bh * SS + kt * 128 + row) * DKK;
            uint32_t so = sb + (uint32_t)(row * QROWB);
#pragma unroll
            for (int j = 0; j < 4; j++) {
                cpasync16(so + SK_HI + (sN + j) * 16, g_Khi + ga + (sN + j) * 8);
                cpasync16(so + SK_LO + (sN + j) * 16, g_Klo + ga + (sN + j) * 8);
            }
            cpcommit();
        }
        // V^T tile cp.async (64 d x 128 keys)
        {
            int row = tid >> 2;
            int sN  = (tid & 3) * 4;
            size_t   ga = ((size_t)bh * DKK + row) * SS + kt * 128;
            uint32_t so = sb + (uint32_t)(row * PROWB);
#pragma unroll
            for (int j = 0; j < 4; j++) {
                cpasync16(so + SV_HI + (sN + j) * 16, g_Vthi + ga + (sN + j) * 8);
                cpasync16(so + SV_LO + (sN + j) * 16, g_Vtlo + ga + (sN + j) * 8);
            }
            cpcommit();
        }
        cpwait<1>();                    // Q + K complete (V may be in flight)
        __syncthreads();

        // ---- scores: 32q x 32k per warp ----
        float s4[2][4][4] = {};
#pragma unroll
        for (int ks = 0; ks < 4; ks++) {
            uint32_t aH[2][4], aL[2][4], bH[2][4], bL[2][4];
#pragma unroll
            for (int mi = 0; mi < 2; mi++) {
                uint32_t ad = sb + (uint32_t)((QR + mi * 16) * QROWB) + ks * 32 + lmoQ;
                LDMX4(aH[mi], ad + SQ_HI);
                LDMX4(aL[mi], ad + SQ_LO);
            }
#pragma unroll
            for (int nn = 0; nn < 2; nn++) {
                uint32_t bd = sb + (uint32_t)((KNB + nn * 16) * QROWB) + ks * 32 + lmoQ;
                LDMX4(bH[nn], bd + SK_HI);
                LDMX4(bL[nn], bd + SK_LO);
            }
#pragma unroll
            for (int mi = 0; mi < 2; mi++)
#pragma unroll
                for (int ni = 0; ni < 4; ni++) {
                    const int nn = ni >> 1, sel = ni & 1;
                    mma16(s4[mi][ni], aH[mi], bH[nn][sel], bH[nn][sel + 2]);
                    mma16(s4[mi][ni], aL[mi], bH[nn][sel], bH[nn][sel + 2]);
                    mma16(s4[mi][ni], aH[mi], bL[nn][sel], bL[nn][sel + 2]);
                }
        }

        // ---- mask (pure select: scores pre-scaled in log2 domain) ----
        int2 mk[4];
#pragma unroll
        for (int ni = 0; ni < 4; ni++)
            mk[ni] = *(const int2*)(mask + b * SS + kt * 128 + KNB + ni * 8 + 2 * t4);
#pragma unroll
        for (int mi = 0; mi < 2; mi++)
#pragma unroll
            for (int ni = 0; ni < 4; ni++) {
                s4[mi][ni][0] = mk[ni].x ? s4[mi][ni][0] : -1e30f;
                s4[mi][ni][1] = mk[ni].y ? s4[mi][ni][1] : -1e30f;
                s4[mi][ni][2] = mk[ni].x ? s4[mi][ni][2] : -1e30f;
                s4[mi][ni][3] = mk[ni].y ? s4[mi][ni][3] : -1e30f;
            }

        // ---- local row max -> smem ----
#pragma unroll
        for (int mi = 0; mi < 2; mi++)
#pragma unroll
            for (int half = 0; half < 2; half++) {
                float m = -1e30f;
#pragma unroll
                for (int ni = 0; ni < 4; ni++)
                    m = fmaxf(m, fmaxf(s4[mi][ni][half * 2], s4[mi][ni][half * 2 + 1]));
                m = fmaxf(m, __shfl_xor_sync(0xffffffffu, m, 1));
                m = fmaxf(m, __shfl_xor_sync(0xffffffffu, m, 2));
                if (t4 == 0)
                    redf[(wm2 * 4 + wn2) * 32 + mi * 16 + g + 8 * half] = m;
            }
        __syncthreads();

        // ---- global max, rescale O + partial li, p=exp2, write P ----
        float mnew[2][2], lsum[2][2] = {};
#pragma unroll
        for (int mi = 0; mi < 2; mi++)
#pragma unroll
            for (int half = 0; half < 2; half++) {
                const int rl = mi * 16 + g + 8 * half;
                float gm = fmaxf(fmaxf(redf[(wm2 * 4 + 0) * 32 + rl],
                                       redf[(wm2 * 4 + 1) * 32 + rl]),
                                 fmaxf(redf[(wm2 * 4 + 2) * 32 + rl],
                                       redf[(wm2 * 4 + 3) * 32 + rl]));
                float mn = fmaxf(mx[mi][half], gm);
                float al = exp2f(mx[mi][half] - mn);
                mx[mi][half] = mn;
                mnew[mi][half] = mn;
                li[mi][half] *= al;
#pragma unroll
                for (int ni2 = 0; ni2 < 2; ni2++) {
                    acc_o[mi][ni2][half * 2]     *= al;
                    acc_o[mi][ni2][half * 2 + 1] *= al;
                }
            }
#pragma unroll
        for (int mi = 0; mi < 2; mi++)
#pragma unroll
            for (int ni = 0; ni < 4; ni++) {
                float p0 = exp2f(s4[mi][ni][0] - mnew[mi][0]);
                float p1 = exp2f(s4[mi][ni][1] - mnew[mi][0]);
                float p2 = exp2f(s4[mi][ni][2] - mnew[mi][1]);
                float p3 = exp2f(s4[mi][ni][3] - mnew[mi][1]);
                lsum[mi][0] += p0 + p1;
                lsum[mi][1] += p2 + p3;
                uint32_t lo0, lo1;
                uint32_t hi0 = split_hi(p0, p1, lo0);
                uint32_t hi1 = split_hi(p2, p3, lo1);
                const uint32_t cb = (uint32_t)((KNB + ni * 8 + 2 * t4) * 2);
                const uint32_t r0 = (uint32_t)((QR + mi * 16 + g) * PROWB) + cb;
                *(uint32_t*)(smc + SP_HI + r0)               = hi0;
                *(uint32_t*)(smc + SP_LO + r0)               = lo0;
                *(uint32_t*)(smc + SP_HI + r0 + 8 * PROWB)   = hi1;
                *(uint32_t*)(smc + SP_LO + r0 + 8 * PROWB)   = lo1;
            }
        // partial li (this warp's 32-key slice; lanes t4 0..3 hold same q-rows,
        // so reduce over the 4 t4 lanes now to keep li exact per thread)
#pragma unroll
        for (int mi = 0; mi < 2; mi++)
#pragma unroll
            for (int half = 0; half < 2; half++) {
                float sgl = lsum[mi][half];
                sgl += __shfl_xor_sync(0xffffffffu, sgl, 1);
                sgl += __shfl_xor_sync(0xffffffffu, sgl, 2);
                li[mi][half] += sgl;
            }

        cpwait<0>();                    // V complete
        __syncthreads();                // V + P visible to all

        // ---- PV: 32q x 16v per warp, k = 128 keys ----
#pragma unroll
        for (int ks = 0; ks < 8; ks++) {
            uint32_t pH[2][4], pL[2][4], vH[4], vL[4];
#pragma unroll
            for (int mi = 0; mi < 2; mi++) {
                uint32_t pd = sb + (uint32_t)((QR + mi * 16) * PROWB) + ks * 32 + lmoP;
                LDMX4(pH[mi], pd + SP_HI);
                LDMX4(pL[mi], pd + SP_LO);
            }
            uint32_t vd = sb + (uint32_t)((wn2 * 16) * PROWB) + ks * 32 + lmoP;
            LDMX4(vH, vd + SV_HI);
            LDMX4(vL, vd + SV_LO);
#pragma unroll
            for (int mi = 0; mi < 2; mi++)
#pragma unroll
                for (int ni2 = 0; ni2 < 2; ni2++) {
                    mma16(acc_o[mi][ni2], pH[mi], vH[ni2], vH[ni2 + 2]);
                    mma16(acc_o[mi][ni2], pL[mi], vH[ni2], vH[ni2 + 2]);
                    mma16(acc_o[mi][ni2], pH[mi], vL[ni2], vL[ni2 + 2]);
                }
        }
    }

    // ---- final li reduction across the 4 wn2 warps ----
#pragma unroll
    for (int mi = 0; mi < 2; mi++)
#pragma unroll
        for (int half = 0; half < 2; half++)
            if (t4 == 0)
                redf2[(wm2 * 4 + wn2) * 32 + mi * 16 + g + 8 * half] = li[mi][half];
    __syncthreads();
#pragma unroll
    for (int mi = 0; mi < 2; mi++)
#pragma unroll
        for (int half = 0; half < 2; half++) {
            const int rl = mi * 16 + g + 8 * half;
            li[mi][half] = redf2[(wm2 * 4 + 0) * 32 + rl]
                         + redf2[(wm2 * 4 + 1) * 32 + rl]
                         + redf2[(wm2 * 4 + 2) * 32 + rl]
                         + redf2[(wm2 * 4 + 3) * 32 + rl];
        }

    // ---- finalize: heads (concat layout) as bf16 hi/lo ----
#pragma unroll
    for (int mi = 0; mi < 2; mi++)
#pragma unroll
        for (int half = 0; half < 2; half++) {
            const float inv = 1.0f / li[mi][half];
            const int tok = q0 + QR + mi * 16 + g + 8 * half;
#pragma unroll
            for (int ni2 = 0; ni2 < 2; ni2++) {
                const int col = wn2 * 16 + ni2 * 8 + 2 * t4;
                float v0 = acc_o[mi][ni2][half * 2]     * inv;
                float v1 = acc_o[mi][ni2][half * 2 + 1] * inv;
                uint32_t lo;
                uint32_t hi = split_hi(v0, v1, lo);
                size_t a = ((size_t)b * SS + tok) * DD + h * DKK + col;
                *(uint32_t*)(g_hhi + a) = hi;
                *(uint32_t*)(g_hlo + a) = lo;
            }
        }
}

// ---------------------------------------------------------------------------
extern "C" void kernel_launch(void* const* d_in, const int* in_sizes, int n_in,
                              void* d_out, int out_size) {
    const float* x    = (const float*)d_in[0];
    const int*   mask = (const int*)  d_in[1];
    const float* Wq   = (const float*)d_in[2];
    const float* Wk   = (const float*)d_in[3];
    const float* Wv   = (const float*)d_in[4];
    const float* Wo   = (const float*)d_in[5];
    const float* bias = (const float*)d_in[6];
    float* out = (float*)d_out;

    // 0) weight transpose + bf16 hi/lo split; x bf16 hi/lo split
    prepw_kernel<<<dim3(8, 8, 4), 256>>>(Wq, Wk, Wv, Wo);
    prepx_kernel<<<MM * DD / 4 / 256, 256>>>(x);

    // 1) QKV projections (3xBF16 mma.sync, double-buffered, 2 blocks/SM)
    cudaFuncSetAttribute(mma_gemm_kernel,
                         cudaFuncAttributeMaxDynamicSharedMemorySize, SMEM_GEMM);
    mma_gemm_kernel<<<dim3(MM / 128, 4, 3), 256, SMEM_GEMM>>>(0, bias, out);

    // 2) fused masked-softmax attention (flash, bf16 mma.sync)
    cudaFuncSetAttribute(attn_kernel,
                         cudaFuncAttributeMaxDynamicSharedMemorySize, SMEM_ATTN);
    attn_kernel<<<dim3(SS / 64, BB * HH), 256, SMEM_ATTN>>>(mask);

    // 3) output projection (3xBF16 mma.sync)
    mma_gemm_kernel<<<dim3(MM / 128, 4, 1), 256, SMEM_GEMM>>>(3, bias, out);
}

// round 10
// speedup vs baseline: 3.0661x; 1.4061x over previous
#include <cuda_runtime.h>
#include <cuda_fp16.h>
#include <cstdint>

#define BB  32
#define SS  512
#define DD  512
#define HH  8
#define DKK 64
#define MM  (BB*SS)   // 16384

typedef __half fp16;

// Q pre-scale: 1/sqrt(64) * log2(e)  (scores land in log2 domain)
#define QSCL (0.125f * 1.4426950408889634f)

// Scratch (device globals; no runtime allocation allowed)
__device__ fp16 g_Qhi[(size_t)BB*HH*SS*DKK];  // [bh][s][dk] (pre-scaled)
__device__ fp16 g_Qlo[(size_t)BB*HH*SS*DKK];
__device__ fp16 g_Khi[(size_t)BB*HH*SS*DKK];  // [bh][s][dk] (hi only)
__device__ fp16 g_Vthi[(size_t)BB*HH*DKK*SS]; // [bh][dk][s] (hi only)
__device__ fp16 g_xhi[(size_t)MM*DD];         // x split hi
__device__ fp16 g_xlo[(size_t)MM*DD];
__device__ fp16 g_hhi[(size_t)MM*DD];         // heads split hi (concat layout)
__device__ fp16 g_hlo[(size_t)MM*DD];
__device__ fp16 g_Whi[(size_t)4*DD*DD];       // [mat][n][k] (hi only)

// ===================== PTX helpers =====================
__device__ __forceinline__ void cpasync16(uint32_t s, const void* g) {
    asm volatile("cp.async.cg.shared.global [%0], [%1], 16;" :: "r"(s), "l"(g));
}
__device__ __forceinline__ void cpcommit() {
    asm volatile("cp.async.commit_group;" ::: "memory");
}
template <int N> __device__ __forceinline__ void cpwait() {
    asm volatile("cp.async.wait_group %0;" :: "n"(N) : "memory");
}
#define LDMX4(r, a)                                                            \
    asm volatile("ldmatrix.sync.aligned.m8n8.x4.shared.b16 {%0,%1,%2,%3}, [%4];" \
        : "=r"((r)[0]), "=r"((r)[1]), "=r"((r)[2]), "=r"((r)[3]) : "r"(a))

__device__ __forceinline__ void mma16(float* c, const uint32_t* a,
                                      uint32_t b0, uint32_t b1) {
    asm volatile(
        "mma.sync.aligned.m16n8k16.row.col.f32.f16.f16.f32 "
        "{%0,%1,%2,%3},{%4,%5,%6,%7},{%8,%9},{%0,%1,%2,%3};"
        : "+f"(c[0]), "+f"(c[1]), "+f"(c[2]), "+f"(c[3])
        : "r"(a[0]), "r"(a[1]), "r"(a[2]), "r"(a[3]), "r"(b0), "r"(b1));
}

__device__ __forceinline__ uint32_t pack2(fp16 a, fp16 b) {
    return (uint32_t)__half_as_ushort(a) |
           ((uint32_t)__half_as_ushort(b) << 16);
}
__device__ __forceinline__ uint32_t split_hi(float v0, float v1, uint32_t& lo) {
    fp16 h0 = __float2half_rn(v0), h1 = __float2half_rn(v1);
    lo = pack2(__float2half_rn(v0 - __half2float(h0)),
               __float2half_rn(v1 - __half2float(h1)));
    return pack2(h0, h1);
}

// ---------------------------------------------------------------------------
// Prep W: transpose weights into [mat][n][k], quantize to fp16 (hi only).
// ---------------------------------------------------------------------------
__global__ void prepw_kernel(const float* __restrict__ Wq,
                             const float* __restrict__ Wk,
                             const float* __restrict__ Wv,
                             const float* __restrict__ Wo) {
    __shared__ float t[64][65];
    const int z  = blockIdx.z;
    const int y  = blockIdx.y;
    const int xt = blockIdx.x;
    const float* W = (z == 0) ? Wq : (z == 1) ? Wk : (z == 2) ? Wv : Wo;
    const int tid = threadIdx.x;

#pragma unroll
    for (int i = 0; i < 4; i++) {
        int idx = tid + i * 256;
        int r   = idx >> 4;
        int c4  = (idx & 15) * 4;
        const float* p = (z < 3)
            ? W + (size_t)y * DD * DKK + (size_t)(xt * 64 + r) * DKK + c4
            : W + (size_t)(xt * 64 + r) * DD + y * 64 + c4;
        float4 v = *(const float4*)p;
        t[c4 + 0][r] = v.x; t[c4 + 1][r] = v.y;
        t[c4 + 2][r] = v.z; t[c4 + 3][r] = v.w;
    }
    __syncthreads();

    fp16* oh = g_Whi + (size_t)z * DD * DD;
#pragma unroll
    for (int i = 0; i < 4; i++) {
        int idx = tid + i * 256;
        int c   = idx >> 4;
        int r4  = (idx & 15) * 4;
        size_t o = (size_t)(y * 64 + c) * DD + xt * 64 + r4;
        uint2 uh;
        uh.x = pack2(__float2half_rn(t[c][r4]),     __float2half_rn(t[c][r4 + 1]));
        uh.y = pack2(__float2half_rn(t[c][r4 + 2]), __float2half_rn(t[c][r4 + 3]));
        *(uint2*)(oh + o) = uh;
    }
}

// ---------------------------------------------------------------------------
// Prep X: split x into fp16 hi/lo, row-major.
// ---------------------------------------------------------------------------
__global__ void prepx_kernel(const float* __restrict__ x) {
    const size_t i4 = (size_t)blockIdx.x * 256 + threadIdx.x;
    float4 v = ((const float4*)x)[i4];
    uint2 uh, ul;
    uh.x = split_hi(v.x, v.y, ul.x);
    uh.y = split_hi(v.z, v.w, ul.y);
    *(uint2*)(g_xhi + i4 * 4) = uh;
    *(uint2*)(g_xlo + i4 * 4) = ul;
}

// ---------------------------------------------------------------------------
// fp16 2-term split GEMM (A = hi+lo, B = hi only), 2-stage cp.async.
// Block tile 128x128, K=512 in chunks of 32. 8 warps: 64(m) x 32(n).
// mat 0 -> Q (scaled, 2-part), 1 -> K (hi), 2 -> Vt (hi), 3 -> out fp32.
// ---------------------------------------------------------------------------
#define ROWB 80
#define BUFB (128 * ROWB)
#define STGB (3 * BUFB)             // Ah, Al, Bh
#define SMEM_GEMM (2 * STGB)        // 61440

__global__ __launch_bounds__(256, 2)
void mma_gemm_kernel(int matBase, const float* __restrict__ bias,
                     float* __restrict__ outp) {
    extern __shared__ char smc[];
    const uint32_t sb0 = (uint32_t)__cvta_generic_to_shared(smc);

    const int mat = matBase + blockIdx.z;
    const int m0  = blockIdx.x * 128;
    const int n0  = blockIdx.y * 128;
    const fp16* Ahi = (mat >= 3) ? g_hhi : g_xhi;
    const fp16* Alo = (mat >= 3) ? g_hlo : g_xlo;
    const fp16* Bhi = g_Whi + (size_t)mat * DD * DD;

    const int tid  = threadIdx.x;
    const int wid  = tid >> 5;
    const int lane = tid & 31;
    const int wm   = (wid >> 2) * 64;
    const int wn   = (wid & 3) * 32;
    const int g    = lane >> 2;
    const int t4   = lane & 3;

    const uint32_t lq  = lane >> 3;
    const uint32_t lr  = lane & 7;
    const uint32_t lmo = (lr + (lq & 1) * 8) * ROWB + (lq >> 1) * 16;

    float acc[4][4][4] = {};

#define ISSUE(ch) do {                                                         \
        const int d0 = (ch) * 32;                                              \
        const uint32_t st = sb0 + ((ch) & 1) * STGB;                           \
        _Pragma("unroll")                                                      \
        for (int t = 0; t < 2; t++) {                                          \
            int idx = tid + 256 * t;                                           \
            int row = idx >> 2;                                                \
            int seg = idx & 3;                                                 \
            uint32_t so = (uint32_t)(row * ROWB + seg * 16);                   \
            size_t  ga  = (size_t)(m0 + row) * DD + d0 + seg * 8;              \
            size_t  gb  = (size_t)(n0 + row) * DD + d0 + seg * 8;              \
            cpasync16(st + so,            Ahi + ga);                           \
            cpasync16(st + BUFB + so,     Alo + ga);                           \
            cpasync16(st + 2 * BUFB + so, Bhi + gb);                           \
        }                                                                      \
        cpcommit();                                                            \
    } while (0)

    ISSUE(0);

    for (int ch = 0; ch < 16; ch++) {
        if (ch + 1 < 16) { ISSUE(ch + 1); cpwait<1>(); }
        else             { cpwait<0>(); }
        __syncthreads();

        const uint32_t st = sb0 + (ch & 1) * STGB;
#pragma unroll
        for (int kk = 0; kk < 2; kk++) {
            const uint32_t ko = kk * 32;
            uint32_t bH[2][4];
#pragma unroll
            for (int nn = 0; nn < 2; nn++) {
                uint32_t bd = st + 2 * BUFB + (uint32_t)((wn + nn * 16) * ROWB) + ko + lmo;
                LDMX4(bH[nn], bd);
            }
#pragma unroll
            for (int mi = 0; mi < 4; mi++) {
                uint32_t aH[4], aL[4];
                uint32_t ad = st + (uint32_t)((wm + mi * 16) * ROWB) + ko + lmo;
                LDMX4(aH, ad);
                LDMX4(aL, ad + BUFB);
#pragma unroll
                for (int ni = 0; ni < 4; ni++) {
                    const int nn = ni >> 1, sel = ni & 1;
                    mma16(acc[mi][ni], aH, bH[nn][sel], bH[nn][sel + 2]);
                    mma16(acc[mi][ni], aL, bH[nn][sel], bH[nn][sel + 2]);
                }
            }
        }
        __syncthreads();
    }

    // epilogue
    const float bv = bias[0];
#pragma unroll
    for (int mi = 0; mi < 4; mi++) {
#pragma unroll
        for (int h2 = 0; h2 < 2; h2++) {
            const int row = m0 + wm + mi * 16 + g + 8 * h2;
            const int b   = row >> 9;
            const int s   = row & 511;
#pragma unroll
            for (int ni = 0; ni < 4; ni++) {
                const int col0 = n0 + wn + ni * 8 + 2 * t4;
                float v0 = acc[mi][ni][2 * h2]     + bv;
                float v1 = acc[mi][ni][2 * h2 + 1] + bv;
                if (mat == 0) {
                    v0 *= QSCL; v1 *= QSCL;
                    size_t a = ((size_t)(b * HH + (col0 >> 6)) * SS + s) * DKK
                               + (col0 & 63);
                    uint32_t lo;
                    uint32_t hi = split_hi(v0, v1, lo);
                    *(uint32_t*)(g_Qhi + a) = hi;
                    *(uint32_t*)(g_Qlo + a) = lo;
                } else if (mat == 1) {
                    size_t a = ((size_t)(b * HH + (col0 >> 6)) * SS + s) * DKK
                               + (col0 & 63);
                    *(uint32_t*)(g_Khi + a) =
                        pack2(__float2half_rn(v0), __float2half_rn(v1));
                } else if (mat == 2) {
                    size_t a = ((size_t)(b * HH + (col0 >> 6)) * DKK + (col0 & 63)) * SS + s;
                    g_Vthi[a]      = __float2half_rn(v0);
                    g_Vthi[a + SS] = __float2half_rn(v1);
                } else {
                    *(float2*)(outp + (size_t)row * DD + col0) = make_float2(v0, v1);
                }
            }
        }
    }
#undef ISSUE
}

// ---------------------------------------------------------------------------
// Flash attention, fp16 2-term split (Q/P carry residuals; K/V hi only).
// Q pre-scaled by 0.125*log2e -> softmax via exp2f, mask is a pure select.
// grid (S/64, B*H), block 256 (8 warps: 2m x 4n).
// ---------------------------------------------------------------------------
#define QROWB 144                 // 128B row + 16 pad (conflict-free ldmatrix)
#define PROWB 272                 // 256B row + 16 pad
#define SQ_HI 0                   // 64*144 = 9216
#define SQ_LO 9216
#define SK    18432               // 128*144 = 18432 (hi only)
#define SP_HI 18432               // P overlays K (dead during PV)
#define SP_LO 35840               // 64*272 = 17408 each
#define SV    53248               // 64*272 = 17408 (hi only)
#define SRED  70656
#define SRED2 71680
#define SMEM_ATTN 72704

__global__ __launch_bounds__(256, 2)
void attn_kernel(const int* __restrict__ mask) {
    extern __shared__ char smc[];
    const uint32_t sb = (uint32_t)__cvta_generic_to_shared(smc);
    float* redf  = (float*)(smc + SRED);
    float* redf2 = (float*)(smc + SRED2);

    const int q0 = blockIdx.x * 64;
    const int bh = blockIdx.y;
    const int b  = bh / HH;
    const int h  = bh % HH;

    const int tid  = threadIdx.x;
    const int wid  = tid >> 5;
    const int lane = tid & 31;
    const int wm2  = wid >> 2;          // 0/1: q 32-group
    const int wn2  = wid & 3;           // 0..3
    const int g    = lane >> 2;
    const int t4   = lane & 3;
    const int QR   = wm2 * 32;
    const int KNB  = wn2 * 32;          // key base within ktile (scores)

    const uint32_t lq = lane >> 3, lr = lane & 7;
    const uint32_t lmoQ = (lr + (lq & 1) * 8) * QROWB + (lq >> 1) * 16;
    const uint32_t lmoP = (lr + (lq & 1) * 8) * PROWB + (lq >> 1) * 16;

    // Q tile load (hi + lo)
    {
        int row = tid >> 2;
        int s0  = (tid & 3) * 2;
        size_t   ga = ((size_t)bh * SS + q0 + row) * DKK;
        uint32_t so = sb + (uint32_t)(row * QROWB);
#pragma unroll
        for (int j = 0; j < 2; j++) {
            cpasync16(so + SQ_HI + (s0 + j) * 16, g_Qhi + ga + (s0 + j) * 8);
            cpasync16(so + SQ_LO + (s0 + j) * 16, g_Qlo + ga + (s0 + j) * 8);
        }
        cpcommit();
    }

    float acc_o[2][2][4] = {};          // [mi][ni2][c]
    float li[2][2] = {};                // per-warp PARTIAL (own key slice)
    float mx[2][2] = {{-1e30f, -1e30f}, {-1e30f, -1e30f}};

    for (int kt = 0; kt < 4; kt++) {
        __syncthreads();                // K/P and V regions free

        // K tile cp.async (128 keys x 64 d, hi only)
        {
            int row = tid >> 1;
            int sN  = (tid & 1) * 4;
            size_t   ga = ((size_t)bh * SS + kt * 128 + row) * DKK;
            uint32_t so = sb + (uint32_t)(row * QROWB);
#pragma unroll
            for (int j = 0; j < 4; j++)
                cpasync16(so + SK + (sN + j) * 16, g_Khi + ga + (sN + j) * 8);
            cpcommit();
        }
        // V^T tile cp.async (64 d x 128 keys, hi only)
        {
            int row = tid >> 2;
            int sN  = (tid & 3) * 4;
            size_t   ga = ((size_t)bh * DKK + row) * SS + kt * 128;
            uint32_t so = sb + (uint32_t)(row * PROWB);
#pragma unroll
            for (int j = 0; j < 4; j++)
                cpasync16(so + SV + (sN + j) * 16, g_Vthi + ga + (sN + j) * 8);
            cpcommit();
        }
        cpwait<1>();                    // Q + K complete (V may be in flight)
        __syncthreads();

        // ---- scores: 32q x 32k per warp, 2 passes ----
        float s4[2][4][4] = {};
#pragma unroll
        for (int ks = 0; ks < 4; ks++) {
            uint32_t aH[2][4], aL[2][4], bH[2][4];
#pragma unroll
            for (int mi = 0; mi < 2; mi++) {
                uint32_t ad = sb + (uint32_t)((QR + mi * 16) * QROWB) + ks * 32 + lmoQ;
                LDMX4(aH[mi], ad + SQ_HI);
                LDMX4(aL[mi], ad + SQ_LO);
            }
#pragma unroll
            for (int nn = 0; nn < 2; nn++) {
                uint32_t bd = sb + (uint32_t)((KNB + nn * 16) * QROWB) + ks * 32 + lmoQ;
                LDMX4(bH[nn], bd + SK);
            }
#pragma unroll
            for (int mi = 0; mi < 2; mi++)
#pragma unroll
                for (int ni = 0; ni < 4; ni++) {
                    const int nn = ni >> 1, sel = ni & 1;
                    mma16(s4[mi][ni], aH[mi], bH[nn][sel], bH[nn][sel + 2]);
                    mma16(s4[mi][ni], aL[mi], bH[nn][sel], bH[nn][sel + 2]);
                }
        }

        // ---- mask (pure select: scores pre-scaled in log2 domain) ----
        int2 mk[4];
#pragma unroll
        for (int ni = 0; ni < 4; ni++)
            mk[ni] = *(const int2*)(mask + b * SS + kt * 128 + KNB + ni * 8 + 2 * t4);
#pragma unroll
        for (int mi = 0; mi < 2; mi++)
#pragma unroll
            for (int ni = 0; ni < 4; ni++) {
                s4[mi][ni][0] = mk[ni].x ? s4[mi][ni][0] : -1e30f;
                s4[mi][ni][1] = mk[ni].y ? s4[mi][ni][1] : -1e30f;
                s4[mi][ni][2] = mk[ni].x ? s4[mi][ni][2] : -1e30f;
                s4[mi][ni][3] = mk[ni].y ? s4[mi][ni][3] : -1e30f;
            }

        // ---- local row max -> smem ----
#pragma unroll
        for (int mi = 0; mi < 2; mi++)
#pragma unroll
            for (int half = 0; half < 2; half++) {
                float m = -1e30f;
#pragma unroll
                for (int ni = 0; ni < 4; ni++)
                    m = fmaxf(m, fmaxf(s4[mi][ni][half * 2], s4[mi][ni][half * 2 + 1]));
                m = fmaxf(m, __shfl_xor_sync(0xffffffffu, m, 1));
                m = fmaxf(m, __shfl_xor_sync(0xffffffffu, m, 2));
                if (t4 == 0)
                    redf[(wm2 * 4 + wn2) * 32 + mi * 16 + g + 8 * half] = m;
            }
        __syncthreads();

        // ---- global max, rescale O + partial li, p=exp2, write P ----
        float mnew[2][2], lsum[2][2] = {};
#pragma unroll
        for (int mi = 0; mi < 2; mi++)
#pragma unroll
            for (int half = 0; half < 2; half++) {
                const int rl = mi * 16 + g + 8 * half;
                float gm = fmaxf(fmaxf(redf[(wm2 * 4 + 0) * 32 + rl],
                                       redf[(wm2 * 4 + 1) * 32 + rl]),
                                 fmaxf(redf[(wm2 * 4 + 2) * 32 + rl],
                                       redf[(wm2 * 4 + 3) * 32 + rl]));
                float mn = fmaxf(mx[mi][half], gm);
                float al = exp2f(mx[mi][half] - mn);
                mx[mi][half] = mn;
                mnew[mi][half] = mn;
                li[mi][half] *= al;
#pragma unroll
                for (int ni2 = 0; ni2 < 2; ni2++) {
                    acc_o[mi][ni2][half * 2]     *= al;
                    acc_o[mi][ni2][half * 2 + 1] *= al;
                }
            }
#pragma unroll
        for (int mi = 0; mi < 2; mi++)
#pragma unroll
            for (int ni = 0; ni < 4; ni++) {
                float p0 = exp2f(s4[mi][ni][0] - mnew[mi][0]);
                float p1 = exp2f(s4[mi][ni][1] - mnew[mi][0]);
                float p2 = exp2f(s4[mi][ni][2] - mnew[mi][1]);
                float p3 = exp2f(s4[mi][ni][3] - mnew[mi][1]);
                lsum[mi][0] += p0 + p1;
                lsum[mi][1] += p2 + p3;
                uint32_t lo0, lo1;
                uint32_t hi0 = split_hi(p0, p1, lo0);
                uint32_t hi1 = split_hi(p2, p3, lo1);
                const uint32_t cb = (uint32_t)((KNB + ni * 8 + 2 * t4) * 2);
                const uint32_t r0 = (uint32_t)((QR + mi * 16 + g) * PROWB) + cb;
                *(uint32_t*)(smc + SP_HI + r0)               = hi0;
                *(uint32_t*)(smc + SP_LO + r0)               = lo0;
                *(uint32_t*)(smc + SP_HI + r0 + 8 * PROWB)   = hi1;
                *(uint32_t*)(smc + SP_LO + r0 + 8 * PROWB)   = lo1;
            }
        // partial li over this warp's 32-key slice
#pragma unroll
        for (int mi = 0; mi < 2; mi++)
#pragma unroll
            for (int half = 0; half < 2; half++) {
                float sgl = lsum[mi][half];
                sgl += __shfl_xor_sync(0xffffffffu, sgl, 1);
                sgl += __shfl_xor_sync(0xffffffffu, sgl, 2);
                li[mi][half] += sgl;
            }

        cpwait<0>();                    // V complete
        __syncthreads();                // V + P visible to all

        // ---- PV: 32q x 16v per warp, k = 128 keys, 2 passes ----
#pragma unroll
        for (int ks = 0; ks < 8; ks++) {
            uint32_t pH[2][4], pL[2][4], vH[4];
#pragma unroll
            for (int mi = 0; mi < 2; mi++) {
                uint32_t pd = sb + (uint32_t)((QR + mi * 16) * PROWB) + ks * 32 + lmoP;
                LDMX4(pH[mi], pd + SP_HI);
                LDMX4(pL[mi], pd + SP_LO);
            }
            uint32_t vd = sb + (uint32_t)((wn2 * 16) * PROWB) + ks * 32 + lmoP;
            LDMX4(vH, vd + SV);
#pragma unroll
            for (int mi = 0; mi < 2; mi++)
#pragma unroll
                for (int ni2 = 0; ni2 < 2; ni2++) {
                    mma16(acc_o[mi][ni2], pH[mi], vH[ni2], vH[ni2 + 2]);
                    mma16(acc_o[mi][ni2], pL[mi], vH[ni2], vH[ni2 + 2]);
                }
        }
    }

    // ---- final li reduction across the 4 wn2 warps ----
#pragma unroll
    for (int mi = 0; mi < 2; mi++)
#pragma unroll
        for (int half = 0; half < 2; half++)
            if (t4 == 0)
                redf2[(wm2 * 4 + wn2) * 32 + mi * 16 + g + 8 * half] = li[mi][half];
    __syncthreads();
#pragma unroll
    for (int mi = 0; mi < 2; mi++)
#pragma unroll
        for (int half = 0; half < 2; half++) {
            const int rl = mi * 16 + g + 8 * half;
            li[mi][half] = redf2[(wm2 * 4 + 0) * 32 + rl]
                         + redf2[(wm2 * 4 + 1) * 32 + rl]
                         + redf2[(wm2 * 4 + 2) * 32 + rl]
                         + redf2[(wm2 * 4 + 3) * 32 + rl];
        }

    // ---- finalize: heads (concat layout) as fp16 hi/lo ----
#pragma unroll
    for (int mi = 0; mi < 2; mi++)
#pragma unroll
        for (int half = 0; half < 2; half++) {
            const float inv = 1.0f / li[mi][half];
            const int tok = q0 + QR + mi * 16 + g + 8 * half;
#pragma unroll
            for (int ni2 = 0; ni2 < 2; ni2++) {
                const int col = wn2 * 16 + ni2 * 8 + 2 * t4;
                float v0 = acc_o[mi][ni2][half * 2]     * inv;
                float v1 = acc_o[mi][ni2][half * 2 + 1] * inv;
                uint32_t lo;
                uint32_t hi = split_hi(v0, v1, lo);
                size_t a = ((size_t)b * SS + tok) * DD + h * DKK + col;
                *(uint32_t*)(g_hhi + a) = hi;
                *(uint32_t*)(g_hlo + a) = lo;
            }
        }
}

// ---------------------------------------------------------------------------
extern "C" void kernel_launch(void* const* d_in, const int* in_sizes, int n_in,
                              void* d_out, int out_size) {
    const float* x    = (const float*)d_in[0];
    const int*   mask = (const int*)  d_in[1];
    const float* Wq   = (const float*)d_in[2];
    const float* Wk   = (const float*)d_in[3];
    const float* Wv   = (const float*)d_in[4];
    const float* Wo   = (const float*)d_in[5];
    const float* bias = (const float*)d_in[6];
    float* out = (float*)d_out;

    // 0) weight transpose + fp16 quantize; x fp16 hi/lo split
    prepw_kernel<<<dim3(8, 8, 4), 256>>>(Wq, Wk, Wv, Wo);
    prepx_kernel<<<MM * DD / 4 / 256, 256>>>(x);

    // 1) QKV projections (fp16 2-term mma.sync, double-buffered)
    cudaFuncSetAttribute(mma_gemm_kernel,
                         cudaFuncAttributeMaxDynamicSharedMemorySize, SMEM_GEMM);
    mma_gemm_kernel<<<dim3(MM / 128, 4, 3), 256, SMEM_GEMM>>>(0, bias, out);

    // 2) fused masked-softmax attention (flash, fp16 mma.sync)
    cudaFuncSetAttribute(attn_kernel,
                         cudaFuncAttributeMaxDynamicSharedMemorySize, SMEM_ATTN);
    attn_kernel<<<dim3(SS / 64, BB * HH), 256, SMEM_ATTN>>>(mask);

    // 3) output projection (fp16 2-term mma.sync)
    mma_gemm_kernel<<<dim3(MM / 128, 4, 1), 256, SMEM_GEMM>>>(3, bias, out);
}

// round 12
// speedup vs baseline: 3.0683x; 1.0007x over previous
#include <cuda_runtime.h>
#include <cuda_fp16.h>
#include <cstdint>

#define BB  32
#define SS  512
#define DD  512
#define HH  8
#define DKK 64
#define MM  (BB*SS)   // 16384

typedef __half fp16;

// Q pre-scale: 1/sqrt(64) * log2(e)  (scores land in log2 domain)
#define QSCL (0.125f * 1.4426950408889634f)

// Scratch (device globals; no runtime allocation allowed)
__device__ fp16 g_Qhi[(size_t)BB*HH*SS*DKK];  // [bh][s][dk] (pre-scaled)
__device__ fp16 g_Qlo[(size_t)BB*HH*SS*DKK];
__device__ fp16 g_Khi[(size_t)BB*HH*SS*DKK];  // [bh][s][dk] (hi only)
__device__ fp16 g_Vthi[(size_t)BB*HH*DKK*SS]; // [bh][dk][s] (hi only)
__device__ fp16 g_xhi[(size_t)MM*DD];         // x split hi
__device__ fp16 g_xlo[(size_t)MM*DD];
__device__ fp16 g_hhi[(size_t)MM*DD];         // heads split hi (concat layout)
__device__ fp16 g_hlo[(size_t)MM*DD];
__device__ fp16 g_Whi[(size_t)4*DD*DD];       // [mat][n][k] (hi only)

// ===================== PTX helpers =====================
__device__ __forceinline__ void cpasync16(uint32_t s, const void* g) {
    asm volatile("cp.async.cg.shared.global [%0], [%1], 16;" :: "r"(s), "l"(g));
}
__device__ __forceinline__ void cpcommit() {
    asm volatile("cp.async.commit_group;" ::: "memory");
}
template <int N> __device__ __forceinline__ void cpwait() {
    asm volatile("cp.async.wait_group %0;" :: "n"(N) : "memory");
}
#define LDMX4(r, a)                                                            \
    asm volatile("ldmatrix.sync.aligned.m8n8.x4.shared.b16 {%0,%1,%2,%3}, [%4];" \
        : "=r"((r)[0]), "=r"((r)[1]), "=r"((r)[2]), "=r"((r)[3]) : "r"(a))

__device__ __forceinline__ void mma16(float* c, const uint32_t* a,
                                      uint32_t b0, uint32_t b1) {
    asm volatile(
        "mma.sync.aligned.m16n8k16.row.col.f32.f16.f16.f32 "
        "{%0,%1,%2,%3},{%4,%5,%6,%7},{%8,%9},{%0,%1,%2,%3};"
        : "+f"(c[0]), "+f"(c[1]), "+f"(c[2]), "+f"(c[3])
        : "r"(a[0]), "r"(a[1]), "r"(a[2]), "r"(a[3]), "r"(b0), "r"(b1));
}

__device__ __forceinline__ uint32_t pack2(fp16 a, fp16 b) {
    return (uint32_t)__half_as_ushort(a) |
           ((uint32_t)__half_as_ushort(b) << 16);
}
__device__ __forceinline__ uint32_t split_hi(float v0, float v1, uint32_t& lo) {
    fp16 h0 = __float2half_rn(v0), h1 = __float2half_rn(v1);
    lo = pack2(__float2half_rn(v0 - __half2float(h0)),
               __float2half_rn(v1 - __half2float(h1)));
    return pack2(h0, h1);
}

// ---------------------------------------------------------------------------
// Prep W: transpose weights into [mat][n][k], quantize to fp16 (hi only).
// ---------------------------------------------------------------------------
__global__ void prepw_kernel(const float* __restrict__ Wq,
                             const float* __restrict__ Wk,
                             const float* __restrict__ Wv,
                             const float* __restrict__ Wo) {
    __shared__ float t[64][65];
    const int z  = blockIdx.z;
    const int y  = blockIdx.y;
    const int xt = blockIdx.x;
    const float* W = (z == 0) ? Wq : (z == 1) ? Wk : (z == 2) ? Wv : Wo;
    const int tid = threadIdx.x;

#pragma unroll
    for (int i = 0; i < 4; i++) {
        int idx = tid + i * 256;
        int r   = idx >> 4;
        int c4  = (idx & 15) * 4;
        const float* p = (z < 3)
            ? W + (size_t)y * DD * DKK + (size_t)(xt * 64 + r) * DKK + c4
            : W + (size_t)(xt * 64 + r) * DD + y * 64 + c4;
        float4 v = *(const float4*)p;
        t[c4 + 0][r] = v.x; t[c4 + 1][r] = v.y;
        t[c4 + 2][r] = v.z; t[c4 + 3][r] = v.w;
    }
    __syncthreads();

    fp16* oh = g_Whi + (size_t)z * DD * DD;
#pragma unroll
    for (int i = 0; i < 4; i++) {
        int idx = tid + i * 256;
        int c   = idx >> 4;
        int r4  = (idx & 15) * 4;
        size_t o = (size_t)(y * 64 + c) * DD + xt * 64 + r4;
        uint2 uh;
        uh.x = pack2(__float2half_rn(t[c][r4]),     __float2half_rn(t[c][r4 + 1]));
        uh.y = pack2(__float2half_rn(t[c][r4 + 2]), __float2half_rn(t[c][r4 + 3]));
        *(uint2*)(oh + o) = uh;
    }
}

// ---------------------------------------------------------------------------
// Prep X: split x into fp16 hi/lo, row-major.
// ---------------------------------------------------------------------------
__global__ void prepx_kernel(const float* __restrict__ x) {
    const size_t i4 = (size_t)blockIdx.x * 256 + threadIdx.x;
    float4 v = ((const float4*)x)[i4];
    uint2 uh, ul;
    uh.x = split_hi(v.x, v.y, ul.x);
    uh.y = split_hi(v.z, v.w, ul.y);
    *(uint2*)(g_xhi + i4 * 4) = uh;
    *(uint2*)(g_xlo + i4 * 4) = ul;
}

// ---------------------------------------------------------------------------
// fp16 2-term split GEMM (A = hi+lo, B = hi only), 3-stage cp.async,
// ONE __syncthreads per chunk. Block tile 128x128, K=512 in chunks of 32.
// mat 0 -> Q (scaled, 2-part), 1 -> K (hi), 2 -> Vt (hi), 3 -> out fp32.
// ---------------------------------------------------------------------------
#define ROWB 80
#define BUFB (128 * ROWB)
#define STGB (3 * BUFB)             // Ah, Al, Bh = 30720
#define NSTG 3
#define SMEM_GEMM (NSTG * STGB)     // 92160

__global__ __launch_bounds__(256, 2)
void mma_gemm_kernel(int matBase, const float* __restrict__ bias,
                     float* __restrict__ outp) {
    extern __shared__ char smc[];
    const uint32_t sb0 = (uint32_t)__cvta_generic_to_shared(smc);

    const int mat = matBase + blockIdx.z;
    const int m0  = blockIdx.x * 128;
    const int n0  = blockIdx.y * 128;
    const fp16* Ahi = (mat >= 3) ? g_hhi : g_xhi;
    const fp16* Alo = (mat >= 3) ? g_hlo : g_xlo;
    const fp16* Bhi = g_Whi + (size_t)mat * DD * DD;

    const int tid  = threadIdx.x;
    const int wid  = tid >> 5;
    const int lane = tid & 31;
    const int wm   = (wid >> 2) * 64;
    const int wn   = (wid & 3) * 32;
    const int g    = lane >> 2;
    const int t4   = lane & 3;

    const uint32_t lq  = lane >> 3;
    const uint32_t lr  = lane & 7;
    const uint32_t lmo = (lr + (lq & 1) * 8) * ROWB + (lq >> 1) * 16;

    float acc[4][4][4] = {};

#define ISSUE(ch) do {                                                         \
        const int d0 = (ch) * 32;                                              \
        const uint32_t st = sb0 + ((ch) % NSTG) * STGB;                        \
        _Pragma("unroll")                                                      \
        for (int t = 0; t < 2; t++) {                                          \
            int idx = tid + 256 * t;                                           \
            int row = idx >> 2;                                                \
            int seg = idx & 3;                                                 \
            uint32_t so = (uint32_t)(row * ROWB + seg * 16);                   \
            size_t  ga  = (size_t)(m0 + row) * DD + d0 + seg * 8;              \
            size_t  gb  = (size_t)(n0 + row) * DD + d0 + seg * 8;              \
            cpasync16(st + so,            Ahi + ga);                           \
            cpasync16(st + BUFB + so,     Alo + ga);                           \
            cpasync16(st + 2 * BUFB + so, Bhi + gb);                           \
        }                                                                      \
        cpcommit();                                                            \
    } while (0)

    ISSUE(0);
    ISSUE(1);

    for (int ch = 0; ch < 16; ch++) {
        if (ch < 15) cpwait<1>(); else cpwait<0>();
        __syncthreads();
        if (ch + 2 < 16) ISSUE(ch + 2);   // overwrites stage read 2 iters ago

        const uint32_t st = sb0 + (ch % NSTG) * STGB;
#pragma unroll
        for (int kk = 0; kk < 2; kk++) {
            const uint32_t ko = kk * 32;
            uint32_t bH[2][4];
#pragma unroll
            for (int nn = 0; nn < 2; nn++) {
                uint32_t bd = st + 2 * BUFB + (uint32_t)((wn + nn * 16) * ROWB) + ko + lmo;
                LDMX4(bH[nn], bd);
            }
#pragma unroll
            for (int mi = 0; mi < 4; mi++) {
                uint32_t aH[4], aL[4];
                uint32_t ad = st + (uint32_t)((wm + mi * 16) * ROWB) + ko + lmo;
                LDMX4(aH, ad);
                LDMX4(aL, ad + BUFB);
#pragma unroll
                for (int ni = 0; ni < 4; ni++) {
                    const int nn = ni >> 1, sel = ni & 1;
                    mma16(acc[mi][ni], aH, bH[nn][sel], bH[nn][sel + 2]);
                    mma16(acc[mi][ni], aL, bH[nn][sel], bH[nn][sel + 2]);
                }
            }
        }
    }

    // epilogue
    const float bv = bias[0];
#pragma unroll
    for (int mi = 0; mi < 4; mi++) {
#pragma unroll
        for (int h2 = 0; h2 < 2; h2++) {
            const int row = m0 + wm + mi * 16 + g + 8 * h2;
            const int b   = row >> 9;
            const int s   = row & 511;
#pragma unroll
            for (int ni = 0; ni < 4; ni++) {
                const int col0 = n0 + wn + ni * 8 + 2 * t4;
                float v0 = acc[mi][ni][2 * h2]     + bv;
                float v1 = acc[mi][ni][2 * h2 + 1] + bv;
                if (mat == 0) {
                    v0 *= QSCL; v1 *= QSCL;
                    size_t a = ((size_t)(b * HH + (col0 >> 6)) * SS + s) * DKK
                               + (col0 & 63);
                    uint32_t lo;
                    uint32_t hi = split_hi(v0, v1, lo);
                    *(uint32_t*)(g_Qhi + a) = hi;
                    *(uint32_t*)(g_Qlo + a) = lo;
                } else if (mat == 1) {
                    size_t a = ((size_t)(b * HH + (col0 >> 6)) * SS + s) * DKK
                               + (col0 & 63);
                    *(uint32_t*)(g_Khi + a) =
                        pack2(__float2half_rn(v0), __float2half_rn(v1));
                } else if (mat == 2) {
                    size_t a = ((size_t)(b * HH + (col0 >> 6)) * DKK + (col0 & 63)) * SS + s;
                    g_Vthi[a]      = __float2half_rn(v0);
                    g_Vthi[a + SS] = __float2half_rn(v1);
                } else {
                    *(float2*)(outp + (size_t)row * DD + col0) = make_float2(v0, v1);
                }
            }
        }
    }
#undef ISSUE
}

// ---------------------------------------------------------------------------
// Flash attention, fp16 2-term (Q/P carry residuals; K/V hi only).
// Pipelined: K(kt+1) issued after scores(kt); V double-buffered.
// grid (S/64, B*H), block 256 (8 warps: 2m x 4n).
// ---------------------------------------------------------------------------
#define QROWB 144                 // 128B row + 16 pad (conflict-free ldmatrix)
#define PROWB 272                 // 256B row + 16 pad
#define SQ_HI 0                   // 64*144 = 9216
#define SQ_LO 9216
#define SK    18432               // 128*144 = 18432 (hi only, own buffer)
#define SP_HI 36864               // 64*272 = 17408
#define SP_LO 54272
#define SV0   71680               // 2 x 17408 (double buffer)
#define SVSZ  17408
#define SRED  106496
#define SRED2 107520
#define SMEM_ATTN 108544

__global__ __launch_bounds__(256, 2)
void attn_kernel(const int* __restrict__ mask) {
    extern __shared__ char smc[];
    const uint32_t sb = (uint32_t)__cvta_generic_to_shared(smc);
    float* redf  = (float*)(smc + SRED);
    float* redf2 = (float*)(smc + SRED2);

    const int q0 = blockIdx.x * 64;
    const int bh = blockIdx.y;
    const int b  = bh / HH;
    const int h  = bh % HH;

    const int tid  = threadIdx.x;
    const int wid  = tid >> 5;
    const int lane = tid & 31;
    const int wm2  = wid >> 2;          // 0/1: q 32-group
    const int wn2  = wid & 3;           // 0..3
    const int g    = lane >> 2;
    const int t4   = lane & 3;
    const int QR   = wm2 * 32;
    const int KNB  = wn2 * 32;          // key base within ktile (scores)

    const uint32_t lq = lane >> 3, lr = lane & 7;
    const uint32_t lmoQ = (lr + (lq & 1) * 8) * QROWB + (lq >> 1) * 16;
    const uint32_t lmoP = (lr + (lq & 1) * 8) * PROWB + (lq >> 1) * 16;

    // Issue Q (hi+lo) — group 1
    {
        int row = tid >> 2;
        int s0  = (tid & 3) * 2;
        size_t   ga = ((size_t)bh * SS + q0 + row) * DKK;
        uint32_t so = sb + (uint32_t)(row * QROWB);
#pragma unroll
        for (int j = 0; j < 2; j++) {
            cpasync16(so + SQ_HI + (s0 + j) * 16, g_Qhi + ga + (s0 + j) * 8);
            cpasync16(so + SQ_LO + (s0 + j) * 16, g_Qlo + ga + (s0 + j) * 8);
        }
        cpcommit();
    }
    // Issue K(0) — group 2
    {
        int row = tid >> 1;
        int sN  = (tid & 1) * 4;
        size_t   ga = ((size_t)bh * SS + row) * DKK;
        uint32_t so = sb + (uint32_t)(row * QROWB);
#pragma unroll
        for (int j = 0; j < 4; j++)
            cpasync16(so + SK + (sN + j) * 16, g_Khi + ga + (sN + j) * 8);
        cpcommit();
    }
    // Issue V(0) -> SV0 — group 3
    {
        int row = tid >> 2;
        int sN  = (tid & 3) * 4;
        size_t   ga = ((size_t)bh * DKK + row) * SS;
        uint32_t so = sb + (uint32_t)(row * PROWB);
#pragma unroll
        for (int j = 0; j < 4; j++)
            cpasync16(so + SV0 + (sN + j) * 16, g_Vthi + ga + (sN + j) * 8);
        cpcommit();
    }

    float acc_o[2][2][4] = {};          // [mi][ni2][c]
    float li[2][2] = {};                // per-warp PARTIAL (own key slice)
    float mx[2][2] = {{-1e30f, -1e30f}, {-1e30f, -1e30f}};

    for (int kt = 0; kt < 4; kt++) {
        cpwait<1>();                    // K(kt) [+Q] complete; V(kt) may pend
        __syncthreads();                // also: all warps done with prev PV/P

        // ---- scores: 32q x 32k per warp, 2 passes ----
        float s4[2][4][4] = {};
#pragma unroll
        for (int ks = 0; ks < 4; ks++) {
            uint32_t aH[2][4], aL[2][4], bH[2][4];
#pragma unroll
            for (int mi = 0; mi < 2; mi++) {
                uint32_t ad = sb + (uint32_t)((QR + mi * 16) * QROWB) + ks * 32 + lmoQ;
                LDMX4(aH[mi], ad + SQ_HI);
                LDMX4(aL[mi], ad + SQ_LO);
            }
#pragma unroll
            for (int nn = 0; nn < 2; nn++) {
                uint32_t bd = sb + (uint32_t)((KNB + nn * 16) * QROWB) + ks * 32 + lmoQ;
                LDMX4(bH[nn], bd + SK);
            }
#pragma unroll
            for (int mi = 0; mi < 2; mi++)
#pragma unroll
                for (int ni = 0; ni < 4; ni++) {
                    const int nn = ni >> 1, sel = ni & 1;
                    mma16(s4[mi][ni], aH[mi], bH[nn][sel], bH[nn][sel + 2]);
                    mma16(s4[mi][ni], aL[mi], bH[nn][sel], bH[nn][sel + 2]);
                }
        }

        // ---- mask (pure select) ----
        int2 mk[4];
#pragma unroll
        for (int ni = 0; ni < 4; ni++)
            mk[ni] = *(const int2*)(mask + b * SS + kt * 128 + KNB + ni * 8 + 2 * t4);
#pragma unroll
        for (int mi = 0; mi < 2; mi++)
#pragma unroll
            for (int ni = 0; ni < 4; ni++) {
                s4[mi][ni][0] = mk[ni].x ? s4[mi][ni][0] : -1e30f;
                s4[mi][ni][1] = mk[ni].y ? s4[mi][ni][1] : -1e30f;
                s4[mi][ni][2] = mk[ni].x ? s4[mi][ni][2] : -1e30f;
                s4[mi][ni][3] = mk[ni].y ? s4[mi][ni][3] : -1e30f;
            }

        // ---- local row max -> smem ----
#pragma unroll
        for (int mi = 0; mi < 2; mi++)
#pragma unroll
            for (int half = 0; half < 2; half++) {
                float m = -1e30f;
#pragma unroll
                for (int ni = 0; ni < 4; ni++)
                    m = fmaxf(m, fmaxf(s4[mi][ni][half * 2], s4[mi][ni][half * 2 + 1]));
                m = fmaxf(m, __shfl_xor_sync(0xffffffffu, m, 1));
                m = fmaxf(m, __shfl_xor_sync(0xffffffffu, m, 2));
                if (t4 == 0)
                    redf[(wm2 * 4 + wn2) * 32 + mi * 16 + g + 8 * half] = m;
            }
        __syncthreads();                // scores done: SK free from here

        // ---- prefetch K(kt+1) into SK (overlaps softmax + PV) ----
        if (kt < 3) {
            int row = tid >> 1;
            int sN  = (tid & 1) * 4;
            size_t   ga = ((size_t)bh * SS + (kt + 1) * 128 + row) * DKK;
            uint32_t so = sb + (uint32_t)(row * QROWB);
#pragma unroll
            for (int j = 0; j < 4; j++)
                cpasync16(so + SK + (sN + j) * 16, g_Khi + ga + (sN + j) * 8);
            cpcommit();
        }

        // ---- global max, rescale O + partial li, p=exp2, write P ----
        float mnew[2][2], lsum[2][2] = {};
#pragma unroll
        for (int mi = 0; mi < 2; mi++)
#pragma unroll
            for (int half = 0; half < 2; half++) {
                const int rl = mi * 16 + g + 8 * half;
                float gm = fmaxf(fmaxf(redf[(wm2 * 4 + 0) * 32 + rl],
                                       redf[(wm2 * 4 + 1) * 32 + rl]),
                                 fmaxf(redf[(wm2 * 4 + 2) * 32 + rl],
                                       redf[(wm2 * 4 + 3) * 32 + rl]));
                float mn = fmaxf(mx[mi][half], gm);
                float al = exp2f(mx[mi][half] - mn);
                mx[mi][half] = mn;
                mnew[mi][half] = mn;
                li[mi][half] *= al;
#pragma unroll
                for (int ni2 = 0; ni2 < 2; ni2++) {
                    acc_o[mi][ni2][half * 2]     *= al;
                    acc_o[mi][ni2][half * 2 + 1] *= al;
                }
            }
#pragma unroll
        for (int mi = 0; mi < 2; mi++)
#pragma unroll
            for (int ni = 0; ni < 4; ni++) {
                float p0 = exp2f(s4[mi][ni][0] - mnew[mi][0]);
                float p1 = exp2f(s4[mi][ni][1] - mnew[mi][0]);
                float p2 = exp2f(s4[mi][ni][2] - mnew[mi][1]);
                float p3 = exp2f(s4[mi][ni][3] - mnew[mi][1]);
                lsum[mi][0] += p0 + p1;
                lsum[mi][1] += p2 + p3;
                uint32_t lo0, lo1;
                uint32_t hi0 = split_hi(p0, p1, lo0);
                uint32_t hi1 = split_hi(p2, p3, lo1);
                const uint32_t cb = (uint32_t)((KNB + ni * 8 + 2 * t4) * 2);
                const uint32_t r0 = (uint32_t)((QR + mi * 16 + g) * PROWB) + cb;
                *(uint32_t*)(smc + SP_HI + r0)               = hi0;
                *(uint32_t*)(smc + SP_LO + r0)               = lo0;
                *(uint32_t*)(smc + SP_HI + r0 + 8 * PROWB)   = hi1;
                *(uint32_t*)(smc + SP_LO + r0 + 8 * PROWB)   = lo1;
            }
        // partial li over this warp's 32-key slice
#pragma unroll
        for (int mi = 0; mi < 2; mi++)
#pragma unroll
            for (int half = 0; half < 2; half++) {
                float sgl = lsum[mi][half];
                sgl += __shfl_xor_sync(0xffffffffu, sgl, 1);
                sgl += __shfl_xor_sync(0xffffffffu, sgl, 2);
                li[mi][half] += sgl;
            }

        if (kt < 3) cpwait<1>();        // V(kt) done (K(kt+1) may pend)
        else        cpwait<0>();
        __syncthreads();                // V + P visible to all

        // ---- prefetch V(kt+1) into the other V buffer ----
        if (kt < 3) {
            int row = tid >> 2;
            int sN  = (tid & 3) * 4;
            size_t   ga = ((size_t)bh * DKK + row) * SS + (kt + 1) * 128;
            uint32_t so = sb + (uint32_t)(row * PROWB) + SV0 + ((kt + 1) & 1) * SVSZ;
#pragma unroll
            for (int j = 0; j < 4; j++)
                cpasync16(so + (sN + j) * 16, g_Vthi + ga + (sN + j) * 8);
            cpcommit();
        }

        // ---- PV: 32q x 16v per warp, k = 128 keys, 2 passes ----
        const uint32_t svb = (uint32_t)(SV0 + (kt & 1) * SVSZ);
#pragma unroll
        for (int ks = 0; ks < 8; ks++) {
            uint32_t pH[2][4], pL[2][4], vH[4];
#pragma unroll
            for (int mi = 0; mi < 2; mi++) {
                uint32_t pd = sb + (uint32_t)((QR + mi * 16) * PROWB) + ks * 32 + lmoP;
                LDMX4(pH[mi], pd + SP_HI);
                LDMX4(pL[mi], pd + SP_LO);
            }
            uint32_t vd = sb + (uint32_t)((wn2 * 16) * PROWB) + ks * 32 + lmoP + svb;
            LDMX4(vH, vd);
#pragma unroll
            for (int mi = 0; mi < 2; mi++)
#pragma unroll
                for (int ni2 = 0; ni2 < 2; ni2++) {
                    mma16(acc_o[mi][ni2], pH[mi], vH[ni2], vH[ni2 + 2]);
                    mma16(acc_o[mi][ni2], pL[mi], vH[ni2], vH[ni2 + 2]);
                }
        }
    }

    // ---- final li reduction across the 4 wn2 warps ----
#pragma unroll
    for (int mi = 0; mi < 2; mi++)
#pragma unroll
        for (int half = 0; half < 2; half++)
            if (t4 == 0)
                redf2[(wm2 * 4 + wn2) * 32 + mi * 16 + g + 8 * half] = li[mi][half];
    __syncthreads();
#pragma unroll
    for (int mi = 0; mi < 2; mi++)
#pragma unroll
        for (int half = 0; half < 2; half++) {
            const int rl = mi * 16 + g + 8 * half;
            li[mi][half] = redf2[(wm2 * 4 + 0) * 32 + rl]
                         + redf2[(wm2 * 4 + 1) * 32 + rl]
                         + redf2[(wm2 * 4 + 2) * 32 + rl]
                         + redf2[(wm2 * 4 + 3) * 32 + rl];
        }

    // ---- finalize: heads (concat layout) as fp16 hi/lo ----
#pragma unroll
    for (int mi = 0; mi < 2; mi++)
#pragma unroll
        for (int half = 0; half < 2; half++) {
            const float inv = 1.0f / li[mi][half];
            const int tok = q0 + QR + mi * 16 + g + 8 * half;
#pragma unroll
            for (int ni2 = 0; ni2 < 2; ni2++) {
                const int col = wn2 * 16 + ni2 * 8 + 2 * t4;
                float v0 = acc_o[mi][ni2][half * 2]     * inv;
                float v1 = acc_o[mi][ni2][half * 2 + 1] * inv;
                uint32_t lo;
                uint32_t hi = split_hi(v0, v1, lo);
                size_t a = ((size_t)b * SS + tok) * DD + h * DKK + col;
                *(uint32_t*)(g_hhi + a) = hi;
                *(uint32_t*)(g_hlo + a) = lo;
            }
        }
}

// ---------------------------------------------------------------------------
extern "C" void kernel_launch(void* const* d_in, const int* in_sizes, int n_in,
                              void* d_out, int out_size) {
    const float* x    = (const float*)d_in[0];
    const int*   mask = (const int*)  d_in[1];
    const float* Wq   = (const float*)d_in[2];
    const float* Wk   = (const float*)d_in[3];
    const float* Wv   = (const float*)d_in[4];
    const float* Wo   = (const float*)d_in[5];
    const float* bias = (const float*)d_in[6];
    float* out = (float*)d_out;

    // 0) weight transpose + fp16 quantize; x fp16 hi/lo split
    prepw_kernel<<<dim3(8, 8, 4), 256>>>(Wq, Wk, Wv, Wo);
    prepx_kernel<<<MM * DD / 4 / 256, 256>>>(x);

    // 1) QKV projections (fp16 2-term mma.sync, 3-stage pipeline)
    cudaFuncSetAttribute(mma_gemm_kernel,
                         cudaFuncAttributeMaxDynamicSharedMemorySize, SMEM_GEMM);
    mma_gemm_kernel<<<dim3(MM / 128, 4, 3), 256, SMEM_GEMM>>>(0, bias, out);

    // 2) fused masked-softmax attention (flash, fp16 mma.sync, pipelined K/V)
    cudaFuncSetAttribute(attn_kernel,
                         cudaFuncAttributeMaxDynamicSharedMemorySize, SMEM_ATTN);
    attn_kernel<<<dim3(SS / 64, BB * HH), 256, SMEM_ATTN>>>(mask);

    // 3) output projection (fp16 2-term mma.sync)
    mma_gemm_kernel<<<dim3(MM / 128, 4, 1), 256, SMEM_GEMM>>>(3, bias, out);
}

// round 16
// speedup vs baseline: 3.1121x; 1.0143x over previous
#include <cuda_runtime.h>
#include <cuda_fp16.h>
#include <cstdint>

#define BB  32
#define SS  512
#define DD  512
#define HH  8
#define DKK 64
#define MM  (BB*SS)   // 16384

typedef __half fp16;

// Q pre-scale: 1/sqrt(64) * log2(e)  (scores land in log2 domain)
#define QSCL (0.125f * 1.4426950408889634f)

// Scratch (device globals; no runtime allocation allowed)
__device__ fp16 g_Qhi[(size_t)BB*HH*SS*DKK];  // [bh][s][dk] (pre-scaled)
__device__ fp16 g_Qlo[(size_t)BB*HH*SS*DKK];
__device__ fp16 g_Khi[(size_t)BB*HH*SS*DKK];  // [bh][s][dk] (hi only)
__device__ fp16 g_Vthi[(size_t)BB*HH*DKK*SS]; // [bh][dk][s] (hi only)
__device__ fp16 g_xhi[(size_t)MM*DD];         // x split hi
__device__ fp16 g_xlo[(size_t)MM*DD];
__device__ fp16 g_hhi[(size_t)MM*DD];         // heads split hi (concat layout)
__device__ fp16 g_hlo[(size_t)MM*DD];
__device__ fp16 g_Whi[(size_t)4*DD*DD];       // [mat][n][k] (hi only)

// ===================== PTX helpers =====================
__device__ __forceinline__ void cpasync16(uint32_t s, const void* g) {
    asm volatile("cp.async.cg.shared.global [%0], [%1], 16;" :: "r"(s), "l"(g));
}
__device__ __forceinline__ void cpcommit() {
    asm volatile("cp.async.commit_group;" ::: "memory");
}
template <int N> __device__ __forceinline__ void cpwait() {
    asm volatile("cp.async.wait_group %0;" :: "n"(N) : "memory");
}
#define LDMX4(r, a)                                                            \
    asm volatile("ldmatrix.sync.aligned.m8n8.x4.shared.b16 {%0,%1,%2,%3}, [%4];" \
        : "=r"((r)[0]), "=r"((r)[1]), "=r"((r)[2]), "=r"((r)[3]) : "r"(a))

__device__ __forceinline__ void mma16(float* c, const uint32_t* a,
                                      uint32_t b0, uint32_t b1) {
    asm volatile(
        "mma.sync.aligned.m16n8k16.row.col.f32.f16.f16.f32 "
        "{%0,%1,%2,%3},{%4,%5,%6,%7},{%8,%9},{%0,%1,%2,%3};"
        : "+f"(c[0]), "+f"(c[1]), "+f"(c[2]), "+f"(c[3])
        : "r"(a[0]), "r"(a[1]), "r"(a[2]), "r"(a[3]), "r"(b0), "r"(b1));
}

// Packed hi/lo split: cvt.rn.f16x2.f32 — bit-identical to scalar rounding.
__device__ __forceinline__ uint32_t split_hi(float v0, float v1, uint32_t& lo) {
    __half2 h = __floats2half2_rn(v0, v1);
    float2 hf = __half22float2(h);
    __half2 l = __floats2half2_rn(v0 - hf.x, v1 - hf.y);
    lo = *(uint32_t*)&l;
    return *(uint32_t*)&h;
}

// ---------------------------------------------------------------------------
// Prep W: transpose weights into [mat][n][k], quantize to fp16 (hi only).
// ---------------------------------------------------------------------------
__global__ void prepw_kernel(const float* __restrict__ Wq,
                             const float* __restrict__ Wk,
                             const float* __restrict__ Wv,
                             const float* __restrict__ Wo) {
    __shared__ float t[64][65];
    const int z  = blockIdx.z;
    const int y  = blockIdx.y;
    const int xt = blockIdx.x;
    const float* W = (z == 0) ? Wq : (z == 1) ? Wk : (z == 2) ? Wv : Wo;
    const int tid = threadIdx.x;

#pragma unroll
    for (int i = 0; i < 4; i++) {
        int idx = tid + i * 256;
        int r   = idx >> 4;
        int c4  = (idx & 15) * 4;
        const float* p = (z < 3)
            ? W + (size_t)y * DD * DKK + (size_t)(xt * 64 + r) * DKK + c4
            : W + (size_t)(xt * 64 + r) * DD + y * 64 + c4;
        float4 v = *(const float4*)p;
        t[c4 + 0][r] = v.x; t[c4 + 1][r] = v.y;
        t[c4 + 2][r] = v.z; t[c4 + 3][r] = v.w;
    }
    __syncthreads();

    fp16* oh = g_Whi + (size_t)z * DD * DD;
#pragma unroll
    for (int i = 0; i < 4; i++) {
        int idx = tid + i * 256;
        int c   = idx >> 4;
        int r4  = (idx & 15) * 4;
        size_t o = (size_t)(y * 64 + c) * DD + xt * 64 + r4;
        uint2 uh;
        __half2 a = __floats2half2_rn(t[c][r4],     t[c][r4 + 1]);
        __half2 b = __floats2half2_rn(t[c][r4 + 2], t[c][r4 + 3]);
        uh.x = *(uint32_t*)&a;
        uh.y = *(uint32_t*)&b;
        *(uint2*)(oh + o) = uh;
    }
}

// ---------------------------------------------------------------------------
// Prep X: split x into fp16 hi/lo, row-major.
// ---------------------------------------------------------------------------
__global__ void prepx_kernel(const float* __restrict__ x) {
    const size_t i4 = (size_t)blockIdx.x * 256 + threadIdx.x;
    float4 v = ((const float4*)x)[i4];
    uint2 uh, ul;
    uh.x = split_hi(v.x, v.y, ul.x);
    uh.y = split_hi(v.z, v.w, ul.y);
    *(uint2*)(g_xhi + i4 * 4) = uh;
    *(uint2*)(g_xlo + i4 * 4) = ul;
}

// ---------------------------------------------------------------------------
// fp16 2-term split GEMM (A = hi+lo, B = hi only), 3-stage cp.async,
// ONE __syncthreads per chunk. Block tile 128x128, K=512 in chunks of 32.
// mat 0 -> Q (scaled, 2-part), 1 -> K (hi), 2 -> Vt (hi), 3 -> out fp32.
// ---------------------------------------------------------------------------
#define ROWB 80
#define BUFB (128 * ROWB)
#define STGB (3 * BUFB)             // Ah, Al, Bh = 30720
#define NSTG 3
#define SMEM_GEMM (NSTG * STGB)     // 92160

__global__ __launch_bounds__(256, 2)
void mma_gemm_kernel(int matBase, const float* __restrict__ bias,
                     float* __restrict__ outp) {
    extern __shared__ char smc[];
    const uint32_t sb0 = (uint32_t)__cvta_generic_to_shared(smc);

    const int mat = matBase + blockIdx.z;
    const int m0  = blockIdx.x * 128;
    const int n0  = blockIdx.y * 128;
    const fp16* Ahi = (mat >= 3) ? g_hhi : g_xhi;
    const fp16* Alo = (mat >= 3) ? g_hlo : g_xlo;
    const fp16* Bhi = g_Whi + (size_t)mat * DD * DD;

    const int tid  = threadIdx.x;
    const int wid  = tid >> 5;
    const int lane = tid & 31;
    const int wm   = (wid >> 2) * 64;
    const int wn   = (wid & 3) * 32;
    const int g    = lane >> 2;
    const int t4   = lane & 3;

    const uint32_t lq  = lane >> 3;
    const uint32_t lr  = lane & 7;
    const uint32_t lmo = (lr + (lq & 1) * 8) * ROWB + (lq >> 1) * 16;

    float acc[4][4][4] = {};

#define ISSUE(ch) do {                                                         \
        const int d0 = (ch) * 32;                                              \
        const uint32_t st = sb0 + ((ch) % NSTG) * STGB;                        \
        _Pragma("unroll")                                                      \
        for (int t = 0; t < 2; t++) {                                          \
            int idx = tid + 256 * t;                                           \
            int row = idx >> 2;                                                \
            int seg = idx & 3;                                                 \
            uint32_t so = (uint32_t)(row * ROWB + seg * 16);                   \
            size_t  ga  = (size_t)(m0 + row) * DD + d0 + seg * 8;              \
            size_t  gb  = (size_t)(n0 + row) * DD + d0 + seg * 8;              \
            cpasync16(st + so,            Ahi + ga);                           \
            cpasync16(st + BUFB + so,     Alo + ga);                           \
            cpasync16(st + 2 * BUFB + so, Bhi + gb);                           \
        }                                                                      \
        cpcommit();                                                            \
    } while (0)

    ISSUE(0);
    ISSUE(1);

    for (int ch = 0; ch < 16; ch++) {
        if (ch < 15) cpwait<1>(); else cpwait<0>();
        __syncthreads();
        if (ch + 2 < 16) ISSUE(ch + 2);   // overwrites stage read 2 iters ago

        const uint32_t st = sb0 + (ch % NSTG) * STGB;
#pragma unroll
        for (int kk = 0; kk < 2; kk++) {
            const uint32_t ko = kk * 32;
            uint32_t bH[2][4];
#pragma unroll
            for (int nn = 0; nn < 2; nn++) {
                uint32_t bd = st + 2 * BUFB + (uint32_t)((wn + nn * 16) * ROWB) + ko + lmo;
                LDMX4(bH[nn], bd);
            }
#pragma unroll
            for (int mi = 0; mi < 4; mi++) {
                uint32_t aH[4], aL[4];
                uint32_t ad = st + (uint32_t)((wm + mi * 16) * ROWB) + ko + lmo;
                LDMX4(aH, ad);
                LDMX4(aL, ad + BUFB);
#pragma unroll
                for (int ni = 0; ni < 4; ni++) {
                    const int nn = ni >> 1, sel = ni & 1;
                    mma16(acc[mi][ni], aH, bH[nn][sel], bH[nn][sel + 2]);
                    mma16(acc[mi][ni], aL, bH[nn][sel], bH[nn][sel + 2]);
                }
            }
        }
    }

    // epilogue
    const float bv = bias[0];
#pragma unroll
    for (int mi = 0; mi < 4; mi++) {
#pragma unroll
        for (int h2 = 0; h2 < 2; h2++) {
            const int row = m0 + wm + mi * 16 + g + 8 * h2;
            const int b   = row >> 9;
            const int s   = row & 511;
#pragma unroll
            for (int ni = 0; ni < 4; ni++) {
                const int col0 = n0 + wn + ni * 8 + 2 * t4;
                float v0 = acc[mi][ni][2 * h2]     + bv;
                float v1 = acc[mi][ni][2 * h2 + 1] + bv;
                if (mat == 0) {
                    v0 *= QSCL; v1 *= QSCL;
                    size_t a = ((size_t)(b * HH + (col0 >> 6)) * SS + s) * DKK
                               + (col0 & 63);
                    uint32_t lo;
                    uint32_t hi = split_hi(v0, v1, lo);
                    *(uint32_t*)(g_Qhi + a) = hi;
                    *(uint32_t*)(g_Qlo + a) = lo;
                } else if (mat == 1) {
                    size_t a = ((size_t)(b * HH + (col0 >> 6)) * SS + s) * DKK
                               + (col0 & 63);
                    __half2 hv = __floats2half2_rn(v0, v1);
                    *(uint32_t*)(g_Khi + a) = *(uint32_t*)&hv;
                } else if (mat == 2) {
                    size_t a = ((size_t)(b * HH + (col0 >> 6)) * DKK + (col0 & 63)) * SS + s;
                    g_Vthi[a]      = __float2half_rn(v0);
                    g_Vthi[a + SS] = __float2half_rn(v1);
                } else {
                    *(float2*)(outp + (size_t)row * DD + col0) = make_float2(v0, v1);
                }
            }
        }
    }
#undef ISSUE
}

// ---------------------------------------------------------------------------
// Flash attention, fp16 2-term (Q/P carry residuals; K/V hi only).
// Pipelined: K(kt+1) issued after scores(kt); V double-buffered.
// 3 barriers per key tile — the loop-top barrier is the cp.async
// cross-thread visibility fence for SK/SQ (removal => NaN, round 13).
// grid (S/64, B*H), block 256 (8 warps: 2m x 4n).
// ---------------------------------------------------------------------------
#define QROWB 144                 // 128B row + 16 pad (conflict-free ldmatrix)
#define PROWB 272                 // 256B row + 16 pad
#define SQ_HI 0                   // 64*144 = 9216
#define SQ_LO 9216
#define SK    18432               // 128*144 = 18432 (hi only, own buffer)
#define SP_HI 36864               // 64*272 = 17408
#define SP_LO 54272
#define SV0   71680               // 2 x 17408 (double buffer)
#define SVSZ  17408
#define SRED  106496
#define SRED2 107520
#define SMEM_ATTN 108544

__global__ __launch_bounds__(256, 2)
void attn_kernel(const int* __restrict__ mask) {
    extern __shared__ char smc[];
    const uint32_t sb = (uint32_t)__cvta_generic_to_shared(smc);
    float* redf  = (float*)(smc + SRED);
    float* redf2 = (float*)(smc + SRED2);

    const int q0 = blockIdx.x * 64;
    const int bh = blockIdx.y;
    const int b  = bh / HH;
    const int h  = bh % HH;

    const int tid  = threadIdx.x;
    const int wid  = tid >> 5;
    const int lane = tid & 31;
    const int wm2  = wid >> 2;          // 0/1: q 32-group
    const int wn2  = wid & 3;           // 0..3
    const int g    = lane >> 2;
    const int t4   = lane & 3;
    const int QR   = wm2 * 32;
    const int KNB  = wn2 * 32;          // key base within ktile (scores)

    const uint32_t lq = lane >> 3, lr = lane & 7;
    const uint32_t lmoQ = (lr + (lq & 1) * 8) * QROWB + (lq >> 1) * 16;
    const uint32_t lmoP = (lr + (lq & 1) * 8) * PROWB + (lq >> 1) * 16;

    // Issue Q (hi+lo) — group 1
    {
        int row = tid >> 2;
        int s0  = (tid & 3) * 2;
        size_t   ga = ((size_t)bh * SS + q0 + row) * DKK;
        uint32_t so = sb + (uint32_t)(row * QROWB);
#pragma unroll
        for (int j = 0; j < 2; j++) {
            cpasync16(so + SQ_HI + (s0 + j) * 16, g_Qhi + ga + (s0 + j) * 8);
            cpasync16(so + SQ_LO + (s0 + j) * 16, g_Qlo + ga + (s0 + j) * 8);
        }
        cpcommit();
    }
    // Issue K(0) — group 2
    {
        int row = tid >> 1;
        int sN  = (tid & 1) * 4;
        size_t   ga = ((size_t)bh * SS + row) * DKK;
        uint32_t so = sb + (uint32_t)(row * QROWB);
#pragma unroll
        for (int j = 0; j < 4; j++)
            cpasync16(so + SK + (sN + j) * 16, g_Khi + ga + (sN + j) * 8);
        cpcommit();
    }
    // Issue V(0) -> SV0 — group 3
    {
        int row = tid >> 2;
        int sN  = (tid & 3) * 4;
        size_t   ga = ((size_t)bh * DKK + row) * SS;
        uint32_t so = sb + (uint32_t)(row * PROWB);
#pragma unroll
        for (int j = 0; j < 4; j++)
            cpasync16(so + SV0 + (sN + j) * 16, g_Vthi + ga + (sN + j) * 8);
        cpcommit();
    }

    float acc_o[2][2][4] = {};          // [mi][ni2][c]
    float li[2][2] = {};                // per-warp PARTIAL (own key slice)
    float mx[2][2] = {{-1e30f, -1e30f}, {-1e30f, -1e30f}};

    for (int kt = 0; kt < 4; kt++) {
        cpwait<1>();                    // K(kt) [+Q] complete; V(kt) may pend
        __syncthreads();                // cp.async cross-thread visibility fence

        // ---- mask load hoisted: overlaps the scores mma phase ----
        int2 mk[4];
#pragma unroll
        for (int ni = 0; ni < 4; ni++)
            mk[ni] = *(const int2*)(mask + b * SS + kt * 128 + KNB + ni * 8 + 2 * t4);

        // ---- scores: 32q x 32k per warp, 2 passes ----
        float s4[2][4][4] = {};
#pragma unroll
        for (int ks = 0; ks < 4; ks++) {
            uint32_t aH[2][4], aL[2][4], bH[2][4];
#pragma unroll
            for (int mi = 0; mi < 2; mi++) {
                uint32_t ad = sb + (uint32_t)((QR + mi * 16) * QROWB) + ks * 32 + lmoQ;
                LDMX4(aH[mi], ad + SQ_HI);
                LDMX4(aL[mi], ad + SQ_LO);
            }
#pragma unroll
            for (int nn = 0; nn < 2; nn++) {
                uint32_t bd = sb + (uint32_t)((KNB + nn * 16) * QROWB) + ks * 32 + lmoQ;
                LDMX4(bH[nn], bd + SK);
            }
#pragma unroll
            for (int mi = 0; mi < 2; mi++)
#pragma unroll
                for (int ni = 0; ni < 4; ni++) {
                    const int nn = ni >> 1, sel = ni & 1;
                    mma16(s4[mi][ni], aH[mi], bH[nn][sel], bH[nn][sel + 2]);
                    mma16(s4[mi][ni], aL[mi], bH[nn][sel], bH[nn][sel + 2]);
                }
        }

        // ---- mask (pure select) ----
#pragma unroll
        for (int mi = 0; mi < 2; mi++)
#pragma unroll
            for (int ni = 0; ni < 4; ni++) {
                s4[mi][ni][0] = mk[ni].x ? s4[mi][ni][0] : -1e30f;
                s4[mi][ni][1] = mk[ni].y ? s4[mi][ni][1] : -1e30f;
                s4[mi][ni][2] = mk[ni].x ? s4[mi][ni][2] : -1e30f;
                s4[mi][ni][3] = mk[ni].y ? s4[mi][ni][3] : -1e30f;
            }

        // ---- local row max -> smem ----
#pragma unroll
        for (int mi = 0; mi < 2; mi++)
#pragma unroll
            for (int half = 0; half < 2; half++) {
                float m = -1e30f;
#pragma unroll
                for (int ni = 0; ni < 4; ni++)
                    m = fmaxf(m, fmaxf(s4[mi][ni][half * 2], s4[mi][ni][half * 2 + 1]));
                m = fmaxf(m, __shfl_xor_sync(0xffffffffu, m, 1));
                m = fmaxf(m, __shfl_xor_sync(0xffffffffu, m, 2));
                if (t4 == 0)
                    redf[(wm2 * 4 + wn2) * 32 + mi * 16 + g + 8 * half] = m;
            }
        __syncthreads();                // barrier(1): maxes visible, SK free

        // ---- prefetch K(kt+1) into SK (overlaps softmax + PV) ----
        if (kt < 3) {
            int row = tid >> 1;
            int sN  = (tid & 1) * 4;
            size_t   ga = ((size_t)bh * SS + (kt + 1) * 128 + row) * DKK;
            uint32_t so = sb + (uint32_t)(row * QROWB);
#pragma unroll
            for (int j = 0; j < 4; j++)
                cpasync16(so + SK + (sN + j) * 16, g_Khi + ga + (sN + j) * 8);
            cpcommit();
        }

        // ---- global max, rescale O + partial li, p=exp2, write P ----
        float mnew[2][2], lsum[2][2] = {};
#pragma unroll
        for (int mi = 0; mi < 2; mi++)
#pragma unroll
            for (int half = 0; half < 2; half++) {
                const int rl = mi * 16 + g + 8 * half;
                float gm = fmaxf(fmaxf(redf[(wm2 * 4 + 0) * 32 + rl],
                                       redf[(wm2 * 4 + 1) * 32 + rl]),
                                 fmaxf(redf[(wm2 * 4 + 2) * 32 + rl],
                                       redf[(wm2 * 4 + 3) * 32 + rl]));
                float mn = fmaxf(mx[mi][half], gm);
                float al = exp2f(mx[mi][half] - mn);
                mx[mi][half] = mn;
                mnew[mi][half] = mn;
                li[mi][half] *= al;
#pragma unroll
                for (int ni2 = 0; ni2 < 2; ni2++) {
                    acc_o[mi][ni2][half * 2]     *= al;
                    acc_o[mi][ni2][half * 2 + 1] *= al;
                }
            }
#pragma unroll
        for (int mi = 0; mi < 2; mi++)
#pragma unroll
            for (int ni = 0; ni < 4; ni++) {
                float p0 = exp2f(s4[mi][ni][0] - mnew[mi][0]);
                float p1 = exp2f(s4[mi][ni][1] - mnew[mi][0]);
                float p2 = exp2f(s4[mi][ni][2] - mnew[mi][1]);
                float p3 = exp2f(s4[mi][ni][3] - mnew[mi][1]);
                lsum[mi][0] += p0 + p1;
                lsum[mi][1] += p2 + p3;
                uint32_t lo0, lo1;
                uint32_t hi0 = split_hi(p0, p1, lo0);
                uint32_t hi1 = split_hi(p2, p3, lo1);
                const uint32_t cb = (uint32_t)((KNB + ni * 8 + 2 * t4) * 2);
                const uint32_t r0 = (uint32_t)((QR + mi * 16 + g) * PROWB) + cb;
                *(uint32_t*)(smc + SP_HI + r0)               = hi0;
                *(uint32_t*)(smc + SP_LO + r0)               = lo0;
                *(uint32_t*)(smc + SP_HI + r0 + 8 * PROWB)   = hi1;
                *(uint32_t*)(smc + SP_LO + r0 + 8 * PROWB)   = lo1;
            }
        // partial li over this warp's 32-key slice
#pragma unroll
        for (int mi = 0; mi < 2; mi++)
#pragma unroll
            for (int half = 0; half < 2; half++) {
                float sgl = lsum[mi][half];
                sgl += __shfl_xor_sync(0xffffffffu, sgl, 1);
                sgl += __shfl_xor_sync(0xffffffffu, sgl, 2);
                li[mi][half] += sgl;
            }

        if (kt < 3) cpwait<1>();        // V(kt) done (K(kt+1) may pend)
        else        cpwait<0>();
        __syncthreads();                // barrier(2): V + P visible to all

        // ---- prefetch V(kt+1) into the other V buffer ----
        if (kt < 3) {
            int row = tid >> 2;
            int sN  = (tid & 3) * 4;
            size_t   ga = ((size_t)bh * DKK + row) * SS + (kt + 1) * 128;
            uint32_t so = sb + (uint32_t)(row * PROWB) + SV0 + ((kt + 1) & 1) * SVSZ;
#pragma unroll
            for (int j = 0; j < 4; j++)
                cpasync16(so + (sN + j) * 16, g_Vthi + ga + (sN + j) * 8);
            cpcommit();
        }

        // ---- PV: 32q x 16v per warp, k = 128 keys, 2 passes ----
        const uint32_t svb = (uint32_t)(SV0 + (kt & 1) * SVSZ);
#pragma unroll
        for (int ks = 0; ks < 8; ks++) {
            uint32_t pH[2][4], pL[2][4], vH[4];
#pragma unroll
            for (int mi = 0; mi < 2; mi++) {
                uint32_t pd = sb + (uint32_t)((QR + mi * 16) * PROWB) + ks * 32 + lmoP;
                LDMX4(pH[mi], pd + SP_HI);
                LDMX4(pL[mi], pd + SP_LO);
            }
            uint32_t vd = sb + (uint32_t)((wn2 * 16) * PROWB) + ks * 32 + lmoP + svb;
            LDMX4(vH, vd);
#pragma unroll
            for (int mi = 0; mi < 2; mi++)
#pragma unroll
                for (int ni2 = 0; ni2 < 2; ni2++) {
                    mma16(acc_o[mi][ni2], pH[mi], vH[ni2], vH[ni2 + 2]);
                    mma16(acc_o[mi][ni2], pL[mi], vH[ni2], vH[ni2 + 2]);
                }
        }
    }

    // ---- final li reduction across the 4 wn2 warps ----
#pragma unroll
    for (int mi = 0; mi < 2; mi++)
#pragma unroll
        for (int half = 0; half < 2; half++)
            if (t4 == 0)
                redf2[(wm2 * 4 + wn2) * 32 + mi * 16 + g + 8 * half] = li[mi][half];
    __syncthreads();
#pragma unroll
    for (int mi = 0; mi < 2; mi++)
#pragma unroll
        for (int half = 0; half < 2; half++) {
            const int rl = mi * 16 + g + 8 * half;
            li[mi][half] = redf2[(wm2 * 4 + 0) * 32 + rl]
                         + redf2[(wm2 * 4 + 1) * 32 + rl]
                         + redf2[(wm2 * 4 + 2) * 32 + rl]
                         + redf2[(wm2 * 4 + 3) * 32 + rl];
        }

    // ---- finalize: heads (concat layout) as fp16 hi/lo ----
#pragma unroll
    for (int mi = 0; mi < 2; mi++)
#pragma unroll
        for (int half = 0; half < 2; half++) {
            const float inv = 1.0f / li[mi][half];
            const int tok = q0 + QR + mi * 16 + g + 8 * half;
#pragma unroll
            for (int ni2 = 0; ni2 < 2; ni2++) {
                const int col = wn2 * 16 + ni2 * 8 + 2 * t4;
                float v0 = acc_o[mi][ni2][half * 2]     * inv;
                float v1 = acc_o[mi][ni2][half * 2 + 1] * inv;
                uint32_t lo;
                uint32_t hi = split_hi(v0, v1, lo);
                size_t a = ((size_t)b * SS + tok) * DD + h * DKK + col;
                *(uint32_t*)(g_hhi + a) = hi;
                *(uint32_t*)(g_hlo + a) = lo;
            }
        }
}

// ---------------------------------------------------------------------------
extern "C" void kernel_launch(void* const* d_in, const int* in_sizes, int n_in,
                              void* d_out, int out_size) {
    const float* x    = (const float*)d_in[0];
    const int*   mask = (const int*)  d_in[1];
    const float* Wq   = (const float*)d_in[2];
    const float* Wk   = (const float*)d_in[3];
    const float* Wv   = (const float*)d_in[4];
    const float* Wo   = (const float*)d_in[5];
    const float* bias = (const float*)d_in[6];
    float* out = (float*)d_out;

    // 0) weight transpose + fp16 quantize; x fp16 hi/lo split
    prepw_kernel<<<dim3(8, 8, 4), 256>>>(Wq, Wk, Wv, Wo);
    prepx_kernel<<<MM * DD / 4 / 256, 256>>>(x);

    // 1) QKV projections (fp16 2-term mma.sync, 3-stage pipeline)
    cudaFuncSetAttribute(mma_gemm_kernel,
                         cudaFuncAttributeMaxDynamicSharedMemorySize, SMEM_GEMM);
    mma_gemm_kernel<<<dim3(MM / 128, 4, 3), 256, SMEM_GEMM>>>(0, bias, out);

    // 2) fused masked-softmax attention (flash, fp16 mma.sync, pipelined K/V)
    cudaFuncSetAttribute(attn_kernel,
                         cudaFuncAttributeMaxDynamicSharedMemorySize, SMEM_ATTN);
    attn_kernel<<<dim3(SS / 64, BB * HH), 256, SMEM_ATTN>>>(mask);

    // 3) output projection (fp16 2-term mma.sync)
    mma_gemm_kernel<<<dim3(MM / 128, 4, 1), 256, SMEM_GEMM>>>(3, bias, out);
}

// round 17
// speedup vs baseline: 3.3325x; 1.0708x over previous
#include <cuda_runtime.h>
#include <cuda_fp16.h>
#include <cstdint>

#define BB  32
#define SS  512
#define DD  512
#define HH  8
#define DKK 64
#define MM  (BB*SS)   // 16384

typedef __half fp16;

// Q pre-scale: 1/sqrt(64) * log2(e)  (scores land in log2 domain)
#define QSCL (0.125f * 1.4426950408889634f)

// Scratch (device globals; no runtime allocation allowed)
__device__ fp16 g_Qhi[(size_t)BB*HH*SS*DKK];  // [bh][s][dk] (pre-scaled)
__device__ fp16 g_Qlo[(size_t)BB*HH*SS*DKK];
__device__ fp16 g_Khi[(size_t)BB*HH*SS*DKK];  // [bh][s][dk] (hi only)
__device__ fp16 g_Vthi[(size_t)BB*HH*DKK*SS]; // [bh][dk][s] (hi only)
__device__ fp16 g_xhi[(size_t)MM*DD];         // x split hi
__device__ fp16 g_xlo[(size_t)MM*DD];
__device__ fp16 g_hhi[(size_t)MM*DD];         // heads split hi (concat layout)
__device__ fp16 g_hlo[(size_t)MM*DD];
__device__ fp16 g_Whi[(size_t)4*DD*DD];       // [mat][n][k] (hi only)

// ===================== PTX helpers =====================
__device__ __forceinline__ void cpasync16(uint32_t s, const void* g) {
    asm volatile("cp.async.cg.shared.global [%0], [%1], 16;" :: "r"(s), "l"(g));
}
__device__ __forceinline__ void cpcommit() {
    asm volatile("cp.async.commit_group;" ::: "memory");
}
template <int N> __device__ __forceinline__ void cpwait() {
    asm volatile("cp.async.wait_group %0;" :: "n"(N) : "memory");
}
#define LDMX4(r, a)                                                            \
    asm volatile("ldmatrix.sync.aligned.m8n8.x4.shared.b16 {%0,%1,%2,%3}, [%4];" \
        : "=r"((r)[0]), "=r"((r)[1]), "=r"((r)[2]), "=r"((r)[3]) : "r"(a))

__device__ __forceinline__ void mma16(float* c, const uint32_t* a,
                                      uint32_t b0, uint32_t b1) {
    asm volatile(
        "mma.sync.aligned.m16n8k16.row.col.f32.f16.f16.f32 "
        "{%0,%1,%2,%3},{%4,%5,%6,%7},{%8,%9},{%0,%1,%2,%3};"
        : "+f"(c[0]), "+f"(c[1]), "+f"(c[2]), "+f"(c[3])
        : "r"(a[0]), "r"(a[1]), "r"(a[2]), "r"(a[3]), "r"(b0), "r"(b1));
}

// Packed hi/lo split: cvt.rn.f16x2.f32 — bit-identical to scalar rounding.
__device__ __forceinline__ uint32_t split_hi(float v0, float v1, uint32_t& lo) {
    __half2 h = __floats2half2_rn(v0, v1);
    float2 hf = __half22float2(h);
    __half2 l = __floats2half2_rn(v0 - hf.x, v1 - hf.y);
    lo = *(uint32_t*)&l;
    return *(uint32_t*)&h;
}

// ---------------------------------------------------------------------------
// Merged prep: blocks [0, 8192) split x into fp16 hi/lo; blocks [8192, 8448)
// transpose + quantize one 64x64 weight tile. One launch, work overlaps.
// ---------------------------------------------------------------------------
__global__ void prep_kernel(const float* __restrict__ x,
                            const float* __restrict__ Wq,
                            const float* __restrict__ Wk,
                            const float* __restrict__ Wv,
                            const float* __restrict__ Wo) {
    __shared__ float t[64][65];
    const int tid = threadIdx.x;

    if (blockIdx.x < 8192) {
        // ---- prepx ----
        const size_t i4 = (size_t)blockIdx.x * 256 + tid;
        float4 v = ((const float4*)x)[i4];
        uint2 uh, ul;
        uh.x = split_hi(v.x, v.y, ul.x);
        uh.y = split_hi(v.z, v.w, ul.y);
        *(uint2*)(g_xhi + i4 * 4) = uh;
        *(uint2*)(g_xlo + i4 * 4) = ul;
        return;
    }

    // ---- prepw ----
    const int idx0 = blockIdx.x - 8192;     // 0..255
    const int z  = idx0 >> 6;               // 0..3
    const int y  = (idx0 >> 3) & 7;         // 0..7
    const int xt = idx0 & 7;                // 0..7
    const float* W = (z == 0) ? Wq : (z == 1) ? Wk : (z == 2) ? Wv : Wo;

#pragma unroll
    for (int i = 0; i < 4; i++) {
        int idx = tid + i * 256;
        int r   = idx >> 4;
        int c4  = (idx & 15) * 4;
        const float* p = (z < 3)
            ? W + (size_t)y * DD * DKK + (size_t)(xt * 64 + r) * DKK + c4
            : W + (size_t)(xt * 64 + r) * DD + y * 64 + c4;
        float4 v = *(const float4*)p;
        t[c4 + 0][r] = v.x; t[c4 + 1][r] = v.y;
        t[c4 + 2][r] = v.z; t[c4 + 3][r] = v.w;
    }
    __syncthreads();

    fp16* oh = g_Whi + (size_t)z * DD * DD;
#pragma unroll
    for (int i = 0; i < 4; i++) {
        int idx = tid + i * 256;
        int c   = idx >> 4;
        int r4  = (idx & 15) * 4;
        size_t o = (size_t)(y * 64 + c) * DD + xt * 64 + r4;
        uint2 uh;
        __half2 a = __floats2half2_rn(t[c][r4],     t[c][r4 + 1]);
        __half2 b = __floats2half2_rn(t[c][r4 + 2], t[c][r4 + 3]);
        uh.x = *(uint32_t*)&a;
        uh.y = *(uint32_t*)&b;
        *(uint2*)(oh + o) = uh;
    }
}

// ---------------------------------------------------------------------------
// fp16 split GEMM, 3-stage cp.async, one __syncthreads per chunk.
// A-passes per mat: Q (0) and out (3) use hi+lo (2 passes); K (1) and Vt (2)
// use hi only (their outputs are fp16-quantized anyway — lo adds nothing).
// Block tile 128x128, K=512 in chunks of 32.
// ---------------------------------------------------------------------------
#define ROWB 80
#define BUFB (128 * ROWB)
#define STGB (3 * BUFB)             // Ah, Al, Bh = 30720
#define NSTG 3
#define SMEM_GEMM (NSTG * STGB)     // 92160

__global__ __launch_bounds__(256, 2)
void mma_gemm_kernel(int matBase, const float* __restrict__ bias,
                     float* __restrict__ outp) {
    extern __shared__ char smc[];
    const uint32_t sb0 = (uint32_t)__cvta_generic_to_shared(smc);

    const int mat = matBase + blockIdx.z;
    const bool twoA = (mat == 0 || mat >= 3);   // Q and out carry A residual
    const int m0  = blockIdx.x * 128;
    const int n0  = blockIdx.y * 128;
    const fp16* Ahi = (mat >= 3) ? g_hhi : g_xhi;
    const fp16* Alo = (mat >= 3) ? g_hlo : g_xlo;
    const fp16* Bhi = g_Whi + (size_t)mat * DD * DD;

    const int tid  = threadIdx.x;
    const int wid  = tid >> 5;
    const int lane = tid & 31;
    const int wm   = (wid >> 2) * 64;
    const int wn   = (wid & 3) * 32;
    const int g    = lane >> 2;
    const int t4   = lane & 3;

    const uint32_t lq  = lane >> 3;
    const uint32_t lr  = lane & 7;
    const uint32_t lmo = (lr + (lq & 1) * 8) * ROWB + (lq >> 1) * 16;

    float acc[4][4][4] = {};

#define ISSUE(ch) do {                                                         \
        const int d0 = (ch) * 32;                                              \
        const uint32_t st = sb0 + ((ch) % NSTG) * STGB;                        \
        _Pragma("unroll")                                                      \
        for (int t = 0; t < 2; t++) {                                          \
            int idx = tid + 256 * t;                                           \
            int row = idx >> 2;                                                \
            int seg = idx & 3;                                                 \
            uint32_t so = (uint32_t)(row * ROWB + seg * 16);                   \
            size_t  ga  = (size_t)(m0 + row) * DD + d0 + seg * 8;              \
            size_t  gb  = (size_t)(n0 + row) * DD + d0 + seg * 8;              \
            cpasync16(st + so,            Ahi + ga);                           \
            if (twoA) cpasync16(st + BUFB + so, Alo + ga);                     \
            cpasync16(st + 2 * BUFB + so, Bhi + gb);                           \
        }                                                                      \
        cpcommit();                                                            \
    } while (0)

    ISSUE(0);
    ISSUE(1);

    for (int ch = 0; ch < 16; ch++) {
        if (ch < 15) cpwait<1>(); else cpwait<0>();
        __syncthreads();
        if (ch + 2 < 16) ISSUE(ch + 2);   // overwrites stage read 2 iters ago

        const uint32_t st = sb0 + (ch % NSTG) * STGB;
#pragma unroll
        for (int kk = 0; kk < 2; kk++) {
            const uint32_t ko = kk * 32;
            uint32_t bH[2][4];
#pragma unroll
            for (int nn = 0; nn < 2; nn++) {
                uint32_t bd = st + 2 * BUFB + (uint32_t)((wn + nn * 16) * ROWB) + ko + lmo;
                LDMX4(bH[nn], bd);
            }
#pragma unroll
            for (int mi = 0; mi < 4; mi++) {
                uint32_t aH[4], aL[4];
                uint32_t ad = st + (uint32_t)((wm + mi * 16) * ROWB) + ko + lmo;
                LDMX4(aH, ad);
                if (twoA) LDMX4(aL, ad + BUFB);
#pragma unroll
                for (int ni = 0; ni < 4; ni++) {
                    const int nn = ni >> 1, sel = ni & 1;
                    mma16(acc[mi][ni], aH, bH[nn][sel], bH[nn][sel + 2]);
                    if (twoA)
                        mma16(acc[mi][ni], aL, bH[nn][sel], bH[nn][sel + 2]);
                }
            }
        }
    }

    // epilogue
    const float bv = bias[0];
#pragma unroll
    for (int mi = 0; mi < 4; mi++) {
#pragma unroll
        for (int h2 = 0; h2 < 2; h2++) {
            const int row = m0 + wm + mi * 16 + g + 8 * h2;
            const int b   = row >> 9;
            const int s   = row & 511;
#pragma unroll
            for (int ni = 0; ni < 4; ni++) {
                const int col0 = n0 + wn + ni * 8 + 2 * t4;
                float v0 = acc[mi][ni][2 * h2]     + bv;
                float v1 = acc[mi][ni][2 * h2 + 1] + bv;
                if (mat == 0) {
                    v0 *= QSCL; v1 *= QSCL;
                    size_t a = ((size_t)(b * HH + (col0 >> 6)) * SS + s) * DKK
                               + (col0 & 63);
                    uint32_t lo;
                    uint32_t hi = split_hi(v0, v1, lo);
                    *(uint32_t*)(g_Qhi + a) = hi;
                    *(uint32_t*)(g_Qlo + a) = lo;
                } else if (mat == 1) {
                    size_t a = ((size_t)(b * HH + (col0 >> 6)) * SS + s) * DKK
                               + (col0 & 63);
                    __half2 hv = __floats2half2_rn(v0, v1);
                    *(uint32_t*)(g_Khi + a) = *(uint32_t*)&hv;
                } else if (mat == 2) {
                    size_t a = ((size_t)(b * HH + (col0 >> 6)) * DKK + (col0 & 63)) * SS + s;
                    g_Vthi[a]      = __float2half_rn(v0);
                    g_Vthi[a + SS] = __float2half_rn(v1);
                } else {
                    *(float2*)(outp + (size_t)row * DD + col0) = make_float2(v0, v1);
                }
            }
        }
    }
#undef ISSUE
}

// ---------------------------------------------------------------------------
// Flash attention, fp16 2-term (Q/P carry residuals; K/V hi only).
// Pipelined: K(kt+1) issued after scores(kt); V double-buffered.
// 3 barriers per key tile — the loop-top barrier is the cp.async
// cross-thread visibility fence for SK/SQ (removal => NaN, round 13).
// grid (S/64, B*H), block 256 (8 warps: 2m x 4n).
// ---------------------------------------------------------------------------
#define QROWB 144                 // 128B row + 16 pad (conflict-free ldmatrix)
#define PROWB 272                 // 256B row + 16 pad
#define SQ_HI 0                   // 64*144 = 9216
#define SQ_LO 9216
#define SK    18432               // 128*144 = 18432 (hi only, own buffer)
#define SP_HI 36864               // 64*272 = 17408
#define SP_LO 54272
#define SV0   71680               // 2 x 17408 (double buffer)
#define SVSZ  17408
#define SRED  106496
#define SRED2 107520
#define SMEM_ATTN 108544

__global__ __launch_bounds__(256, 2)
void attn_kernel(const int* __restrict__ mask) {
    extern __shared__ char smc[];
    const uint32_t sb = (uint32_t)__cvta_generic_to_shared(smc);
    float* redf  = (float*)(smc + SRED);
    float* redf2 = (float*)(smc + SRED2);

    const int q0 = blockIdx.x * 64;
    const int bh = blockIdx.y;
    const int b  = bh / HH;
    const int h  = bh % HH;

    const int tid  = threadIdx.x;
    const int wid  = tid >> 5;
    const int lane = tid & 31;
    const int wm2  = wid >> 2;          // 0/1: q 32-group
    const int wn2  = wid & 3;           // 0..3
    const int g    = lane >> 2;
    const int t4   = lane & 3;
    const int QR   = wm2 * 32;
    const int KNB  = wn2 * 32;          // key base within ktile (scores)

    const uint32_t lq = lane >> 3, lr = lane & 7;
    const uint32_t lmoQ = (lr + (lq & 1) * 8) * QROWB + (lq >> 1) * 16;
    const uint32_t lmoP = (lr + (lq & 1) * 8) * PROWB + (lq >> 1) * 16;

    // Issue Q (hi+lo) — group 1
    {
        int row = tid >> 2;
        int s0  = (tid & 3) * 2;
        size_t   ga = ((size_t)bh * SS + q0 + row) * DKK;
        uint32_t so = sb + (uint32_t)(row * QROWB);
#pragma unroll
        for (int j = 0; j < 2; j++) {
            cpasync16(so + SQ_HI + (s0 + j) * 16, g_Qhi + ga + (s0 + j) * 8);
            cpasync16(so + SQ_LO + (s0 + j) * 16, g_Qlo + ga + (s0 + j) * 8);
        }
        cpcommit();
    }
    // Issue K(0) — group 2
    {
        int row = tid >> 1;
        int sN  = (tid & 1) * 4;
        size_t   ga = ((size_t)bh * SS + row) * DKK;
        uint32_t so = sb + (uint32_t)(row * QROWB);
#pragma unroll
        for (int j = 0; j < 4; j++)
            cpasync16(so + SK + (sN + j) * 16, g_Khi + ga + (sN + j) * 8);
        cpcommit();
    }
    // Issue V(0) -> SV0 — group 3
    {
        int row = tid >> 2;
        int sN  = (tid & 3) * 4;
        size_t   ga = ((size_t)bh * DKK + row) * SS;
        uint32_t so = sb + (uint32_t)(row * PROWB);
#pragma unroll
        for (int j = 0; j < 4; j++)
            cpasync16(so + SV0 + (sN + j) * 16, g_Vthi + ga + (sN + j) * 8);
        cpcommit();
    }

    float acc_o[2][2][4] = {};          // [mi][ni2][c]
    float li[2][2] = {};                // per-warp PARTIAL (own key slice)
    float mx[2][2] = {{-1e30f, -1e30f}, {-1e30f, -1e30f}};

    for (int kt = 0; kt < 4; kt++) {
        cpwait<1>();                    // K(kt) [+Q] complete; V(kt) may pend
        __syncthreads();                // cp.async cross-thread visibility fence

        // ---- mask load hoisted: overlaps the scores mma phase ----
        int2 mk[4];
#pragma unroll
        for (int ni = 0; ni < 4; ni++)
            mk[ni] = *(const int2*)(mask + b * SS + kt * 128 + KNB + ni * 8 + 2 * t4);

        // ---- scores: 32q x 32k per warp, 2 passes ----
        float s4[2][4][4] = {};
#pragma unroll
        for (int ks = 0; ks < 4; ks++) {
            uint32_t aH[2][4], aL[2][4], bH[2][4];
#pragma unroll
            for (int mi = 0; mi < 2; mi++) {
                uint32_t ad = sb + (uint32_t)((QR + mi * 16) * QROWB) + ks * 32 + lmoQ;
                LDMX4(aH[mi], ad + SQ_HI);
                LDMX4(aL[mi], ad + SQ_LO);
            }
#pragma unroll
            for (int nn = 0; nn < 2; nn++) {
                uint32_t bd = sb + (uint32_t)((KNB + nn * 16) * QROWB) + ks * 32 + lmoQ;
                LDMX4(bH[nn], bd + SK);
            }
#pragma unroll
            for (int mi = 0; mi < 2; mi++)
#pragma unroll
                for (int ni = 0; ni < 4; ni++) {
                    const int nn = ni >> 1, sel = ni & 1;
                    mma16(s4[mi][ni], aH[mi], bH[nn][sel], bH[nn][sel + 2]);
                    mma16(s4[mi][ni], aL[mi], bH[nn][sel], bH[nn][sel + 2]);
                }
        }

        // ---- mask (pure select) ----
#pragma unroll
        for (int mi = 0; mi < 2; mi++)
#pragma unroll
            for (int ni = 0; ni < 4; ni++) {
                s4[mi][ni][0] = mk[ni].x ? s4[mi][ni][0] : -1e30f;
                s4[mi][ni][1] = mk[ni].y ? s4[mi][ni][1] : -1e30f;
                s4[mi][ni][2] = mk[ni].x ? s4[mi][ni][2] : -1e30f;
                s4[mi][ni][3] = mk[ni].y ? s4[mi][ni][3] : -1e30f;
            }

        // ---- local row max -> smem ----
#pragma unroll
        for (int mi = 0; mi < 2; mi++)
#pragma unroll
            for (int half = 0; half < 2; half++) {
                float m = -1e30f;
#pragma unroll
                for (int ni = 0; ni < 4; ni++)
                    m = fmaxf(m, fmaxf(s4[mi][ni][half * 2], s4[mi][ni][half * 2 + 1]));
                m = fmaxf(m, __shfl_xor_sync(0xffffffffu, m, 1));
                m = fmaxf(m, __shfl_xor_sync(0xffffffffu, m, 2));
                if (t4 == 0)
                    redf[(wm2 * 4 + wn2) * 32 + mi * 16 + g + 8 * half] = m;
            }
        __syncthreads();                // barrier(1): maxes visible, SK free

        // ---- prefetch K(kt+1) into SK (overlaps softmax + PV) ----
        if (kt < 3) {
            int row = tid >> 1;
            int sN  = (tid & 1) * 4;
            size_t   ga = ((size_t)bh * SS + (kt + 1) * 128 + row) * DKK;
            uint32_t so = sb + (uint32_t)(row * QROWB);
#pragma unroll
            for (int j = 0; j < 4; j++)
                cpasync16(so + SK + (sN + j) * 16, g_Khi + ga + (sN + j) * 8);
            cpcommit();
        }

        // ---- global max, rescale O + partial li, p=exp2, write P ----
        float mnew[2][2], lsum[2][2] = {};
#pragma unroll
        for (int mi = 0; mi < 2; mi++)
#pragma unroll
            for (int half = 0; half < 2; half++) {
                const int rl = mi * 16 + g + 8 * half;
                float gm = fmaxf(fmaxf(redf[(wm2 * 4 + 0) * 32 + rl],
                                       redf[(wm2 * 4 + 1) * 32 + rl]),
                                 fmaxf(redf[(wm2 * 4 + 2) * 32 + rl],
                                       redf[(wm2 * 4 + 3) * 32 + rl]));
                float mn = fmaxf(mx[mi][half], gm);
                float al = exp2f(mx[mi][half] - mn);
                mx[mi][half] = mn;
                mnew[mi][half] = mn;
                li[mi][half] *= al;
#pragma unroll
                for (int ni2 = 0; ni2 < 2; ni2++) {
                    acc_o[mi][ni2][half * 2]     *= al;
                    acc_o[mi][ni2][half * 2 + 1] *= al;
                }
            }
#pragma unroll
        for (int mi = 0; mi < 2; mi++)
#pragma unroll
            for (int ni = 0; ni < 4; ni++) {
                float p0 = exp2f(s4[mi][ni][0] - mnew[mi][0]);
                float p1 = exp2f(s4[mi][ni][1] - mnew[mi][0]);
                float p2 = exp2f(s4[mi][ni][2] - mnew[mi][1]);
                float p3 = exp2f(s4[mi][ni][3] - mnew[mi][1]);
                lsum[mi][0] += p0 + p1;
                lsum[mi][1] += p2 + p3;
                uint32_t lo0, lo1;
                uint32_t hi0 = split_hi(p0, p1, lo0);
                uint32_t hi1 = split_hi(p2, p3, lo1);
                const uint32_t cb = (uint32_t)((KNB + ni * 8 + 2 * t4) * 2);
                const uint32_t r0 = (uint32_t)((QR + mi * 16 + g) * PROWB) + cb;
                *(uint32_t*)(smc + SP_HI + r0)               = hi0;
                *(uint32_t*)(smc + SP_LO + r0)               = lo0;
                *(uint32_t*)(smc + SP_HI + r0 + 8 * PROWB)   = hi1;
                *(uint32_t*)(smc + SP_LO + r0 + 8 * PROWB)   = lo1;
            }
        // partial li over this warp's 32-key slice
#pragma unroll
        for (int mi = 0; mi < 2; mi++)
#pragma unroll
            for (int half = 0; half < 2; half++) {
                float sgl = lsum[mi][half];
                sgl += __shfl_xor_sync(0xffffffffu, sgl, 1);
                sgl += __shfl_xor_sync(0xffffffffu, sgl, 2);
                li[mi][half] += sgl;
            }

        if (kt < 3) cpwait<1>();        // V(kt) done (K(kt+1) may pend)
        else        cpwait<0>();
        __syncthreads();                // barrier(2): V + P visible to all

        // ---- prefetch V(kt+1) into the other V buffer ----
        if (kt < 3) {
            int row = tid >> 2;
            int sN  = (tid & 3) * 4;
            size_t   ga = ((size_t)bh * DKK + row) * SS + (kt + 1) * 128;
            uint32_t so = sb + (uint32_t)(row * PROWB) + SV0 + ((kt + 1) & 1) * SVSZ;
#pragma unroll
            for (int j = 0; j < 4; j++)
                cpasync16(so + (sN + j) * 16, g_Vthi + ga + (sN + j) * 8);
            cpcommit();
        }

        // ---- PV: 32q x 16v per warp, k = 128 keys, 2 passes ----
        const uint32_t svb = (uint32_t)(SV0 + (kt & 1) * SVSZ);
#pragma unroll
        for (int ks = 0; ks < 8; ks++) {
            uint32_t pH[2][4], pL[2][4], vH[4];
#pragma unroll
            for (int mi = 0; mi < 2; mi++) {
                uint32_t pd = sb + (uint32_t)((QR + mi * 16) * PROWB) + ks * 32 + lmoP;
                LDMX4(pH[mi], pd + SP_HI);
                LDMX4(pL[mi], pd + SP_LO);
            }
            uint32_t vd = sb + (uint32_t)((wn2 * 16) * PROWB) + ks * 32 + lmoP + svb;
            LDMX4(vH, vd);
#pragma unroll
            for (int mi = 0; mi < 2; mi++)
#pragma unroll
                for (int ni2 = 0; ni2 < 2; ni2++) {
                    mma16(acc_o[mi][ni2], pH[mi], vH[ni2], vH[ni2 + 2]);
                    mma16(acc_o[mi][ni2], pL[mi], vH[ni2], vH[ni2 + 2]);
                }
        }
    }

    // ---- final li reduction across the 4 wn2 warps ----
#pragma unroll
    for (int mi = 0; mi < 2; mi++)
#pragma unroll
        for (int half = 0; half < 2; half++)
            if (t4 == 0)
                redf2[(wm2 * 4 + wn2) * 32 + mi * 16 + g + 8 * half] = li[mi][half];
    __syncthreads();
#pragma unroll
    for (int mi = 0; mi < 2; mi++)
#pragma unroll
        for (int half = 0; half < 2; half++) {
            const int rl = mi * 16 + g + 8 * half;
            li[mi][half] = redf2[(wm2 * 4 + 0) * 32 + rl]
                         + redf2[(wm2 * 4 + 1) * 32 + rl]
                         + redf2[(wm2 * 4 + 2) * 32 + rl]
                         + redf2[(wm2 * 4 + 3) * 32 + rl];
        }

    // ---- finalize: heads (concat layout) as fp16 hi/lo ----
#pragma unroll
    for (int mi = 0; mi < 2; mi++)
#pragma unroll
        for (int half = 0; half < 2; half++) {
            const float inv = 1.0f / li[mi][half];
            const int tok = q0 + QR + mi * 16 + g + 8 * half;
#pragma unroll
            for (int ni2 = 0; ni2 < 2; ni2++) {
                const int col = wn2 * 16 + ni2 * 8 + 2 * t4;
                float v0 = acc_o[mi][ni2][half * 2]     * inv;
                float v1 = acc_o[mi][ni2][half * 2 + 1] * inv;
                uint32_t lo;
                uint32_t hi = split_hi(v0, v1, lo);
                size_t a = ((size_t)b * SS + tok) * DD + h * DKK + col;
                *(uint32_t*)(g_hhi + a) = hi;
                *(uint32_t*)(g_hlo + a) = lo;
            }
        }
}

// ---------------------------------------------------------------------------
extern "C" void kernel_launch(void* const* d_in, const int* in_sizes, int n_in,
                              void* d_out, int out_size) {
    const float* x    = (const float*)d_in[0];
    const int*   mask = (const int*)  d_in[1];
    const float* Wq   = (const float*)d_in[2];
    const float* Wk   = (const float*)d_in[3];
    const float* Wv   = (const float*)d_in[4];
    const float* Wo   = (const float*)d_in[5];
    const float* bias = (const float*)d_in[6];
    float* out = (float*)d_out;

    // 0) merged prep: x hi/lo split + weight transpose/quantize (one launch)
    prep_kernel<<<8192 + 256, 256>>>(x, Wq, Wk, Wv, Wo);

    // 1) QKV projections (Q: 2-pass; K/V: 1-pass — outputs are fp16 anyway)
    cudaFuncSetAttribute(mma_gemm_kernel,
                         cudaFuncAttributeMaxDynamicSharedMemorySize, SMEM_GEMM);
    mma_gemm_kernel<<<dim3(MM / 128, 4, 3), 256, SMEM_GEMM>>>(0, bias, out);

    // 2) fused masked-softmax attention (flash, fp16 mma.sync, pipelined K/V)
    cudaFuncSetAttribute(attn_kernel,
                         cudaFuncAttributeMaxDynamicSharedMemorySize, SMEM_ATTN);
    attn_kernel<<<dim3(SS / 64, BB * HH), 256, SMEM_ATTN>>>(mask);

    // 3) output projection (2-pass: fp32 output needs the heads residual)
    mma_gemm_kernel<<<dim3(MM / 128, 4, 1), 256, SMEM_GEMM>>>(3, bias, out);
}